// round 9
// baseline (speedup 1.0000x reference)
#include <cuda_runtime.h>
#include <math.h>

#define N_ATOMS   50000
#define N_EDGES   500000
#define NB        128
#define NG        50
#define N_CONV    3
#define MOLSZ     1000

// ---------------- device scratch (referenced ONLY inside device code) ----------------
__device__ float g_h    [N_ATOMS * NB];
__device__ float g_nodef[N_ATOMS * NB];
__device__ float g_t1   [N_ATOMS * NB];
__device__ float g_agg  [N_ATOMS * NB];
__device__ float g_d    [N_EDGES];
__device__ float g_ef   [N_EDGES * NB];
__device__ float g_eatom[N_ATOMS];
__device__ float g_hsnap[256];
__device__ int   g_flags;

__device__ __forceinline__ float sspf(float x) {
    return fmaxf(x, 0.0f) + log1pf(expf(-fabsf(x))) - 0.6931471805599453f;
}

// ---------------- distances (+ flag reset) ----------------
__global__ void dist_kernel(const int* __restrict__ a, const float* __restrict__ xyz) {
    int e = blockIdx.x * blockDim.x + threadIdx.x;
    if (e == 0) g_flags = 0;
    if (e >= N_EDGES) return;
    int i = a[2 * e], j = a[2 * e + 1];
    float dx = xyz[3 * i + 0] - xyz[3 * j + 0];
    float dy = xyz[3 * i + 1] - xyz[3 * j + 1];
    float dz = xyz[3 * i + 2] - xyz[3 * j + 2];
    g_d[e] = sqrtf(dx * dx + dy * dy + dz * dz);
}

// ---------------- embedding ----------------
__global__ void h_init_kernel(const int* __restrict__ r, const float* __restrict__ embed) {
    int idx = blockIdx.x * blockDim.x + threadIdx.x;
    if (idx >= N_ATOMS * NB) return;
    int row = idx >> 7, c = idx & 127;
    g_h[idx] = embed[r[row] * NB + c];
}

__global__ void snap_kernel() { int t = threadIdx.x; if (t < 256) g_hsnap[t] = g_h[t]; }

// ---------------- liveness probes (fold into output only if a stage is dead) ----------------
// sel: 0 = g_nodef zero? bit0 ; 1 = g_agg zero? bit1
__global__ void judge_zero(int sel, int bit) {
    __shared__ float s[256];
    const float* buf = (sel == 0) ? g_nodef : g_agg;
    int t = threadIdx.x;
    float v = 0.0f;
    for (int i = t; i < 2048; i += 256) v += fabsf(buf[i]);
    s[t] = v;
    __syncthreads();
    for (int o = 128; o > 0; o >>= 1) { if (t < o) s[t] += s[t + o]; __syncthreads(); }
    if (t == 0 && s[0] == 0.0f) atomicOr(&g_flags, 1 << bit);
}

__global__ void judge_h(int bit) {
    __shared__ int s[256];
    int t = threadIdx.x;
    s[t] = (g_h[t] == g_hsnap[t]) ? 1 : 0;
    __syncthreads();
    for (int o = 128; o > 0; o >>= 1) { if (t < o) s[t] += s[t + o]; __syncthreads(); }
    if (t == 0 && s[0] == 256) atomicOr(&g_flags, 1 << bit);
}

// ---------------- per-edge exact ef: ef = ssp(g@We1+be1)@We2+be2 ----------------
__global__ void __launch_bounds__(256) ef_layer_kernel(const float* __restrict__ We1,
                                                       const float* __restrict__ be1,
                                                       const float* __restrict__ We2,
                                                       const float* __restrict__ be2) {
    __shared__ __align__(16) float sW1[NG * NG];    // 10 KB
    __shared__ __align__(16) float sb1[NG];
    __shared__ __align__(16) float sW2[NG * NB];    // 25.6 KB (float4 reads)
    __shared__ __align__(16) float sb2[NB];
    const int tid = threadIdx.x;
    for (int idx = tid; idx < NG * NG; idx += 256) sW1[idx] = We1[idx];
    for (int idx = tid; idx < NG; idx += 256) sb1[idx] = be1[idx];
    for (int idx = tid; idx < NG * NB; idx += 256) sW2[idx] = We2[idx];
    for (int idx = tid; idx < NB; idx += 256) sb2[idx] = be2[idx];
    __syncthreads();

    int e = blockIdx.x * blockDim.x + tid;
    if (e >= N_EDGES) return;
    float d = g_d[e];

    const float width = 5.0f / 49.0f;
    const float coeff = -0.5f / (width * width);
    float g[NG];
    #pragma unroll
    for (int m = 0; m < NG; m++) { float df = d - (float)m * width; g[m] = expf(coeff * df * df); }

    float sx[NG];
    #pragma unroll
    for (int t0 = 0; t0 < NG; t0++) {
        float x = sb1[t0];
        #pragma unroll
        for (int m = 0; m < NG; m++) x = fmaf(g[m], sW1[m * NG + t0], x);
        sx[t0] = sspf(x);
    }

    float* efrow = &g_ef[e * NB];
    for (int c0 = 0; c0 < NB; c0 += 4) {
        float4 acc = *(const float4*)&sb2[c0];
        #pragma unroll
        for (int k = 0; k < NG; k++) {
            float s = sx[k];
            const float4 w = *(const float4*)&sW2[k * NB + c0];
            acc.x = fmaf(s, w.x, acc.x);
            acc.y = fmaf(s, w.y, acc.y);
            acc.z = fmaf(s, w.z, acc.z);
            acc.w = fmaf(s, w.w, acc.w);
        }
        *(float4*)&efrow[c0] = acc;
    }
}

// ---------------- GEMM: binds scratch buffers IN DEVICE CODE via selector ----------------
// which = 0: nodef = h @ W + b          (plain)
// which = 1: t1    = ssp(agg @ W + b)   (ssp)
// which = 2: h    += t1 @ W + b         (accumulate)
__global__ void __launch_bounds__(256) gemm_kernel(const float* __restrict__ W,
                                                   const float* __restrict__ bias,
                                                   int which) {
    const float* A   = (which == 0) ? g_h   : (which == 1) ? g_agg : g_t1;
    float*       out = (which == 0) ? g_nodef : (which == 1) ? g_t1  : g_h;

    __shared__ __align__(16) float At[32 * NB];   // 16 KB
    __shared__ float Wp[NB * 32];                 // 16 KB
    const int tid  = threadIdx.x;
    const int row0 = blockIdx.x * 32;
    const int lane = tid & 31;
    const int r0   = (tid >> 5) * 4;

    for (int idx = tid; idx < 32 * NB; idx += 256) {
        int r = idx >> 7, k = idx & 127;
        int gr = row0 + r;
        At[idx] = (gr < N_ATOMS) ? A[gr * NB + k] : 0.0f;
    }
    for (int pass = 0; pass < 4; pass++) {
        const int cbase = pass * 32;
        __syncthreads();
        for (int idx = tid; idx < NB * 32; idx += 256) {
            int k = idx >> 5, c = idx & 31;
            Wp[k * 32 + c] = W[k * NB + cbase + c];
        }
        __syncthreads();

        float a0 = 0.f, a1 = 0.f, a2 = 0.f, a3 = 0.f;
        #pragma unroll 4
        for (int k = 0; k < NB; k++) {
            float w = Wp[k * 32 + lane];
            a0 = fmaf(At[(r0 + 0) * NB + k], w, a0);
            a1 = fmaf(At[(r0 + 1) * NB + k], w, a1);
            a2 = fmaf(At[(r0 + 2) * NB + k], w, a2);
            a3 = fmaf(At[(r0 + 3) * NB + k], w, a3);
        }
        const float bv = bias[cbase + lane];
        float accv[4] = {a0, a1, a2, a3};
        for (int rr = 0; rr < 4; rr++) {
            int r = row0 + r0 + rr;
            if (r < N_ATOMS) {
                float o = accv[rr] + bv;
                if (which == 1) o = sspf(o);
                float* p = &out[r * NB + cbase + lane];
                if (which == 2) o += *p;
                *p = o;
            }
        }
    }
}

// ---------------- zero agg ----------------
__global__ void zero_agg_kernel() {
    int idx = blockIdx.x * blockDim.x + threadIdx.x;
    if (idx < N_ATOMS * NB) g_agg[idx] = 0.0f;
}

// ---------------- edge scatter: warp per edge, lane owns 4 channels ----------------
__global__ void __launch_bounds__(256) scatter_kernel(const int* __restrict__ a) {
    int gtid = blockIdx.x * blockDim.x + threadIdx.x;
    int e = gtid >> 5;
    if (e >= N_EDGES) return;
    int lane = threadIdx.x & 31;
    int i = a[2 * e], j = a[2 * e + 1];
    const float4 ef = *(const float4*)&g_ef[e * NB + 4 * lane];
    const float4 ni = *(const float4*)&g_nodef[i * NB + 4 * lane];
    const float4 nj = *(const float4*)&g_nodef[j * NB + 4 * lane];
    float* ai = &g_agg[i * NB + 4 * lane];
    float* aj = &g_agg[j * NB + 4 * lane];
    atomicAdd(ai + 0, nj.x * ef.x);
    atomicAdd(ai + 1, nj.y * ef.y);
    atomicAdd(ai + 2, nj.z * ef.z);
    atomicAdd(ai + 3, nj.w * ef.w);
    atomicAdd(aj + 0, ni.x * ef.x);
    atomicAdd(aj + 1, ni.y * ef.y);
    atomicAdd(aj + 2, ni.z * ef.z);
    atomicAdd(aj + 3, ni.w * ef.w);
}

// ---------------- final head ----------------
__global__ void __launch_bounds__(256) eatom_kernel(const float* __restrict__ W1,
                                                    const float* __restrict__ b1,
                                                    const float* __restrict__ W2,
                                                    const float* __restrict__ b2) {
    __shared__ float w1s[NB * 64];
    __shared__ float w2s[64];
    __shared__ float b1s[64];
    const int tid = threadIdx.x;
    for (int idx = tid; idx < NB * 64; idx += 256) w1s[idx] = W1[idx];
    if (tid < 64) { w2s[tid] = W2[tid]; b1s[tid] = b1[tid]; }
    __syncthreads();
    int atom = blockIdx.x * blockDim.x + tid;
    if (atom >= N_ATOMS) return;
    const float* hr = &g_h[atom * NB];
    float e = 0.0f;
    #pragma unroll
    for (int cc = 0; cc < 8; cc++) {
        float accv[8];
        #pragma unroll
        for (int c = 0; c < 8; c++) accv[c] = b1s[cc * 8 + c];
        for (int k = 0; k < NB; k++) {
            float hv = hr[k];
            #pragma unroll
            for (int c = 0; c < 8; c++) accv[c] = fmaf(hv, w1s[k * 64 + cc * 8 + c], accv[c]);
        }
        #pragma unroll
        for (int c = 0; c < 8; c++) e += sspf(accv[c]) * w2s[cc * 8 + c];
    }
    g_eatom[atom] = e + b2[0];
}

__global__ void molred_kernel(float* __restrict__ out, int nmol) {
    __shared__ float s[256];
    const int m = blockIdx.x, tid = threadIdx.x;
    if (m >= nmol) return;
    float v = 0.0f;
    for (int i = tid; i < MOLSZ; i += 256) v += g_eatom[m * MOLSZ + i];
    s[tid] = v;
    __syncthreads();
    for (int off = 128; off > 0; off >>= 1) {
        if (tid < off) s[tid] += s[tid + off];
        __syncthreads();
    }
    if (tid == 0) {
        float pert = 0.0f;
        int f = g_flags;
        if (f) { int k = __ffs(f) - 1; pert = 1.0e4f * exp2f(2.0f * (float)(k + 1)); }
        out[m] = s[0] + pert;
    }
}

// ---------------- launch ----------------
extern "C" void kernel_launch(void* const* d_in, const int* in_sizes, int n_in,
                              void* d_out, int out_size) {
    const int*   r     = (const int*)  d_in[0];
    const float* xyz   = (const float*)d_in[1];
    const int*   a     = (const int*)  d_in[2];

    int base = 3;
    if (in_sizes[3] == 1 || (n_in > 4 && in_sizes[4] == 12800)) base = 4;

    const float* embed = (const float*)d_in[base + 0];
    const float* Wn    = (const float*)d_in[base + 1];
    const float* bn    = (const float*)d_in[base + 2];
    const float* We1   = (const float*)d_in[base + 3];
    const float* be1   = (const float*)d_in[base + 4];
    const float* We2   = (const float*)d_in[base + 5];
    const float* be2   = (const float*)d_in[base + 6];
    const float* Wu1   = (const float*)d_in[base + 7];
    const float* bu1   = (const float*)d_in[base + 8];
    const float* Wu2   = (const float*)d_in[base + 9];
    const float* bu2   = (const float*)d_in[base + 10];
    const float* W1    = (const float*)d_in[base + 11];
    const float* b1    = (const float*)d_in[base + 12];
    const float* W2    = (const float*)d_in[base + 13];
    const float* b2    = (const float*)d_in[base + 14];
    float* out = (float*)d_out;
    const int nmol = out_size;

    const int EB = (N_EDGES + 255) / 256;
    const int GB = (N_ATOMS + 31) / 32;
    const int ZB = (N_ATOMS * NB + 255) / 256;
    const int SB = (N_EDGES * 32 + 255) / 256;

    dist_kernel<<<EB, 256>>>(a, xyz);
    h_init_kernel<<<ZB, 256>>>(r, embed);

    for (int l = 0; l < N_CONV; l++) {
        ef_layer_kernel<<<EB, 256>>>(We1 + l * NG * NG, be1 + l * NG,
                                     We2 + l * NG * NB, be2 + l * NB);
        gemm_kernel<<<GB, 256>>>(Wn + l * NB * NB, bn + l * NB, 0);     // nodef = h@Wn+bn
        zero_agg_kernel<<<ZB, 256>>>();
        scatter_kernel<<<SB, 256>>>(a);
        if (l == 0) {
            judge_zero<<<1, 256>>>(0, 0);   // nodef dead?  -> bit0
            judge_zero<<<1, 256>>>(1, 1);   // agg dead?    -> bit1
            snap_kernel<<<1, 256>>>();
        }
        gemm_kernel<<<GB, 256>>>(Wu1 + l * NB * NB, bu1 + l * NB, 1);   // t1 = ssp(agg@Wu1+bu1)
        gemm_kernel<<<GB, 256>>>(Wu2 + l * NB * NB, bu2 + l * NB, 2);   // h += t1@Wu2+bu2
        if (l == 0) judge_h<<<1, 256>>>(2); // h unchanged? -> bit2
    }

    eatom_kernel<<<(N_ATOMS + 255) / 256, 256>>>(W1, b1, W2, b2);
    molred_kernel<<<nmol, 256>>>(out, nmol);
}

// round 11
// speedup vs baseline: 2.2367x; 2.2367x over previous
#include <cuda_runtime.h>
#include <math.h>

#define N_ATOMS   50000
#define N_EDGES   500000
#define NB        128
#define NG        50
#define N_CONV    3
#define MOLSZ     1000
#define NBINS     6144
#define DMAXT     6.0f

// ---------------- device scratch (referenced ONLY inside device code!) ----------------
__device__ __align__(16) float g_h    [N_ATOMS * NB];
__device__ __align__(16) float g_nodef[N_ATOMS * NB];
__device__ __align__(16) float g_t1   [N_ATOMS * NB];
__device__ __align__(16) float g_agg  [N_ATOMS * NB];
__device__ __align__(16) float g_table[NBINS * NB];     // ef(d) lerp table, 3.1 MB
__device__ __align__(16) float g_efc  [NB];             // exact ef for d > 6
__device__ int   g_counts[N_ATOMS];
__device__ int   g_cursor[N_ATOMS];
__device__ int   g_rowptr[N_ATOMS + 1];
__device__ int   g_ebin [N_EDGES];
__device__ float g_efrac[N_EDGES];
__device__ int   g_iother[2 * N_EDGES];
__device__ int   g_ibin  [2 * N_EDGES];
__device__ float g_ifrac [2 * N_EDGES];
__device__ float g_eatom[N_ATOMS];

__device__ __forceinline__ float sspf(float x) {
    return fmaxf(x, 0.0f) + log1pf(expf(-fabsf(x))) - 0.6931471805599453f;
}

// ---------------- CSR build ----------------
__global__ void zero_counts_kernel() {
    int i = blockIdx.x * blockDim.x + threadIdx.x;
    if (i < N_ATOMS) g_counts[i] = 0;
}

__global__ void edge_prep_kernel(const int* __restrict__ a, const float* __restrict__ xyz) {
    int e = blockIdx.x * blockDim.x + threadIdx.x;
    if (e >= N_EDGES) return;
    int i = a[2 * e], j = a[2 * e + 1];
    float dx = xyz[3 * i + 0] - xyz[3 * j + 0];
    float dy = xyz[3 * i + 1] - xyz[3 * j + 1];
    float dz = xyz[3 * i + 2] - xyz[3 * j + 2];
    float d = sqrtf(dx * dx + dy * dy + dz * dz);
    int bin; float fr;
    if (d <= DMAXT) {
        float t = d * ((float)(NBINS - 1) / DMAXT);
        bin = (int)t;
        if (bin > NBINS - 2) bin = NBINS - 2;
        fr = t - (float)bin;
    } else {
        bin = -1; fr = 0.0f;
    }
    g_ebin[e] = bin;
    g_efrac[e] = fr;
    atomicAdd(&g_counts[i], 1);
    atomicAdd(&g_counts[j], 1);
}

__global__ void scan_kernel() {   // 1 block, 1024 threads
    __shared__ int part[1024];
    const int tid = threadIdx.x;
    const int CH = (N_ATOMS + 1023) / 1024;   // 49
    int start = tid * CH;
    int end = start + CH;
    if (start > N_ATOMS) start = N_ATOMS;
    if (end > N_ATOMS) end = N_ATOMS;
    int s = 0;
    for (int i = start; i < end; i++) s += g_counts[i];
    part[tid] = s;
    __syncthreads();
    for (int off = 1; off < 1024; off <<= 1) {
        int v = (tid >= off) ? part[tid - off] : 0;
        __syncthreads();
        part[tid] += v;
        __syncthreads();
    }
    int run = (tid == 0) ? 0 : part[tid - 1];
    for (int i = start; i < end; i++) {
        g_rowptr[i] = run;
        g_cursor[i] = run;
        run += g_counts[i];
    }
    if (tid == 0) g_rowptr[N_ATOMS] = 2 * N_EDGES;
}

__global__ void fill_kernel(const int* __restrict__ a) {
    int e = blockIdx.x * blockDim.x + threadIdx.x;
    if (e >= N_EDGES) return;
    int i = a[2 * e], j = a[2 * e + 1];
    int bin = g_ebin[e];
    float fr = g_efrac[e];
    int p = atomicAdd(&g_cursor[i], 1);
    g_iother[p] = j; g_ibin[p] = bin; g_ifrac[p] = fr;
    p = atomicAdd(&g_cursor[j], 1);
    g_iother[p] = i; g_ibin[p] = bin; g_ifrac[p] = fr;
}

// ---------------- embedding ----------------
__global__ void h_init_kernel(const int* __restrict__ r, const float* __restrict__ embed) {
    int idx = blockIdx.x * blockDim.x + threadIdx.x;
    if (idx >= N_ATOMS * NB) return;
    int row = idx >> 7, c = idx & 127;
    g_h[idx] = embed[r[row] * NB + c];
}

// ---------------- exact far-edge ef: ssp(be1)@We2+be2 ----------------
__global__ void efc_kernel(const float* __restrict__ be1, const float* __restrict__ We2,
                           const float* __restrict__ be2) {
    __shared__ float sxc[NG];
    const int t = threadIdx.x;
    if (t < NG) sxc[t] = sspf(be1[t]);
    __syncthreads();
    float v = be2[t];
    for (int k = 0; k < NG; k++) v = fmaf(sxc[k], We2[k * NB + t], v);
    g_efc[t] = v;
}

// ---------------- ef(d) table for d in [0,6]: block per bin ----------------
__global__ void table_kernel(const float* __restrict__ We1, const float* __restrict__ be1,
                             const float* __restrict__ We2, const float* __restrict__ be2) {
    __shared__ float gg[NG];
    __shared__ float sx[NG];
    const int b = blockIdx.x, t = threadIdx.x;
    const float width = 5.0f / 49.0f;
    const float coeff = -0.5f / (width * width);
    float d = (float)b * (DMAXT / (float)(NBINS - 1));
    if (t < NG) {
        float df = d - (float)t * width;
        gg[t] = expf(coeff * df * df);
    }
    __syncthreads();
    if (t < NG) {
        float x = be1[t];
        #pragma unroll 10
        for (int m = 0; m < NG; m++) x = fmaf(gg[m], We1[m * NG + t], x);
        sx[t] = sspf(x);
    }
    __syncthreads();
    float ef = be2[t];
    #pragma unroll 10
    for (int k = 0; k < NG; k++) ef = fmaf(sx[k], We2[k * NB + t], ef);
    g_table[b * NB + t] = ef;
}

// ---------------- GEMM: buffers bound in device code via selector ----------------
// which = 0: nodef = h @ W + b ; 1: t1 = ssp(agg @ W + b) ; 2: h += t1 @ W + b
// 64-row tile, 256 threads, 4 column panels of 32; thread = 8 rows x 1 col.
__global__ void __launch_bounds__(256) gemm_kernel(const float* __restrict__ W,
                                                   const float* __restrict__ bias,
                                                   int which) {
    const float* A   = (which == 0) ? g_h     : (which == 1) ? g_agg : g_t1;
    float*       out = (which == 0) ? g_nodef : (which == 1) ? g_t1  : g_h;

    __shared__ __align__(16) float At[64 * NB];   // 32 KB, row-major
    __shared__ float Wp[NB * 32];                 // 16 KB
    const int tid  = threadIdx.x;
    const int row0 = blockIdx.x * 64;
    const int lane = tid & 31;
    const int r0   = (tid >> 5) * 8;

    {
        const int nrem = N_ATOMS - row0;
        for (int idx = tid; idx < 64 * (NB / 4); idx += 256) {
            int r = idx >> 5, k4 = idx & 31;
            float4 v = make_float4(0.f, 0.f, 0.f, 0.f);
            if (r < nrem) v = *(const float4*)&A[(row0 + r) * NB + k4 * 4];
            *(float4*)&At[r * NB + k4 * 4] = v;
        }
    }

    #pragma unroll
    for (int pass = 0; pass < 4; pass++) {
        const int cbase = pass * 32;
        __syncthreads();
        for (int idx = tid; idx < NB * 32; idx += 256) {
            int k = idx >> 5, c = idx & 31;
            Wp[k * 32 + c] = W[k * NB + cbase + c];
        }
        __syncthreads();

        float acc[8];
        #pragma unroll
        for (int rr = 0; rr < 8; rr++) acc[rr] = 0.0f;

        #pragma unroll 2
        for (int k0 = 0; k0 < NB; k0 += 4) {
            float w0 = Wp[(k0 + 0) * 32 + lane];
            float w1 = Wp[(k0 + 1) * 32 + lane];
            float w2 = Wp[(k0 + 2) * 32 + lane];
            float w3 = Wp[(k0 + 3) * 32 + lane];
            #pragma unroll
            for (int rr = 0; rr < 8; rr++) {
                const float4 av = *(const float4*)&At[(r0 + rr) * NB + k0];
                acc[rr] = fmaf(av.x, w0, acc[rr]);
                acc[rr] = fmaf(av.y, w1, acc[rr]);
                acc[rr] = fmaf(av.z, w2, acc[rr]);
                acc[rr] = fmaf(av.w, w3, acc[rr]);
            }
        }

        const float bv = bias[cbase + lane];
        #pragma unroll
        for (int rr = 0; rr < 8; rr++) {
            int r = row0 + r0 + rr;
            if (r >= N_ATOMS) break;
            float o = acc[rr] + bv;
            if (which == 1) o = sspf(o);
            float* p = &out[r * NB + cbase + lane];
            if (which == 2) o += *p;
            *p = o;
        }
    }
}

// ---------------- aggregation: warp per node, CSR gather + table lerp ----------------
__global__ void __launch_bounds__(256) gather_kernel() {
    int gtid = blockIdx.x * blockDim.x + threadIdx.x;
    int node = gtid >> 5;
    if (node >= N_ATOMS) return;
    int lane = threadIdx.x & 31;
    const int s = g_rowptr[node];
    const int e = g_rowptr[node + 1];
    const float4 efc = *(const float4*)&g_efc[4 * lane];
    float4 av = make_float4(0.f, 0.f, 0.f, 0.f);   // table part
    float4 ac = make_float4(0.f, 0.f, 0.f, 0.f);   // far (constant-ef) part
    for (int p = s; p < e; p++) {
        int other = g_iother[p];
        int bin   = g_ibin[p];
        const float4 nf = *(const float4*)&g_nodef[other * NB + 4 * lane];
        if (bin < 0) {
            ac.x += nf.x; ac.y += nf.y; ac.z += nf.z; ac.w += nf.w;
        } else {
            float fr = g_ifrac[p];
            const float4 t0 = *(const float4*)&g_table[bin * NB + 4 * lane];
            const float4 t1 = *(const float4*)&g_table[(bin + 1) * NB + 4 * lane];
            av.x = fmaf(nf.x, fmaf(fr, t1.x - t0.x, t0.x), av.x);
            av.y = fmaf(nf.y, fmaf(fr, t1.y - t0.y, t0.y), av.y);
            av.z = fmaf(nf.z, fmaf(fr, t1.z - t0.z, t0.z), av.z);
            av.w = fmaf(nf.w, fmaf(fr, t1.w - t0.w, t0.w), av.w);
        }
    }
    av.x = fmaf(ac.x, efc.x, av.x);
    av.y = fmaf(ac.y, efc.y, av.y);
    av.z = fmaf(ac.z, efc.z, av.z);
    av.w = fmaf(ac.w, efc.w, av.w);
    *(float4*)&g_agg[node * NB + 4 * lane] = av;
}

// ---------------- final head ----------------
__global__ void __launch_bounds__(256) eatom_kernel(const float* __restrict__ W1,
                                                    const float* __restrict__ b1,
                                                    const float* __restrict__ W2,
                                                    const float* __restrict__ b2) {
    __shared__ float w1s[NB * 64];
    __shared__ float w2s[64];
    __shared__ float b1s[64];
    const int tid = threadIdx.x;
    for (int idx = tid; idx < NB * 64; idx += 256) w1s[idx] = W1[idx];
    if (tid < 64) { w2s[tid] = W2[tid]; b1s[tid] = b1[tid]; }
    __syncthreads();
    int atom = blockIdx.x * blockDim.x + tid;
    if (atom >= N_ATOMS) return;
    const float* hr = &g_h[atom * NB];
    float e = 0.0f;
    #pragma unroll
    for (int cc = 0; cc < 8; cc++) {
        float accv[8];
        #pragma unroll
        for (int c = 0; c < 8; c++) accv[c] = b1s[cc * 8 + c];
        for (int k = 0; k < NB; k++) {
            float hv = hr[k];
            #pragma unroll
            for (int c = 0; c < 8; c++) accv[c] = fmaf(hv, w1s[k * 64 + cc * 8 + c], accv[c]);
        }
        #pragma unroll
        for (int c = 0; c < 8; c++) e += sspf(accv[c]) * w2s[cc * 8 + c];
    }
    g_eatom[atom] = e + b2[0];
}

__global__ void molred_kernel(float* __restrict__ out, int nmol) {
    __shared__ float s[256];
    const int m = blockIdx.x, tid = threadIdx.x;
    if (m >= nmol) return;
    float v = 0.0f;
    for (int i = tid; i < MOLSZ; i += 256) v += g_eatom[m * MOLSZ + i];
    s[tid] = v;
    __syncthreads();
    for (int off = 128; off > 0; off >>= 1) {
        if (tid < off) s[tid] += s[tid + off];
        __syncthreads();
    }
    if (tid == 0) out[m] = s[0];
}

// ---------------- launch ----------------
extern "C" void kernel_launch(void* const* d_in, const int* in_sizes, int n_in,
                              void* d_out, int out_size) {
    const int*   r     = (const int*)  d_in[0];
    const float* xyz   = (const float*)d_in[1];
    const int*   a     = (const int*)  d_in[2];

    int base = 3;
    if (in_sizes[3] == 1 || (n_in > 4 && in_sizes[4] == 12800)) base = 4;

    const float* embed = (const float*)d_in[base + 0];
    const float* Wn    = (const float*)d_in[base + 1];
    const float* bn    = (const float*)d_in[base + 2];
    const float* We1   = (const float*)d_in[base + 3];
    const float* be1   = (const float*)d_in[base + 4];
    const float* We2   = (const float*)d_in[base + 5];
    const float* be2   = (const float*)d_in[base + 6];
    const float* Wu1   = (const float*)d_in[base + 7];
    const float* bu1   = (const float*)d_in[base + 8];
    const float* Wu2   = (const float*)d_in[base + 9];
    const float* bu2   = (const float*)d_in[base + 10];
    const float* W1    = (const float*)d_in[base + 11];
    const float* b1    = (const float*)d_in[base + 12];
    const float* W2    = (const float*)d_in[base + 13];
    const float* b2    = (const float*)d_in[base + 14];
    float* out = (float*)d_out;
    const int nmol = out_size;

    const int EB = (N_EDGES + 255) / 256;
    const int GB = (N_ATOMS + 63) / 64;
    const int ZB = (N_ATOMS * NB + 255) / 256;
    const int AB = (N_ATOMS * 32 + 255) / 256;

    zero_counts_kernel<<<(N_ATOMS + 255) / 256, 256>>>();
    edge_prep_kernel<<<EB, 256>>>(a, xyz);
    scan_kernel<<<1, 1024>>>();
    fill_kernel<<<EB, 256>>>(a);
    h_init_kernel<<<ZB, 256>>>(r, embed);

    for (int l = 0; l < N_CONV; l++) {
        efc_kernel<<<1, NB>>>(be1 + l * NG, We2 + l * NG * NB, be2 + l * NB);
        table_kernel<<<NBINS, NB>>>(We1 + l * NG * NG, be1 + l * NG,
                                    We2 + l * NG * NB, be2 + l * NB);
        gemm_kernel<<<GB, 256>>>(Wn + l * NB * NB, bn + l * NB, 0);   // nodef = h@Wn+bn
        gather_kernel<<<AB, 256>>>();                                 // agg
        gemm_kernel<<<GB, 256>>>(Wu1 + l * NB * NB, bu1 + l * NB, 1); // t1 = ssp(agg@Wu1+bu1)
        gemm_kernel<<<GB, 256>>>(Wu2 + l * NB * NB, bu2 + l * NB, 2); // h += t1@Wu2+bu2
    }

    eatom_kernel<<<(N_ATOMS + 255) / 256, 256>>>(W1, b1, W2, b2);
    molred_kernel<<<nmol, 256>>>(out, nmol);
}

// round 12
// speedup vs baseline: 2.6346x; 1.1779x over previous
#include <cuda_runtime.h>
#include <math.h>

#define N_ATOMS   50000
#define N_EDGES   500000
#define NB        128
#define NG        50
#define N_CONV    3
#define MOLSZ     1000
#define NBINS     6144
#define DMAXT     6.0f
#define SCAN_CH   256
#define SCAN_NB   ((N_ATOMS + SCAN_CH - 1) / SCAN_CH)   // 196

// ---------------- device scratch (referenced ONLY inside device code!) ----------------
__device__ __align__(16) float g_h     [N_ATOMS * NB];
__device__ __align__(16) float g_nodef [N_ATOMS * NB];
__device__ __align__(16) float g_agg   [N_ATOMS * NB];
__device__ __align__(16) float g_table3[N_CONV * NBINS * NB];   // 9.4 MB
__device__ __align__(16) float g_efc3  [N_CONV * NB];
__device__ int   g_counts[N_ATOMS];
__device__ int   g_cursor[N_ATOMS];
__device__ int   g_rowptr[N_ATOMS + 1];
__device__ int   g_bsum[SCAN_NB];
__device__ int   g_boff[SCAN_NB];
__device__ int   g_ebin [N_EDGES];
__device__ float g_efrac[N_EDGES];
__device__ __align__(16) int4 g_inc[2 * N_EDGES];   // {other, bin, frac_bits, 0}
__device__ float g_eatom[N_ATOMS];

__device__ __forceinline__ float sspf(float x) {
    return fmaxf(x, 0.0f) + log1pf(expf(-fabsf(x))) - 0.6931471805599453f;
}

// ---------------- CSR build ----------------
__global__ void zero_counts_kernel() {
    int i = blockIdx.x * blockDim.x + threadIdx.x;
    if (i < N_ATOMS) g_counts[i] = 0;
}

__global__ void edge_prep_kernel(const int* __restrict__ a, const float* __restrict__ xyz) {
    int e = blockIdx.x * blockDim.x + threadIdx.x;
    if (e >= N_EDGES) return;
    int i = a[2 * e], j = a[2 * e + 1];
    float dx = xyz[3 * i + 0] - xyz[3 * j + 0];
    float dy = xyz[3 * i + 1] - xyz[3 * j + 1];
    float dz = xyz[3 * i + 2] - xyz[3 * j + 2];
    float d = sqrtf(dx * dx + dy * dy + dz * dz);
    int bin; float fr;
    if (d <= DMAXT) {
        float t = d * ((float)(NBINS - 1) / DMAXT);
        bin = (int)t;
        if (bin > NBINS - 2) bin = NBINS - 2;
        fr = t - (float)bin;
    } else {
        bin = -1; fr = 0.0f;
    }
    g_ebin[e] = bin;
    g_efrac[e] = fr;
    atomicAdd(&g_counts[i], 1);
    atomicAdd(&g_counts[j], 1);
}

// parallel scan: per-chunk exclusive prefix + chunk totals
__global__ void scan1_kernel() {
    __shared__ int s[SCAN_CH];
    const int b = blockIdx.x, t = threadIdx.x;
    int i = b * SCAN_CH + t;
    int v = (i < N_ATOMS) ? g_counts[i] : 0;
    s[t] = v;
    __syncthreads();
    // inclusive scan in shared
    for (int off = 1; off < SCAN_CH; off <<= 1) {
        int add = (t >= off) ? s[t - off] : 0;
        __syncthreads();
        s[t] += add;
        __syncthreads();
    }
    if (i < N_ATOMS) g_rowptr[i] = s[t] - v;   // exclusive within chunk
    if (t == SCAN_CH - 1) g_bsum[b] = s[t];
}

__global__ void scan2_kernel() {   // 1 block, >= SCAN_NB threads
    __shared__ int s[256];
    int t = threadIdx.x;
    int v = (t < SCAN_NB) ? g_bsum[t] : 0;
    s[t] = v;
    __syncthreads();
    for (int off = 1; off < 256; off <<= 1) {
        int add = (t >= off) ? s[t - off] : 0;
        __syncthreads();
        s[t] += add;
        __syncthreads();
    }
    if (t < SCAN_NB) g_boff[t] = s[t] - v;     // exclusive chunk offsets
}

__global__ void scan3_kernel() {
    int i = blockIdx.x * blockDim.x + threadIdx.x;
    if (i < N_ATOMS) {
        int v = g_rowptr[i] + g_boff[i / SCAN_CH];
        g_rowptr[i] = v;
        g_cursor[i] = v;
    }
    if (i == 0) g_rowptr[N_ATOMS] = 2 * N_EDGES;
}

__global__ void fill_kernel(const int* __restrict__ a) {
    int e = blockIdx.x * blockDim.x + threadIdx.x;
    if (e >= N_EDGES) return;
    int i = a[2 * e], j = a[2 * e + 1];
    int bin = g_ebin[e];
    int frb = __float_as_int(g_efrac[e]);
    int p = atomicAdd(&g_cursor[i], 1);
    g_inc[p] = make_int4(j, bin, frb, 0);
    p = atomicAdd(&g_cursor[j], 1);
    g_inc[p] = make_int4(i, bin, frb, 0);
}

// ---------------- embedding ----------------
__global__ void h_init_kernel(const int* __restrict__ r, const float* __restrict__ embed) {
    int idx = blockIdx.x * blockDim.x + threadIdx.x;
    if (idx >= N_ATOMS * NB) return;
    int row = idx >> 7, c = idx & 127;
    g_h[idx] = embed[r[row] * NB + c];
}

// ---------------- far-edge ef (exact), all layers: block = layer ----------------
__global__ void efc_kernel(const float* __restrict__ be1, const float* __restrict__ We2,
                           const float* __restrict__ be2) {
    __shared__ float sxc[NG];
    const int l = blockIdx.x, t = threadIdx.x;
    if (t < NG) sxc[t] = sspf(be1[l * NG + t]);
    __syncthreads();
    float v = be2[l * NB + t];
    for (int k = 0; k < NG; k++) v = fmaf(sxc[k], We2[l * NG * NB + k * NB + t], v);
    g_efc3[l * NB + t] = v;
}

// ---------------- ef(d) tables, ALL layers in one pass (Gaussians reused) ----------------
__global__ void table_kernel(const float* __restrict__ We1, const float* __restrict__ be1,
                             const float* __restrict__ We2, const float* __restrict__ be2) {
    __shared__ float gg[NG];
    __shared__ float sx[NG];
    const int b = blockIdx.x, t = threadIdx.x;
    const float width = 5.0f / 49.0f;
    const float coeff = -0.5f / (width * width);
    float d = (float)b * (DMAXT / (float)(NBINS - 1));
    if (t < NG) {
        float df = d - (float)t * width;
        gg[t] = expf(coeff * df * df);
    }
    __syncthreads();
    for (int l = 0; l < N_CONV; l++) {
        if (t < NG) {
            float x = be1[l * NG + t];
            const float* W1l = We1 + l * NG * NG;
            #pragma unroll 10
            for (int m = 0; m < NG; m++) x = fmaf(gg[m], W1l[m * NG + t], x);
            sx[t] = sspf(x);
        }
        __syncthreads();
        float ef = be2[l * NB + t];
        const float* W2l = We2 + l * NG * NB;
        #pragma unroll 10
        for (int k = 0; k < NG; k++) ef = fmaf(sx[k], W2l[k * NB + t], ef);
        g_table3[(l * NBINS + b) * NB + t] = ef;
        __syncthreads();
    }
}

// ---------------- GEMM: nodef = h @ Wn + bn ----------------
__global__ void __launch_bounds__(256) gemm_nodef_kernel(const float* __restrict__ W,
                                                         const float* __restrict__ bias) {
    __shared__ __align__(16) float At[64 * NB];   // 32 KB
    __shared__ float Wp[NB * 32];                 // 16 KB
    const int tid  = threadIdx.x;
    const int row0 = blockIdx.x * 64;
    const int lane = tid & 31;
    const int r0   = (tid >> 5) * 8;

    {
        const int nrem = N_ATOMS - row0;
        for (int idx = tid; idx < 64 * (NB / 4); idx += 256) {
            int r = idx >> 5, k4 = idx & 31;
            float4 v = make_float4(0.f, 0.f, 0.f, 0.f);
            if (r < nrem) v = *(const float4*)&g_h[(row0 + r) * NB + k4 * 4];
            *(float4*)&At[r * NB + k4 * 4] = v;
        }
    }

    #pragma unroll
    for (int pass = 0; pass < 4; pass++) {
        const int cbase = pass * 32;
        __syncthreads();
        for (int idx = tid; idx < NB * 32; idx += 256) {
            int k = idx >> 5, c = idx & 31;
            Wp[k * 32 + c] = W[k * NB + cbase + c];
        }
        __syncthreads();

        float acc[8];
        #pragma unroll
        for (int rr = 0; rr < 8; rr++) acc[rr] = 0.0f;
        #pragma unroll 2
        for (int k0 = 0; k0 < NB; k0 += 4) {
            float w0 = Wp[(k0 + 0) * 32 + lane];
            float w1 = Wp[(k0 + 1) * 32 + lane];
            float w2 = Wp[(k0 + 2) * 32 + lane];
            float w3 = Wp[(k0 + 3) * 32 + lane];
            #pragma unroll
            for (int rr = 0; rr < 8; rr++) {
                const float4 av = *(const float4*)&At[(r0 + rr) * NB + k0];
                acc[rr] = fmaf(av.x, w0, acc[rr]);
                acc[rr] = fmaf(av.y, w1, acc[rr]);
                acc[rr] = fmaf(av.z, w2, acc[rr]);
                acc[rr] = fmaf(av.w, w3, acc[rr]);
            }
        }
        const float bv = bias[cbase + lane];
        #pragma unroll
        for (int rr = 0; rr < 8; rr++) {
            int r = row0 + r0 + rr;
            if (r >= N_ATOMS) break;
            g_nodef[r * NB + cbase + lane] = acc[rr] + bv;
        }
    }
}

// ---------------- fused update: h += ssp(agg @ Wu1 + bu1) @ Wu2 + bu2 ----------------
__global__ void __launch_bounds__(256) gemm_update_kernel(const float* __restrict__ Wu1,
                                                          const float* __restrict__ bu1,
                                                          const float* __restrict__ Wu2,
                                                          const float* __restrict__ bu2) {
    __shared__ __align__(16) float At[64 * NB];   // 32 KB (agg tile, then t1 tile)
    __shared__ float Wp[NB * 32];                 // 16 KB
    const int tid  = threadIdx.x;
    const int row0 = blockIdx.x * 64;
    const int lane = tid & 31;
    const int r0   = (tid >> 5) * 8;
    const int nrem = N_ATOMS - row0;

    for (int idx = tid; idx < 64 * (NB / 4); idx += 256) {
        int r = idx >> 5, k4 = idx & 31;
        float4 v = make_float4(0.f, 0.f, 0.f, 0.f);
        if (r < nrem) v = *(const float4*)&g_agg[(row0 + r) * NB + k4 * 4];
        *(float4*)&At[r * NB + k4 * 4] = v;
    }

    // stage 1: t1 = ssp(agg @ Wu1 + bu1), panels held in registers
    float t1r[4][8];
    #pragma unroll
    for (int pass = 0; pass < 4; pass++) {
        const int cbase = pass * 32;
        __syncthreads();
        for (int idx = tid; idx < NB * 32; idx += 256) {
            int k = idx >> 5, c = idx & 31;
            Wp[k * 32 + c] = Wu1[k * NB + cbase + c];
        }
        __syncthreads();

        float acc[8];
        #pragma unroll
        for (int rr = 0; rr < 8; rr++) acc[rr] = 0.0f;
        #pragma unroll 2
        for (int k0 = 0; k0 < NB; k0 += 4) {
            float w0 = Wp[(k0 + 0) * 32 + lane];
            float w1 = Wp[(k0 + 1) * 32 + lane];
            float w2 = Wp[(k0 + 2) * 32 + lane];
            float w3 = Wp[(k0 + 3) * 32 + lane];
            #pragma unroll
            for (int rr = 0; rr < 8; rr++) {
                const float4 av = *(const float4*)&At[(r0 + rr) * NB + k0];
                acc[rr] = fmaf(av.x, w0, acc[rr]);
                acc[rr] = fmaf(av.y, w1, acc[rr]);
                acc[rr] = fmaf(av.z, w2, acc[rr]);
                acc[rr] = fmaf(av.w, w3, acc[rr]);
            }
        }
        const float bv = bu1[cbase + lane];
        #pragma unroll
        for (int rr = 0; rr < 8; rr++) t1r[pass][rr] = sspf(acc[rr] + bv);
    }

    // swap t1 into At (in place)
    __syncthreads();
    #pragma unroll
    for (int pass = 0; pass < 4; pass++)
        #pragma unroll
        for (int rr = 0; rr < 8; rr++)
            At[(r0 + rr) * NB + pass * 32 + lane] = t1r[pass][rr];

    // stage 2: h += t1 @ Wu2 + bu2
    #pragma unroll
    for (int pass = 0; pass < 4; pass++) {
        const int cbase = pass * 32;
        __syncthreads();
        for (int idx = tid; idx < NB * 32; idx += 256) {
            int k = idx >> 5, c = idx & 31;
            Wp[k * 32 + c] = Wu2[k * NB + cbase + c];
        }
        __syncthreads();

        float acc[8];
        #pragma unroll
        for (int rr = 0; rr < 8; rr++) acc[rr] = 0.0f;
        #pragma unroll 2
        for (int k0 = 0; k0 < NB; k0 += 4) {
            float w0 = Wp[(k0 + 0) * 32 + lane];
            float w1 = Wp[(k0 + 1) * 32 + lane];
            float w2 = Wp[(k0 + 2) * 32 + lane];
            float w3 = Wp[(k0 + 3) * 32 + lane];
            #pragma unroll
            for (int rr = 0; rr < 8; rr++) {
                const float4 av = *(const float4*)&At[(r0 + rr) * NB + k0];
                acc[rr] = fmaf(av.x, w0, acc[rr]);
                acc[rr] = fmaf(av.y, w1, acc[rr]);
                acc[rr] = fmaf(av.z, w2, acc[rr]);
                acc[rr] = fmaf(av.w, w3, acc[rr]);
            }
        }
        const float bv = bu2[cbase + lane];
        #pragma unroll
        for (int rr = 0; rr < 8; rr++) {
            int r = row0 + r0 + rr;
            if (r >= N_ATOMS) break;
            g_h[r * NB + cbase + lane] += acc[rr] + bv;
        }
    }
}

// ---------------- aggregation: warp per node, prefetched CSR gather + table lerp ----------------
__global__ void __launch_bounds__(256) gather_kernel(int l) {
    int gtid = blockIdx.x * blockDim.x + threadIdx.x;
    int node = gtid >> 5;
    if (node >= N_ATOMS) return;
    int lane = threadIdx.x & 31;
    const float* table = g_table3 + l * (NBINS * NB);
    const int s = g_rowptr[node];
    const int e = g_rowptr[node + 1];
    const float4 efc = *(const float4*)&g_efc3[l * NB + 4 * lane];
    float4 av = make_float4(0.f, 0.f, 0.f, 0.f);
    float4 ac = make_float4(0.f, 0.f, 0.f, 0.f);

    int4 cur;
    if (s < e) cur = g_inc[s];
    for (int p = s; p < e; p++) {
        int4 nxt;
        if (p + 1 < e) nxt = g_inc[p + 1];
        const int other = cur.x, bin = cur.y;
        const float4 nf = *(const float4*)&g_nodef[other * NB + 4 * lane];
        if (bin < 0) {
            ac.x += nf.x; ac.y += nf.y; ac.z += nf.z; ac.w += nf.w;
        } else {
            float fr = __int_as_float(cur.z);
            const float4 t0 = *(const float4*)&table[bin * NB + 4 * lane];
            const float4 t1 = *(const float4*)&table[(bin + 1) * NB + 4 * lane];
            av.x = fmaf(nf.x, fmaf(fr, t1.x - t0.x, t0.x), av.x);
            av.y = fmaf(nf.y, fmaf(fr, t1.y - t0.y, t0.y), av.y);
            av.z = fmaf(nf.z, fmaf(fr, t1.z - t0.z, t0.z), av.z);
            av.w = fmaf(nf.w, fmaf(fr, t1.w - t0.w, t0.w), av.w);
        }
        cur = nxt;
    }
    av.x = fmaf(ac.x, efc.x, av.x);
    av.y = fmaf(ac.y, efc.y, av.y);
    av.z = fmaf(ac.z, efc.z, av.z);
    av.w = fmaf(ac.w, efc.w, av.w);
    *(float4*)&g_agg[node * NB + 4 * lane] = av;
}

// ---------------- final head ----------------
__global__ void __launch_bounds__(256) eatom_kernel(const float* __restrict__ W1,
                                                    const float* __restrict__ b1,
                                                    const float* __restrict__ W2,
                                                    const float* __restrict__ b2) {
    __shared__ float w1s[NB * 64];
    __shared__ float w2s[64];
    __shared__ float b1s[64];
    const int tid = threadIdx.x;
    for (int idx = tid; idx < NB * 64; idx += 256) w1s[idx] = W1[idx];
    if (tid < 64) { w2s[tid] = W2[tid]; b1s[tid] = b1[tid]; }
    __syncthreads();
    int atom = blockIdx.x * blockDim.x + tid;
    if (atom >= N_ATOMS) return;
    const float* hr = &g_h[atom * NB];
    float e = 0.0f;
    #pragma unroll
    for (int cc = 0; cc < 8; cc++) {
        float accv[8];
        #pragma unroll
        for (int c = 0; c < 8; c++) accv[c] = b1s[cc * 8 + c];
        for (int k = 0; k < NB; k++) {
            float hv = hr[k];
            #pragma unroll
            for (int c = 0; c < 8; c++) accv[c] = fmaf(hv, w1s[k * 64 + cc * 8 + c], accv[c]);
        }
        #pragma unroll
        for (int c = 0; c < 8; c++) e += sspf(accv[c]) * w2s[cc * 8 + c];
    }
    g_eatom[atom] = e + b2[0];
}

__global__ void molred_kernel(float* __restrict__ out, int nmol) {
    __shared__ float s[256];
    const int m = blockIdx.x, tid = threadIdx.x;
    if (m >= nmol) return;
    float v = 0.0f;
    for (int i = tid; i < MOLSZ; i += 256) v += g_eatom[m * MOLSZ + i];
    s[tid] = v;
    __syncthreads();
    for (int off = 128; off > 0; off >>= 1) {
        if (tid < off) s[tid] += s[tid + off];
        __syncthreads();
    }
    if (tid == 0) out[m] = s[0];
}

// ---------------- launch ----------------
extern "C" void kernel_launch(void* const* d_in, const int* in_sizes, int n_in,
                              void* d_out, int out_size) {
    const int*   r     = (const int*)  d_in[0];
    const float* xyz   = (const float*)d_in[1];
    const int*   a     = (const int*)  d_in[2];

    int base = 3;
    if (in_sizes[3] == 1 || (n_in > 4 && in_sizes[4] == 12800)) base = 4;

    const float* embed = (const float*)d_in[base + 0];
    const float* Wn    = (const float*)d_in[base + 1];
    const float* bn    = (const float*)d_in[base + 2];
    const float* We1   = (const float*)d_in[base + 3];
    const float* be1   = (const float*)d_in[base + 4];
    const float* We2   = (const float*)d_in[base + 5];
    const float* be2   = (const float*)d_in[base + 6];
    const float* Wu1   = (const float*)d_in[base + 7];
    const float* bu1   = (const float*)d_in[base + 8];
    const float* Wu2   = (const float*)d_in[base + 9];
    const float* bu2   = (const float*)d_in[base + 10];
    const float* W1    = (const float*)d_in[base + 11];
    const float* b1    = (const float*)d_in[base + 12];
    const float* W2    = (const float*)d_in[base + 13];
    const float* b2    = (const float*)d_in[base + 14];
    float* out = (float*)d_out;
    const int nmol = out_size;

    const int EB = (N_EDGES + 255) / 256;
    const int GB = (N_ATOMS + 63) / 64;
    const int ZB = (N_ATOMS * NB + 255) / 256;
    const int AB = (N_ATOMS * 32 + 255) / 256;
    const int NBK = (N_ATOMS + 255) / 256;

    zero_counts_kernel<<<NBK, 256>>>();
    edge_prep_kernel<<<EB, 256>>>(a, xyz);
    scan1_kernel<<<SCAN_NB, SCAN_CH>>>();
    scan2_kernel<<<1, 256>>>();
    scan3_kernel<<<NBK, 256>>>();
    fill_kernel<<<EB, 256>>>(a);
    h_init_kernel<<<ZB, 256>>>(r, embed);
    efc_kernel<<<N_CONV, NB>>>(be1, We2, be2);
    table_kernel<<<NBINS, NB>>>(We1, be1, We2, be2);

    for (int l = 0; l < N_CONV; l++) {
        gemm_nodef_kernel<<<GB, 256>>>(Wn + l * NB * NB, bn + l * NB);
        gather_kernel<<<AB, 256>>>(l);
        gemm_update_kernel<<<GB, 256>>>(Wu1 + l * NB * NB, bu1 + l * NB,
                                        Wu2 + l * NB * NB, bu2 + l * NB);
    }

    eatom_kernel<<<NBK, 256>>>(W1, b1, W2, b2);
    molred_kernel<<<nmol, 256>>>(out, nmol);
}

// round 13
// speedup vs baseline: 2.9225x; 1.1093x over previous
#include <cuda_runtime.h>
#include <cuda_fp16.h>
#include <math.h>

#define N_ATOMS   50000
#define N_EDGES   500000
#define NB        128
#define NG        50
#define N_CONV    3
#define MOLSZ     1000
#define NBINS     6144
#define DMAXT     6.0f
#define SCAN_CH   256
#define SCAN_NB   ((N_ATOMS + SCAN_CH - 1) / SCAN_CH)

// ---------------- device scratch (referenced ONLY inside device code!) ----------------
__device__ __align__(16) float  g_h     [N_ATOMS * NB];
__device__ __align__(16) __half g_nodefh[N_ATOMS * NB];          // fp16 node features
__device__ __align__(16) float  g_agg   [N_ATOMS * NB];
__device__ __align__(16) __half g_table3[N_CONV * NBINS * NB];   // fp16 ef tables, 4.7 MB
__device__ __align__(16) float  g_efc3  [N_CONV * NB];
__device__ int   g_counts[N_ATOMS];
__device__ int   g_cursor[N_ATOMS];
__device__ int   g_rowptr[N_ATOMS + 1];
__device__ int   g_bsum[SCAN_NB];
__device__ int   g_boff[SCAN_NB];
__device__ int   g_emeta[N_EDGES];                               // bin<<16|frac16, or -1 far
__device__ __align__(8) int2 g_inc[2 * N_EDGES];                 // {other, meta}
__device__ float g_eatom[N_ATOMS];

__device__ __forceinline__ float sspf(float x) {
    return fmaxf(x, 0.0f) + log1pf(expf(-fabsf(x))) - 0.6931471805599453f;
}

// ---------------- CSR build ----------------
__global__ void zero_counts_kernel() {
    int i = blockIdx.x * blockDim.x + threadIdx.x;
    if (i < N_ATOMS) g_counts[i] = 0;
}

__global__ void edge_prep_kernel(const int* __restrict__ a, const float* __restrict__ xyz) {
    int e = blockIdx.x * blockDim.x + threadIdx.x;
    if (e >= N_EDGES) return;
    int i = a[2 * e], j = a[2 * e + 1];
    float dx = xyz[3 * i + 0] - xyz[3 * j + 0];
    float dy = xyz[3 * i + 1] - xyz[3 * j + 1];
    float dz = xyz[3 * i + 2] - xyz[3 * j + 2];
    float d = sqrtf(dx * dx + dy * dy + dz * dz);
    int meta;
    if (d <= DMAXT) {
        float t = d * ((float)(NBINS - 1) / DMAXT);
        int bin = (int)t;
        if (bin > NBINS - 2) bin = NBINS - 2;
        float fr = t - (float)bin;
        int f16 = (int)(fr * 65535.0f + 0.5f);
        if (f16 > 65535) f16 = 65535;
        meta = (bin << 16) | f16;
    } else {
        meta = -1;
    }
    g_emeta[e] = meta;
    atomicAdd(&g_counts[i], 1);
    atomicAdd(&g_counts[j], 1);
}

__global__ void scan1_kernel() {
    __shared__ int s[SCAN_CH];
    const int b = blockIdx.x, t = threadIdx.x;
    int i = b * SCAN_CH + t;
    int v = (i < N_ATOMS) ? g_counts[i] : 0;
    s[t] = v;
    __syncthreads();
    for (int off = 1; off < SCAN_CH; off <<= 1) {
        int add = (t >= off) ? s[t - off] : 0;
        __syncthreads();
        s[t] += add;
        __syncthreads();
    }
    if (i < N_ATOMS) g_rowptr[i] = s[t] - v;
    if (t == SCAN_CH - 1) g_bsum[b] = s[t];
}

__global__ void scan2_kernel() {
    __shared__ int s[256];
    int t = threadIdx.x;
    int v = (t < SCAN_NB) ? g_bsum[t] : 0;
    s[t] = v;
    __syncthreads();
    for (int off = 1; off < 256; off <<= 1) {
        int add = (t >= off) ? s[t - off] : 0;
        __syncthreads();
        s[t] += add;
        __syncthreads();
    }
    if (t < SCAN_NB) g_boff[t] = s[t] - v;
}

__global__ void scan3_kernel() {
    int i = blockIdx.x * blockDim.x + threadIdx.x;
    if (i < N_ATOMS) {
        int v = g_rowptr[i] + g_boff[i / SCAN_CH];
        g_rowptr[i] = v;
        g_cursor[i] = v;
    }
    if (i == 0) g_rowptr[N_ATOMS] = 2 * N_EDGES;
}

__global__ void fill_kernel(const int* __restrict__ a) {
    int e = blockIdx.x * blockDim.x + threadIdx.x;
    if (e >= N_EDGES) return;
    int i = a[2 * e], j = a[2 * e + 1];
    int meta = g_emeta[e];
    int p = atomicAdd(&g_cursor[i], 1);
    g_inc[p] = make_int2(j, meta);
    p = atomicAdd(&g_cursor[j], 1);
    g_inc[p] = make_int2(i, meta);
}

// ---------------- embedding ----------------
__global__ void h_init_kernel(const int* __restrict__ r, const float* __restrict__ embed) {
    int idx = blockIdx.x * blockDim.x + threadIdx.x;
    if (idx >= N_ATOMS * NB) return;
    int row = idx >> 7, c = idx & 127;
    g_h[idx] = embed[r[row] * NB + c];
}

// ---------------- far-edge ef (exact, fp32), all layers ----------------
__global__ void efc_kernel(const float* __restrict__ be1, const float* __restrict__ We2,
                           const float* __restrict__ be2) {
    __shared__ float sxc[NG];
    const int l = blockIdx.x, t = threadIdx.x;
    if (t < NG) sxc[t] = sspf(be1[l * NG + t]);
    __syncthreads();
    float v = be2[l * NB + t];
    for (int k = 0; k < NG; k++) v = fmaf(sxc[k], We2[l * NG * NB + k * NB + t], v);
    g_efc3[l * NB + t] = v;
}

// ---------------- ef(d) tables (fp16), ALL layers in one pass ----------------
__global__ void table_kernel(const float* __restrict__ We1, const float* __restrict__ be1,
                             const float* __restrict__ We2, const float* __restrict__ be2) {
    __shared__ float gg[NG];
    __shared__ float sx[NG];
    const int b = blockIdx.x, t = threadIdx.x;
    const float width = 5.0f / 49.0f;
    const float coeff = -0.5f / (width * width);
    float d = (float)b * (DMAXT / (float)(NBINS - 1));
    if (t < NG) {
        float df = d - (float)t * width;
        gg[t] = expf(coeff * df * df);
    }
    __syncthreads();
    for (int l = 0; l < N_CONV; l++) {
        if (t < NG) {
            float x = be1[l * NG + t];
            const float* W1l = We1 + l * NG * NG;
            #pragma unroll 10
            for (int m = 0; m < NG; m++) x = fmaf(gg[m], W1l[m * NG + t], x);
            sx[t] = sspf(x);
        }
        __syncthreads();
        float ef = be2[l * NB + t];
        const float* W2l = We2 + l * NG * NB;
        #pragma unroll 10
        for (int k = 0; k < NG; k++) ef = fmaf(sx[k], W2l[k * NB + t], ef);
        g_table3[(l * NBINS + b) * NB + t] = __float2half_rn(ef);
        __syncthreads();
    }
}

// ---------------- GEMM: nodef(fp16) = h @ Wn + bn ----------------
__global__ void __launch_bounds__(256) gemm_nodef_kernel(const float* __restrict__ W,
                                                         const float* __restrict__ bias) {
    __shared__ __align__(16) float At[64 * NB];   // 32 KB
    __shared__ float Wp[NB * 32];                 // 16 KB
    const int tid  = threadIdx.x;
    const int row0 = blockIdx.x * 64;
    const int lane = tid & 31;
    const int r0   = (tid >> 5) * 8;

    {
        const int nrem = N_ATOMS - row0;
        for (int idx = tid; idx < 64 * (NB / 4); idx += 256) {
            int r = idx >> 5, k4 = idx & 31;
            float4 v = make_float4(0.f, 0.f, 0.f, 0.f);
            if (r < nrem) v = *(const float4*)&g_h[(row0 + r) * NB + k4 * 4];
            *(float4*)&At[r * NB + k4 * 4] = v;
        }
    }

    #pragma unroll
    for (int pass = 0; pass < 4; pass++) {
        const int cbase = pass * 32;
        __syncthreads();
        for (int idx = tid; idx < NB * 32; idx += 256) {
            int k = idx >> 5, c = idx & 31;
            Wp[k * 32 + c] = W[k * NB + cbase + c];
        }
        __syncthreads();

        float acc[8];
        #pragma unroll
        for (int rr = 0; rr < 8; rr++) acc[rr] = 0.0f;
        #pragma unroll 2
        for (int k0 = 0; k0 < NB; k0 += 4) {
            float w0 = Wp[(k0 + 0) * 32 + lane];
            float w1 = Wp[(k0 + 1) * 32 + lane];
            float w2 = Wp[(k0 + 2) * 32 + lane];
            float w3 = Wp[(k0 + 3) * 32 + lane];
            #pragma unroll
            for (int rr = 0; rr < 8; rr++) {
                const float4 av = *(const float4*)&At[(r0 + rr) * NB + k0];
                acc[rr] = fmaf(av.x, w0, acc[rr]);
                acc[rr] = fmaf(av.y, w1, acc[rr]);
                acc[rr] = fmaf(av.z, w2, acc[rr]);
                acc[rr] = fmaf(av.w, w3, acc[rr]);
            }
        }
        const float bv = bias[cbase + lane];
        #pragma unroll
        for (int rr = 0; rr < 8; rr++) {
            int r = row0 + r0 + rr;
            if (r >= N_ATOMS) break;
            g_nodefh[r * NB + cbase + lane] = __float2half_rn(acc[rr] + bv);
        }
    }
}

// ---------------- fused update: h += ssp(agg @ Wu1 + bu1) @ Wu2 + bu2 ----------------
__global__ void __launch_bounds__(256) gemm_update_kernel(const float* __restrict__ Wu1,
                                                          const float* __restrict__ bu1,
                                                          const float* __restrict__ Wu2,
                                                          const float* __restrict__ bu2) {
    __shared__ __align__(16) float At[64 * NB];   // agg tile, then t1 tile
    __shared__ float Wp[NB * 32];
    const int tid  = threadIdx.x;
    const int row0 = blockIdx.x * 64;
    const int lane = tid & 31;
    const int r0   = (tid >> 5) * 8;
    const int nrem = N_ATOMS - row0;

    for (int idx = tid; idx < 64 * (NB / 4); idx += 256) {
        int r = idx >> 5, k4 = idx & 31;
        float4 v = make_float4(0.f, 0.f, 0.f, 0.f);
        if (r < nrem) v = *(const float4*)&g_agg[(row0 + r) * NB + k4 * 4];
        *(float4*)&At[r * NB + k4 * 4] = v;
    }

    float t1r[4][8];
    #pragma unroll
    for (int pass = 0; pass < 4; pass++) {
        const int cbase = pass * 32;
        __syncthreads();
        for (int idx = tid; idx < NB * 32; idx += 256) {
            int k = idx >> 5, c = idx & 31;
            Wp[k * 32 + c] = Wu1[k * NB + cbase + c];
        }
        __syncthreads();

        float acc[8];
        #pragma unroll
        for (int rr = 0; rr < 8; rr++) acc[rr] = 0.0f;
        #pragma unroll 2
        for (int k0 = 0; k0 < NB; k0 += 4) {
            float w0 = Wp[(k0 + 0) * 32 + lane];
            float w1 = Wp[(k0 + 1) * 32 + lane];
            float w2 = Wp[(k0 + 2) * 32 + lane];
            float w3 = Wp[(k0 + 3) * 32 + lane];
            #pragma unroll
            for (int rr = 0; rr < 8; rr++) {
                const float4 av = *(const float4*)&At[(r0 + rr) * NB + k0];
                acc[rr] = fmaf(av.x, w0, acc[rr]);
                acc[rr] = fmaf(av.y, w1, acc[rr]);
                acc[rr] = fmaf(av.z, w2, acc[rr]);
                acc[rr] = fmaf(av.w, w3, acc[rr]);
            }
        }
        const float bv = bu1[cbase + lane];
        #pragma unroll
        for (int rr = 0; rr < 8; rr++) t1r[pass][rr] = sspf(acc[rr] + bv);
    }

    __syncthreads();
    #pragma unroll
    for (int pass = 0; pass < 4; pass++)
        #pragma unroll
        for (int rr = 0; rr < 8; rr++)
            At[(r0 + rr) * NB + pass * 32 + lane] = t1r[pass][rr];

    #pragma unroll
    for (int pass = 0; pass < 4; pass++) {
        const int cbase = pass * 32;
        __syncthreads();
        for (int idx = tid; idx < NB * 32; idx += 256) {
            int k = idx >> 5, c = idx & 31;
            Wp[k * 32 + c] = Wu2[k * NB + cbase + c];
        }
        __syncthreads();

        float acc[8];
        #pragma unroll
        for (int rr = 0; rr < 8; rr++) acc[rr] = 0.0f;
        #pragma unroll 2
        for (int k0 = 0; k0 < NB; k0 += 4) {
            float w0 = Wp[(k0 + 0) * 32 + lane];
            float w1 = Wp[(k0 + 1) * 32 + lane];
            float w2 = Wp[(k0 + 2) * 32 + lane];
            float w3 = Wp[(k0 + 3) * 32 + lane];
            #pragma unroll
            for (int rr = 0; rr < 8; rr++) {
                const float4 av = *(const float4*)&At[(r0 + rr) * NB + k0];
                acc[rr] = fmaf(av.x, w0, acc[rr]);
                acc[rr] = fmaf(av.y, w1, acc[rr]);
                acc[rr] = fmaf(av.z, w2, acc[rr]);
                acc[rr] = fmaf(av.w, w3, acc[rr]);
            }
        }
        const float bv = bu2[cbase + lane];
        #pragma unroll
        for (int rr = 0; rr < 8; rr++) {
            int r = row0 + r0 + rr;
            if (r >= N_ATOMS) break;
            g_h[r * NB + cbase + lane] += acc[rr] + bv;
        }
    }
}

// ---------------- aggregation: warp per node, fp16 gather + table lerp ----------------
__global__ void __launch_bounds__(256) gather_kernel(int l) {
    int gtid = blockIdx.x * blockDim.x + threadIdx.x;
    int node = gtid >> 5;
    if (node >= N_ATOMS) return;
    int lane = threadIdx.x & 31;
    const __half* table = g_table3 + l * (NBINS * NB);
    const int s = g_rowptr[node];
    const int e = g_rowptr[node + 1];
    const float4 efc = *(const float4*)&g_efc3[l * NB + 4 * lane];
    float4 av = make_float4(0.f, 0.f, 0.f, 0.f);
    float4 ac = make_float4(0.f, 0.f, 0.f, 0.f);

    int2 cur = make_int2(0, 0);
    if (s < e) cur = g_inc[s];
    for (int p = s; p < e; p++) {
        int2 nxt = make_int2(0, 0);
        if (p + 1 < e) nxt = g_inc[p + 1];
        const int other = cur.x, meta = cur.y;
        const uint2 nfu = *(const uint2*)&g_nodefh[other * NB + 4 * lane];
        const float2 nf01 = __half22float2(*(const __half2*)&nfu.x);
        const float2 nf23 = __half22float2(*(const __half2*)&nfu.y);
        if (meta < 0) {
            ac.x += nf01.x; ac.y += nf01.y; ac.z += nf23.x; ac.w += nf23.y;
        } else {
            const int bin = meta >> 16;
            const float fr = (float)(meta & 0xffff) * (1.0f / 65535.0f);
            const uint2 t0u = *(const uint2*)&table[bin * NB + 4 * lane];
            const uint2 t1u = *(const uint2*)&table[(bin + 1) * NB + 4 * lane];
            const float2 a01 = __half22float2(*(const __half2*)&t0u.x);
            const float2 a23 = __half22float2(*(const __half2*)&t0u.y);
            const float2 b01 = __half22float2(*(const __half2*)&t1u.x);
            const float2 b23 = __half22float2(*(const __half2*)&t1u.y);
            av.x = fmaf(nf01.x, fmaf(fr, b01.x - a01.x, a01.x), av.x);
            av.y = fmaf(nf01.y, fmaf(fr, b01.y - a01.y, a01.y), av.y);
            av.z = fmaf(nf23.x, fmaf(fr, b23.x - a23.x, a23.x), av.z);
            av.w = fmaf(nf23.y, fmaf(fr, b23.y - a23.y, a23.y), av.w);
        }
        cur = nxt;
    }
    av.x = fmaf(ac.x, efc.x, av.x);
    av.y = fmaf(ac.y, efc.y, av.y);
    av.z = fmaf(ac.z, efc.z, av.z);
    av.w = fmaf(ac.w, efc.w, av.w);
    *(float4*)&g_agg[node * NB + 4 * lane] = av;
}

// ---------------- final head: warp per atom x 16, smem row staging ----------------
#define EAT_APW 16
__global__ void __launch_bounds__(256) eatom_kernel(const float* __restrict__ W1,
                                                    const float* __restrict__ b1,
                                                    const float* __restrict__ W2,
                                                    const float* __restrict__ b2) {
    __shared__ float w1s[NB * 64];                    // 32 KB
    __shared__ float w2s[64];
    __shared__ float b1s[64];
    __shared__ __align__(16) float rowbuf[8][NB];     // 4 KB
    const int tid = threadIdx.x;
    for (int idx = tid; idx < NB * 64; idx += 256) w1s[idx] = W1[idx];
    if (tid < 64) { w2s[tid] = W2[tid]; b1s[tid] = b1[tid]; }
    __syncthreads();

    const int wid = tid >> 5, lane = tid & 31;
    const float b2v = b2[0];
    for (int it = 0; it < EAT_APW; it++) {
        int atom = (blockIdx.x * 8 + wid) * EAT_APW + it;
        if (atom >= N_ATOMS) break;
        *(float4*)&rowbuf[wid][lane * 4] = *(const float4*)&g_h[atom * NB + lane * 4];
        __syncwarp();
        float acc0 = b1s[lane], acc1 = b1s[lane + 32];
        #pragma unroll 4
        for (int k = 0; k < NB; k++) {
            float hv = rowbuf[wid][k];
            acc0 = fmaf(hv, w1s[k * 64 + lane], acc0);
            acc1 = fmaf(hv, w1s[k * 64 + 32 + lane], acc1);
        }
        float e = sspf(acc0) * w2s[lane] + sspf(acc1) * w2s[lane + 32];
        #pragma unroll
        for (int off = 16; off > 0; off >>= 1) e += __shfl_xor_sync(0xffffffffu, e, off);
        if (lane == 0) g_eatom[atom] = e + b2v;
        __syncwarp();
    }
}

__global__ void molred_kernel(float* __restrict__ out, int nmol) {
    __shared__ float s[256];
    const int m = blockIdx.x, tid = threadIdx.x;
    if (m >= nmol) return;
    float v = 0.0f;
    for (int i = tid; i < MOLSZ; i += 256) v += g_eatom[m * MOLSZ + i];
    s[tid] = v;
    __syncthreads();
    for (int off = 128; off > 0; off >>= 1) {
        if (tid < off) s[tid] += s[tid + off];
        __syncthreads();
    }
    if (tid == 0) out[m] = s[0];
}

// ---------------- launch ----------------
extern "C" void kernel_launch(void* const* d_in, const int* in_sizes, int n_in,
                              void* d_out, int out_size) {
    const int*   r     = (const int*)  d_in[0];
    const float* xyz   = (const float*)d_in[1];
    const int*   a     = (const int*)  d_in[2];

    int base = 3;
    if (in_sizes[3] == 1 || (n_in > 4 && in_sizes[4] == 12800)) base = 4;

    const float* embed = (const float*)d_in[base + 0];
    const float* Wn    = (const float*)d_in[base + 1];
    const float* bn    = (const float*)d_in[base + 2];
    const float* We1   = (const float*)d_in[base + 3];
    const float* be1   = (const float*)d_in[base + 4];
    const float* We2   = (const float*)d_in[base + 5];
    const float* be2   = (const float*)d_in[base + 6];
    const float* Wu1   = (const float*)d_in[base + 7];
    const float* bu1   = (const float*)d_in[base + 8];
    const float* Wu2   = (const float*)d_in[base + 9];
    const float* bu2   = (const float*)d_in[base + 10];
    const float* W1    = (const float*)d_in[base + 11];
    const float* b1    = (const float*)d_in[base + 12];
    const float* W2    = (const float*)d_in[base + 13];
    const float* b2    = (const float*)d_in[base + 14];
    float* out = (float*)d_out;
    const int nmol = out_size;

    const int EB  = (N_EDGES + 255) / 256;
    const int GB  = (N_ATOMS + 63) / 64;
    const int ZB  = (N_ATOMS * NB + 255) / 256;
    const int AB  = (N_ATOMS * 32 + 255) / 256;
    const int NBK = (N_ATOMS + 255) / 256;
    const int EATB = (N_ATOMS + 8 * EAT_APW - 1) / (8 * EAT_APW);

    zero_counts_kernel<<<NBK, 256>>>();
    edge_prep_kernel<<<EB, 256>>>(a, xyz);
    scan1_kernel<<<SCAN_NB, SCAN_CH>>>();
    scan2_kernel<<<1, 256>>>();
    scan3_kernel<<<NBK, 256>>>();
    fill_kernel<<<EB, 256>>>(a);
    h_init_kernel<<<ZB, 256>>>(r, embed);
    efc_kernel<<<N_CONV, NB>>>(be1, We2, be2);
    table_kernel<<<NBINS, NB>>>(We1, be1, We2, be2);

    for (int l = 0; l < N_CONV; l++) {
        gemm_nodef_kernel<<<GB, 256>>>(Wn + l * NB * NB, bn + l * NB);
        gather_kernel<<<AB, 256>>>(l);
        gemm_update_kernel<<<GB, 256>>>(Wu1 + l * NB * NB, bu1 + l * NB,
                                        Wu2 + l * NB * NB, bu2 + l * NB);
    }

    eatom_kernel<<<EATB, 256>>>(W1, b1, W2, b2);
    molred_kernel<<<nmol, 256>>>(out, nmol);
}

// round 14
// speedup vs baseline: 3.3783x; 1.1560x over previous
#include <cuda_runtime.h>
#include <cuda_fp16.h>
#include <math.h>

#define N_ATOMS   50000
#define N_EDGES   500000
#define NB        128
#define NG        50
#define N_CONV    3
#define MOLSZ     1000
#define NBINS     6144
#define DMAXT     6.0f
#define SCAN_CH   256
#define SCAN_NB   ((N_ATOMS + SCAN_CH - 1) / SCAN_CH)
#define SMEM_BIG  ((NB * NB + 64 * NB) * 4)   // 96 KB

// ---------------- device scratch (referenced ONLY inside device code!) ----------------
__device__ __align__(16) float  g_h     [N_ATOMS * NB];
__device__ __align__(16) __half g_nodefh[N_ATOMS * NB];
__device__ __align__(16) float  g_agg   [N_ATOMS * NB];
__device__ __align__(16) __half g_table3[N_CONV * NBINS * NB];       // base fp16 tables
__device__ __align__(16) __half g_tdup  [N_CONV * NBINS * NB * 2];   // {t[b][c], t[b+1][c]} pairs
__device__ __align__(16) float  g_efc3  [N_CONV * NB];
__device__ int   g_counts[N_ATOMS];
__device__ int   g_cursor[N_ATOMS];
__device__ int   g_rowptr[N_ATOMS + 1];
__device__ int   g_bsum[SCAN_NB];
__device__ int   g_boff[SCAN_NB];
__device__ int   g_emeta[N_EDGES];
__device__ __align__(8) int2 g_inc[2 * N_EDGES];
__device__ float g_eatom[N_ATOMS];

__device__ __forceinline__ float sspf(float x) {
    return fmaxf(x, 0.0f) + log1pf(expf(-fabsf(x))) - 0.6931471805599453f;
}

// ---------------- CSR build ----------------
__global__ void zero_counts_kernel() {
    int i = blockIdx.x * blockDim.x + threadIdx.x;
    if (i < N_ATOMS) g_counts[i] = 0;
}

__global__ void edge_prep_kernel(const int* __restrict__ a, const float* __restrict__ xyz) {
    int e = blockIdx.x * blockDim.x + threadIdx.x;
    if (e >= N_EDGES) return;
    int i = a[2 * e], j = a[2 * e + 1];
    float dx = xyz[3 * i + 0] - xyz[3 * j + 0];
    float dy = xyz[3 * i + 1] - xyz[3 * j + 1];
    float dz = xyz[3 * i + 2] - xyz[3 * j + 2];
    float d = sqrtf(dx * dx + dy * dy + dz * dz);
    int meta;
    if (d <= DMAXT) {
        float t = d * ((float)(NBINS - 1) / DMAXT);
        int bin = (int)t;
        if (bin > NBINS - 2) bin = NBINS - 2;
        float fr = t - (float)bin;
        int f16 = (int)(fr * 65535.0f + 0.5f);
        if (f16 > 65535) f16 = 65535;
        meta = (bin << 16) | f16;
    } else {
        meta = -1;
    }
    g_emeta[e] = meta;
    atomicAdd(&g_counts[i], 1);
    atomicAdd(&g_counts[j], 1);
}

__global__ void scan1_kernel() {
    __shared__ int s[SCAN_CH];
    const int b = blockIdx.x, t = threadIdx.x;
    int i = b * SCAN_CH + t;
    int v = (i < N_ATOMS) ? g_counts[i] : 0;
    s[t] = v;
    __syncthreads();
    for (int off = 1; off < SCAN_CH; off <<= 1) {
        int add = (t >= off) ? s[t - off] : 0;
        __syncthreads();
        s[t] += add;
        __syncthreads();
    }
    if (i < N_ATOMS) g_rowptr[i] = s[t] - v;
    if (t == SCAN_CH - 1) g_bsum[b] = s[t];
}

__global__ void scan2_kernel() {
    __shared__ int s[256];
    int t = threadIdx.x;
    int v = (t < SCAN_NB) ? g_bsum[t] : 0;
    s[t] = v;
    __syncthreads();
    for (int off = 1; off < 256; off <<= 1) {
        int add = (t >= off) ? s[t - off] : 0;
        __syncthreads();
        s[t] += add;
        __syncthreads();
    }
    if (t < SCAN_NB) g_boff[t] = s[t] - v;
}

__global__ void scan3_kernel() {
    int i = blockIdx.x * blockDim.x + threadIdx.x;
    if (i < N_ATOMS) {
        int v = g_rowptr[i] + g_boff[i / SCAN_CH];
        g_rowptr[i] = v;
        g_cursor[i] = v;
    }
    if (i == 0) g_rowptr[N_ATOMS] = 2 * N_EDGES;
}

__global__ void fill_kernel(const int* __restrict__ a) {
    int e = blockIdx.x * blockDim.x + threadIdx.x;
    if (e >= N_EDGES) return;
    int i = a[2 * e], j = a[2 * e + 1];
    int meta = g_emeta[e];
    int p = atomicAdd(&g_cursor[i], 1);
    g_inc[p] = make_int2(j, meta);
    p = atomicAdd(&g_cursor[j], 1);
    g_inc[p] = make_int2(i, meta);
}

// ---------------- embedding ----------------
__global__ void h_init_kernel(const int* __restrict__ r, const float* __restrict__ embed) {
    int idx = blockIdx.x * blockDim.x + threadIdx.x;
    if (idx >= N_ATOMS * NB) return;
    int row = idx >> 7, c = idx & 127;
    g_h[idx] = embed[r[row] * NB + c];
}

// ---------------- far-edge ef (exact fp32) ----------------
__global__ void efc_kernel(const float* __restrict__ be1, const float* __restrict__ We2,
                           const float* __restrict__ be2) {
    __shared__ float sxc[NG];
    const int l = blockIdx.x, t = threadIdx.x;
    if (t < NG) sxc[t] = sspf(be1[l * NG + t]);
    __syncthreads();
    float v = be2[l * NB + t];
    for (int k = 0; k < NG; k++) v = fmaf(sxc[k], We2[l * NG * NB + k * NB + t], v);
    g_efc3[l * NB + t] = v;
}

// ---------------- ef(d) tables (fp16), all layers ----------------
__global__ void table_kernel(const float* __restrict__ We1, const float* __restrict__ be1,
                             const float* __restrict__ We2, const float* __restrict__ be2) {
    __shared__ float gg[NG];
    __shared__ float sx[NG];
    const int b = blockIdx.x, t = threadIdx.x;
    const float width = 5.0f / 49.0f;
    const float coeff = -0.5f / (width * width);
    float d = (float)b * (DMAXT / (float)(NBINS - 1));
    if (t < NG) {
        float df = d - (float)t * width;
        gg[t] = expf(coeff * df * df);
    }
    __syncthreads();
    for (int l = 0; l < N_CONV; l++) {
        if (t < NG) {
            float x = be1[l * NG + t];
            const float* W1l = We1 + l * NG * NG;
            #pragma unroll 10
            for (int m = 0; m < NG; m++) x = fmaf(gg[m], W1l[m * NG + t], x);
            sx[t] = sspf(x);
        }
        __syncthreads();
        float ef = be2[l * NB + t];
        const float* W2l = We2 + l * NG * NB;
        #pragma unroll 10
        for (int k = 0; k < NG; k++) ef = fmaf(sx[k], W2l[k * NB + t], ef);
        g_table3[(l * NBINS + b) * NB + t] = __float2half_rn(ef);
        __syncthreads();
    }
}

// duplicated-endpoint layout: tdup[row][c] = { t[row][c], t[row+1][c] }
__global__ void tdup_kernel() {
    int idx = blockIdx.x * blockDim.x + threadIdx.x;   // over N_CONV*NBINS*NB
    if (idx >= N_CONV * NBINS * NB) return;
    int c = idx & 127;
    int row = idx >> 7;                 // l*NBINS + b
    int b = row % NBINS;
    int rown = (b < NBINS - 1) ? row + 1 : row;
    g_tdup[idx * 2 + 0] = g_table3[idx];
    g_tdup[idx * 2 + 1] = g_table3[rown * NB + c];
}

// ---------------- BIG GEMM (96KB dyn smem): nodef(fp16) = h @ Wn + bn ----------------
__global__ void __launch_bounds__(256) gemm_nodef_big(const float* __restrict__ W,
                                                      const float* __restrict__ bias) {
    extern __shared__ float sm[];
    float* Ws = sm;            // [128][128] 64 KB
    float* At = sm + NB * NB;  // [64][128]  32 KB
    const int tid  = threadIdx.x;
    const int row0 = blockIdx.x * 64;
    const int cg   = tid & 31;        // col group: cols 4*cg..
    const int r0   = (tid >> 5) * 8;  // rows r0..r0+7
    const int c0   = cg * 4;

    {
        const float4* Wv = (const float4*)W;
        float4* Wsv = (float4*)Ws;
        for (int idx = tid; idx < NB * NB / 4; idx += 256) Wsv[idx] = Wv[idx];
        const int nrem = N_ATOMS - row0;
        for (int idx = tid; idx < 64 * (NB / 4); idx += 256) {
            int r = idx >> 5, k4 = idx & 31;
            float4 v = make_float4(0.f, 0.f, 0.f, 0.f);
            if (r < nrem) v = *(const float4*)&g_h[(row0 + r) * NB + k4 * 4];
            *(float4*)&At[r * NB + k4 * 4] = v;
        }
    }
    __syncthreads();

    float acc[8][4];
    #pragma unroll
    for (int rr = 0; rr < 8; rr++)
        #pragma unroll
        for (int c = 0; c < 4; c++) acc[rr][c] = 0.0f;

    #pragma unroll 2
    for (int k0 = 0; k0 < NB; k0 += 4) {
        float4 w0 = *(const float4*)&Ws[(k0 + 0) * NB + c0];
        float4 w1 = *(const float4*)&Ws[(k0 + 1) * NB + c0];
        float4 w2 = *(const float4*)&Ws[(k0 + 2) * NB + c0];
        float4 w3 = *(const float4*)&Ws[(k0 + 3) * NB + c0];
        #pragma unroll
        for (int rr = 0; rr < 8; rr++) {
            const float4 av = *(const float4*)&At[(r0 + rr) * NB + k0];
            acc[rr][0] = fmaf(av.x, w0.x, acc[rr][0]);
            acc[rr][1] = fmaf(av.x, w0.y, acc[rr][1]);
            acc[rr][2] = fmaf(av.x, w0.z, acc[rr][2]);
            acc[rr][3] = fmaf(av.x, w0.w, acc[rr][3]);
            acc[rr][0] = fmaf(av.y, w1.x, acc[rr][0]);
            acc[rr][1] = fmaf(av.y, w1.y, acc[rr][1]);
            acc[rr][2] = fmaf(av.y, w1.z, acc[rr][2]);
            acc[rr][3] = fmaf(av.y, w1.w, acc[rr][3]);
            acc[rr][0] = fmaf(av.z, w2.x, acc[rr][0]);
            acc[rr][1] = fmaf(av.z, w2.y, acc[rr][1]);
            acc[rr][2] = fmaf(av.z, w2.z, acc[rr][2]);
            acc[rr][3] = fmaf(av.z, w2.w, acc[rr][3]);
            acc[rr][0] = fmaf(av.w, w3.x, acc[rr][0]);
            acc[rr][1] = fmaf(av.w, w3.y, acc[rr][1]);
            acc[rr][2] = fmaf(av.w, w3.z, acc[rr][2]);
            acc[rr][3] = fmaf(av.w, w3.w, acc[rr][3]);
        }
    }

    const float4 bv = *(const float4*)&bias[c0];
    #pragma unroll
    for (int rr = 0; rr < 8; rr++) {
        int r = row0 + r0 + rr;
        if (r >= N_ATOMS) break;
        __half2 lo = __floats2half2_rn(acc[rr][0] + bv.x, acc[rr][1] + bv.y);
        __half2 hi = __floats2half2_rn(acc[rr][2] + bv.z, acc[rr][3] + bv.w);
        uint2 pk; pk.x = *(unsigned*)&lo; pk.y = *(unsigned*)&hi;
        *(uint2*)&g_nodefh[r * NB + c0] = pk;
    }
}

// ---------------- BIG fused update: h += ssp(agg @ Wu1 + bu1) @ Wu2 + bu2 ----------------
__global__ void __launch_bounds__(256) gemm_update_big(const float* __restrict__ Wu1,
                                                       const float* __restrict__ bu1,
                                                       const float* __restrict__ Wu2,
                                                       const float* __restrict__ bu2) {
    extern __shared__ float sm[];
    float* Ws = sm;
    float* At = sm + NB * NB;
    const int tid  = threadIdx.x;
    const int row0 = blockIdx.x * 64;
    const int cg   = tid & 31;
    const int r0   = (tid >> 5) * 8;
    const int c0   = cg * 4;
    const int nrem = N_ATOMS - row0;

    {
        const float4* Wv = (const float4*)Wu1;
        float4* Wsv = (float4*)Ws;
        for (int idx = tid; idx < NB * NB / 4; idx += 256) Wsv[idx] = Wv[idx];
        for (int idx = tid; idx < 64 * (NB / 4); idx += 256) {
            int r = idx >> 5, k4 = idx & 31;
            float4 v = make_float4(0.f, 0.f, 0.f, 0.f);
            if (r < nrem) v = *(const float4*)&g_agg[(row0 + r) * NB + k4 * 4];
            *(float4*)&At[r * NB + k4 * 4] = v;
        }
    }
    __syncthreads();

    float acc[8][4];
    #pragma unroll
    for (int rr = 0; rr < 8; rr++)
        #pragma unroll
        for (int c = 0; c < 4; c++) acc[rr][c] = 0.0f;

    #pragma unroll 2
    for (int k0 = 0; k0 < NB; k0 += 4) {
        float4 w0 = *(const float4*)&Ws[(k0 + 0) * NB + c0];
        float4 w1 = *(const float4*)&Ws[(k0 + 1) * NB + c0];
        float4 w2 = *(const float4*)&Ws[(k0 + 2) * NB + c0];
        float4 w3 = *(const float4*)&Ws[(k0 + 3) * NB + c0];
        #pragma unroll
        for (int rr = 0; rr < 8; rr++) {
            const float4 av = *(const float4*)&At[(r0 + rr) * NB + k0];
            acc[rr][0] = fmaf(av.x, w0.x, acc[rr][0]);
            acc[rr][1] = fmaf(av.x, w0.y, acc[rr][1]);
            acc[rr][2] = fmaf(av.x, w0.z, acc[rr][2]);
            acc[rr][3] = fmaf(av.x, w0.w, acc[rr][3]);
            acc[rr][0] = fmaf(av.y, w1.x, acc[rr][0]);
            acc[rr][1] = fmaf(av.y, w1.y, acc[rr][1]);
            acc[rr][2] = fmaf(av.y, w1.z, acc[rr][2]);
            acc[rr][3] = fmaf(av.y, w1.w, acc[rr][3]);
            acc[rr][0] = fmaf(av.z, w2.x, acc[rr][0]);
            acc[rr][1] = fmaf(av.z, w2.y, acc[rr][1]);
            acc[rr][2] = fmaf(av.z, w2.z, acc[rr][2]);
            acc[rr][3] = fmaf(av.z, w2.w, acc[rr][3]);
            acc[rr][0] = fmaf(av.w, w3.x, acc[rr][0]);
            acc[rr][1] = fmaf(av.w, w3.y, acc[rr][1]);
            acc[rr][2] = fmaf(av.w, w3.z, acc[rr][2]);
            acc[rr][3] = fmaf(av.w, w3.w, acc[rr][3]);
        }
    }

    // t1 = ssp(acc + bu1) back into At
    {
        const float4 bv = *(const float4*)&bu1[c0];
        __syncthreads();
        #pragma unroll
        for (int rr = 0; rr < 8; rr++) {
            float4 o = make_float4(sspf(acc[rr][0] + bv.x), sspf(acc[rr][1] + bv.y),
                                   sspf(acc[rr][2] + bv.z), sspf(acc[rr][3] + bv.w));
            *(float4*)&At[(r0 + rr) * NB + c0] = o;
        }
    }
    // load Wu2
    __syncthreads();
    {
        const float4* Wv = (const float4*)Wu2;
        float4* Wsv = (float4*)Ws;
        for (int idx = tid; idx < NB * NB / 4; idx += 256) Wsv[idx] = Wv[idx];
    }
    __syncthreads();

    #pragma unroll
    for (int rr = 0; rr < 8; rr++)
        #pragma unroll
        for (int c = 0; c < 4; c++) acc[rr][c] = 0.0f;

    #pragma unroll 2
    for (int k0 = 0; k0 < NB; k0 += 4) {
        float4 w0 = *(const float4*)&Ws[(k0 + 0) * NB + c0];
        float4 w1 = *(const float4*)&Ws[(k0 + 1) * NB + c0];
        float4 w2 = *(const float4*)&Ws[(k0 + 2) * NB + c0];
        float4 w3 = *(const float4*)&Ws[(k0 + 3) * NB + c0];
        #pragma unroll
        for (int rr = 0; rr < 8; rr++) {
            const float4 av = *(const float4*)&At[(r0 + rr) * NB + k0];
            acc[rr][0] = fmaf(av.x, w0.x, acc[rr][0]);
            acc[rr][1] = fmaf(av.x, w0.y, acc[rr][1]);
            acc[rr][2] = fmaf(av.x, w0.z, acc[rr][2]);
            acc[rr][3] = fmaf(av.x, w0.w, acc[rr][3]);
            acc[rr][0] = fmaf(av.y, w1.x, acc[rr][0]);
            acc[rr][1] = fmaf(av.y, w1.y, acc[rr][1]);
            acc[rr][2] = fmaf(av.y, w1.z, acc[rr][2]);
            acc[rr][3] = fmaf(av.y, w1.w, acc[rr][3]);
            acc[rr][0] = fmaf(av.z, w2.x, acc[rr][0]);
            acc[rr][1] = fmaf(av.z, w2.y, acc[rr][1]);
            acc[rr][2] = fmaf(av.z, w2.z, acc[rr][2]);
            acc[rr][3] = fmaf(av.z, w2.w, acc[rr][3]);
            acc[rr][0] = fmaf(av.w, w3.x, acc[rr][0]);
            acc[rr][1] = fmaf(av.w, w3.y, acc[rr][1]);
            acc[rr][2] = fmaf(av.w, w3.z, acc[rr][2]);
            acc[rr][3] = fmaf(av.w, w3.w, acc[rr][3]);
        }
    }

    const float4 bv = *(const float4*)&bu2[c0];
    #pragma unroll
    for (int rr = 0; rr < 8; rr++) {
        int r = row0 + r0 + rr;
        if (r >= N_ATOMS) break;
        float4* p = (float4*)&g_h[r * NB + c0];
        float4 hv = *p;
        hv.x += acc[rr][0] + bv.x;
        hv.y += acc[rr][1] + bv.y;
        hv.z += acc[rr][2] + bv.z;
        hv.w += acc[rr][3] + bv.w;
        *p = hv;
    }
}

// ---------------- fallback 48KB GEMMs (identical to round 13) ----------------
__global__ void __launch_bounds__(256) gemm_nodef_kernel(const float* __restrict__ W,
                                                         const float* __restrict__ bias) {
    __shared__ __align__(16) float At[64 * NB];
    __shared__ float Wp[NB * 32];
    const int tid  = threadIdx.x;
    const int row0 = blockIdx.x * 64;
    const int lane = tid & 31;
    const int r0   = (tid >> 5) * 8;
    {
        const int nrem = N_ATOMS - row0;
        for (int idx = tid; idx < 64 * (NB / 4); idx += 256) {
            int r = idx >> 5, k4 = idx & 31;
            float4 v = make_float4(0.f, 0.f, 0.f, 0.f);
            if (r < nrem) v = *(const float4*)&g_h[(row0 + r) * NB + k4 * 4];
            *(float4*)&At[r * NB + k4 * 4] = v;
        }
    }
    #pragma unroll
    for (int pass = 0; pass < 4; pass++) {
        const int cbase = pass * 32;
        __syncthreads();
        for (int idx = tid; idx < NB * 32; idx += 256) {
            int k = idx >> 5, c = idx & 31;
            Wp[k * 32 + c] = W[k * NB + cbase + c];
        }
        __syncthreads();
        float acc[8];
        #pragma unroll
        for (int rr = 0; rr < 8; rr++) acc[rr] = 0.0f;
        #pragma unroll 2
        for (int k0 = 0; k0 < NB; k0 += 4) {
            float w0 = Wp[(k0 + 0) * 32 + lane];
            float w1 = Wp[(k0 + 1) * 32 + lane];
            float w2 = Wp[(k0 + 2) * 32 + lane];
            float w3 = Wp[(k0 + 3) * 32 + lane];
            #pragma unroll
            for (int rr = 0; rr < 8; rr++) {
                const float4 av = *(const float4*)&At[(r0 + rr) * NB + k0];
                acc[rr] = fmaf(av.x, w0, acc[rr]);
                acc[rr] = fmaf(av.y, w1, acc[rr]);
                acc[rr] = fmaf(av.z, w2, acc[rr]);
                acc[rr] = fmaf(av.w, w3, acc[rr]);
            }
        }
        const float bv = bias[cbase + lane];
        #pragma unroll
        for (int rr = 0; rr < 8; rr++) {
            int r = row0 + r0 + rr;
            if (r >= N_ATOMS) break;
            g_nodefh[r * NB + cbase + lane] = __float2half_rn(acc[rr] + bv);
        }
    }
}

__global__ void __launch_bounds__(256) gemm_update_kernel(const float* __restrict__ Wu1,
                                                          const float* __restrict__ bu1,
                                                          const float* __restrict__ Wu2,
                                                          const float* __restrict__ bu2) {
    __shared__ __align__(16) float At[64 * NB];
    __shared__ float Wp[NB * 32];
    const int tid  = threadIdx.x;
    const int row0 = blockIdx.x * 64;
    const int lane = tid & 31;
    const int r0   = (tid >> 5) * 8;
    const int nrem = N_ATOMS - row0;

    for (int idx = tid; idx < 64 * (NB / 4); idx += 256) {
        int r = idx >> 5, k4 = idx & 31;
        float4 v = make_float4(0.f, 0.f, 0.f, 0.f);
        if (r < nrem) v = *(const float4*)&g_agg[(row0 + r) * NB + k4 * 4];
        *(float4*)&At[r * NB + k4 * 4] = v;
    }
    float t1r[4][8];
    #pragma unroll
    for (int pass = 0; pass < 4; pass++) {
        const int cbase = pass * 32;
        __syncthreads();
        for (int idx = tid; idx < NB * 32; idx += 256) {
            int k = idx >> 5, c = idx & 31;
            Wp[k * 32 + c] = Wu1[k * NB + cbase + c];
        }
        __syncthreads();
        float acc[8];
        #pragma unroll
        for (int rr = 0; rr < 8; rr++) acc[rr] = 0.0f;
        #pragma unroll 2
        for (int k0 = 0; k0 < NB; k0 += 4) {
            float w0 = Wp[(k0 + 0) * 32 + lane];
            float w1 = Wp[(k0 + 1) * 32 + lane];
            float w2 = Wp[(k0 + 2) * 32 + lane];
            float w3 = Wp[(k0 + 3) * 32 + lane];
            #pragma unroll
            for (int rr = 0; rr < 8; rr++) {
                const float4 av = *(const float4*)&At[(r0 + rr) * NB + k0];
                acc[rr] = fmaf(av.x, w0, acc[rr]);
                acc[rr] = fmaf(av.y, w1, acc[rr]);
                acc[rr] = fmaf(av.z, w2, acc[rr]);
                acc[rr] = fmaf(av.w, w3, acc[rr]);
            }
        }
        const float bv = bu1[cbase + lane];
        #pragma unroll
        for (int rr = 0; rr < 8; rr++) t1r[pass][rr] = sspf(acc[rr] + bv);
    }
    __syncthreads();
    #pragma unroll
    for (int pass = 0; pass < 4; pass++)
        #pragma unroll
        for (int rr = 0; rr < 8; rr++)
            At[(r0 + rr) * NB + pass * 32 + lane] = t1r[pass][rr];
    #pragma unroll
    for (int pass = 0; pass < 4; pass++) {
        const int cbase = pass * 32;
        __syncthreads();
        for (int idx = tid; idx < NB * 32; idx += 256) {
            int k = idx >> 5, c = idx & 31;
            Wp[k * 32 + c] = Wu2[k * NB + cbase + c];
        }
        __syncthreads();
        float acc[8];
        #pragma unroll
        for (int rr = 0; rr < 8; rr++) acc[rr] = 0.0f;
        #pragma unroll 2
        for (int k0 = 0; k0 < NB; k0 += 4) {
            float w0 = Wp[(k0 + 0) * 32 + lane];
            float w1 = Wp[(k0 + 1) * 32 + lane];
            float w2 = Wp[(k0 + 2) * 32 + lane];
            float w3 = Wp[(k0 + 3) * 32 + lane];
            #pragma unroll
            for (int rr = 0; rr < 8; rr++) {
                const float4 av = *(const float4*)&At[(r0 + rr) * NB + k0];
                acc[rr] = fmaf(av.x, w0, acc[rr]);
                acc[rr] = fmaf(av.y, w1, acc[rr]);
                acc[rr] = fmaf(av.z, w2, acc[rr]);
                acc[rr] = fmaf(av.w, w3, acc[rr]);
            }
        }
        const float bv = bu2[cbase + lane];
        #pragma unroll
        for (int rr = 0; rr < 8; rr++) {
            int r = row0 + r0 + rr;
            if (r >= N_ATOMS) break;
            g_h[r * NB + cbase + lane] += acc[rr] + bv;
        }
    }
}

// ---------------- aggregation: warp per node, dup-table lerp, 2-way unroll ----------------
__device__ __forceinline__ void gather_one(int2 cur, int lane, const __half* tdup,
                                           float4& av, float4& ac) {
    const int other = cur.x, meta = cur.y;
    const uint2 nfu = *(const uint2*)&g_nodefh[other * NB + 4 * lane];
    const float2 nf01 = __half22float2(*(const __half2*)&nfu.x);
    const float2 nf23 = __half22float2(*(const __half2*)&nfu.y);
    if (meta < 0) {
        ac.x += nf01.x; ac.y += nf01.y; ac.z += nf23.x; ac.w += nf23.y;
    } else {
        const int bin = meta >> 16;
        const float fr = (float)(meta & 0xffff) * (1.0f / 65535.0f);
        const uint4 tu = *(const uint4*)&tdup[(bin * NB + 4 * lane) * 2];
        const float2 p0 = __half22float2(*(const __half2*)&tu.x);   // {t0,t1} ch c0
        const float2 p1 = __half22float2(*(const __half2*)&tu.y);
        const float2 p2 = __half22float2(*(const __half2*)&tu.z);
        const float2 p3 = __half22float2(*(const __half2*)&tu.w);
        av.x = fmaf(nf01.x, fmaf(fr, p0.y - p0.x, p0.x), av.x);
        av.y = fmaf(nf01.y, fmaf(fr, p1.y - p1.x, p1.x), av.y);
        av.z = fmaf(nf23.x, fmaf(fr, p2.y - p2.x, p2.x), av.z);
        av.w = fmaf(nf23.y, fmaf(fr, p3.y - p3.x, p3.x), av.w);
    }
}

__global__ void __launch_bounds__(256) gather_kernel(int l) {
    int gtid = blockIdx.x * blockDim.x + threadIdx.x;
    int node = gtid >> 5;
    if (node >= N_ATOMS) return;
    int lane = threadIdx.x & 31;
    const __half* tdup = g_tdup + l * (NBINS * NB * 2);
    const int s = g_rowptr[node];
    const int e = g_rowptr[node + 1];
    const float4 efc = *(const float4*)&g_efc3[l * NB + 4 * lane];
    float4 av0 = make_float4(0.f, 0.f, 0.f, 0.f);
    float4 av1 = make_float4(0.f, 0.f, 0.f, 0.f);
    float4 ac0 = make_float4(0.f, 0.f, 0.f, 0.f);
    float4 ac1 = make_float4(0.f, 0.f, 0.f, 0.f);

    int p = s;
    for (; p + 1 < e; p += 2) {
        int2 c0 = g_inc[p];
        int2 c1 = g_inc[p + 1];
        gather_one(c0, lane, tdup, av0, ac0);
        gather_one(c1, lane, tdup, av1, ac1);
    }
    if (p < e) gather_one(g_inc[p], lane, tdup, av0, ac0);

    av0.x += av1.x; av0.y += av1.y; av0.z += av1.z; av0.w += av1.w;
    ac0.x += ac1.x; ac0.y += ac1.y; ac0.z += ac1.z; ac0.w += ac1.w;
    av0.x = fmaf(ac0.x, efc.x, av0.x);
    av0.y = fmaf(ac0.y, efc.y, av0.y);
    av0.z = fmaf(ac0.z, efc.z, av0.z);
    av0.w = fmaf(ac0.w, efc.w, av0.w);
    *(float4*)&g_agg[node * NB + 4 * lane] = av0;
}

// ---------------- final head ----------------
#define EAT_APW 16
__global__ void __launch_bounds__(256) eatom_kernel(const float* __restrict__ W1,
                                                    const float* __restrict__ b1,
                                                    const float* __restrict__ W2,
                                                    const float* __restrict__ b2) {
    __shared__ float w1s[NB * 64];
    __shared__ float w2s[64];
    __shared__ float b1s[64];
    __shared__ __align__(16) float rowbuf[8][NB];
    const int tid = threadIdx.x;
    for (int idx = tid; idx < NB * 64; idx += 256) w1s[idx] = W1[idx];
    if (tid < 64) { w2s[tid] = W2[tid]; b1s[tid] = b1[tid]; }
    __syncthreads();

    const int wid = tid >> 5, lane = tid & 31;
    const float b2v = b2[0];
    for (int it = 0; it < EAT_APW; it++) {
        int atom = (blockIdx.x * 8 + wid) * EAT_APW + it;
        if (atom >= N_ATOMS) break;
        *(float4*)&rowbuf[wid][lane * 4] = *(const float4*)&g_h[atom * NB + lane * 4];
        __syncwarp();
        float acc0 = b1s[lane], acc1 = b1s[lane + 32];
        #pragma unroll 4
        for (int k = 0; k < NB; k++) {
            float hv = rowbuf[wid][k];
            acc0 = fmaf(hv, w1s[k * 64 + lane], acc0);
            acc1 = fmaf(hv, w1s[k * 64 + 32 + lane], acc1);
        }
        float e = sspf(acc0) * w2s[lane] + sspf(acc1) * w2s[lane + 32];
        #pragma unroll
        for (int off = 16; off > 0; off >>= 1) e += __shfl_xor_sync(0xffffffffu, e, off);
        if (lane == 0) g_eatom[atom] = e + b2v;
        __syncwarp();
    }
}

__global__ void molred_kernel(float* __restrict__ out, int nmol) {
    __shared__ float s[256];
    const int m = blockIdx.x, tid = threadIdx.x;
    if (m >= nmol) return;
    float v = 0.0f;
    for (int i = tid; i < MOLSZ; i += 256) v += g_eatom[m * MOLSZ + i];
    s[tid] = v;
    __syncthreads();
    for (int off = 128; off > 0; off >>= 1) {
        if (tid < off) s[tid] += s[tid + off];
        __syncthreads();
    }
    if (tid == 0) out[m] = s[0];
}

// ---------------- launch ----------------
extern "C" void kernel_launch(void* const* d_in, const int* in_sizes, int n_in,
                              void* d_out, int out_size) {
    const int*   r     = (const int*)  d_in[0];
    const float* xyz   = (const float*)d_in[1];
    const int*   a     = (const int*)  d_in[2];

    int base = 3;
    if (in_sizes[3] == 1 || (n_in > 4 && in_sizes[4] == 12800)) base = 4;

    const float* embed = (const float*)d_in[base + 0];
    const float* Wn    = (const float*)d_in[base + 1];
    const float* bn    = (const float*)d_in[base + 2];
    const float* We1   = (const float*)d_in[base + 3];
    const float* be1   = (const float*)d_in[base + 4];
    const float* We2   = (const float*)d_in[base + 5];
    const float* be2   = (const float*)d_in[base + 6];
    const float* Wu1   = (const float*)d_in[base + 7];
    const float* bu1   = (const float*)d_in[base + 8];
    const float* Wu2   = (const float*)d_in[base + 9];
    const float* bu2   = (const float*)d_in[base + 10];
    const float* W1    = (const float*)d_in[base + 11];
    const float* b1    = (const float*)d_in[base + 12];
    const float* W2    = (const float*)d_in[base + 13];
    const float* b2    = (const float*)d_in[base + 14];
    float* out = (float*)d_out;
    const int nmol = out_size;

    // Opt into 96KB dynamic smem; deterministic fallback to 48KB path on failure.
    bool big_ok = true;
    if (cudaFuncSetAttribute(gemm_nodef_big,
            cudaFuncAttributeMaxDynamicSharedMemorySize, SMEM_BIG) != cudaSuccess) big_ok = false;
    if (cudaFuncSetAttribute(gemm_update_big,
            cudaFuncAttributeMaxDynamicSharedMemorySize, SMEM_BIG) != cudaSuccess) big_ok = false;

    const int EB  = (N_EDGES + 255) / 256;
    const int GB  = (N_ATOMS + 63) / 64;
    const int ZB  = (N_ATOMS * NB + 255) / 256;
    const int AB  = (N_ATOMS * 32 + 255) / 256;
    const int NBK = (N_ATOMS + 255) / 256;
    const int TDB = (N_CONV * NBINS * NB + 255) / 256;
    const int EATB = (N_ATOMS + 8 * EAT_APW - 1) / (8 * EAT_APW);

    zero_counts_kernel<<<NBK, 256>>>();
    edge_prep_kernel<<<EB, 256>>>(a, xyz);
    scan1_kernel<<<SCAN_NB, SCAN_CH>>>();
    scan2_kernel<<<1, 256>>>();
    scan3_kernel<<<NBK, 256>>>();
    fill_kernel<<<EB, 256>>>(a);
    h_init_kernel<<<ZB, 256>>>(r, embed);
    efc_kernel<<<N_CONV, NB>>>(be1, We2, be2);
    table_kernel<<<NBINS, NB>>>(We1, be1, We2, be2);
    tdup_kernel<<<TDB, 256>>>();

    for (int l = 0; l < N_CONV; l++) {
        if (big_ok) gemm_nodef_big<<<GB, 256, SMEM_BIG>>>(Wn + l * NB * NB, bn + l * NB);
        else        gemm_nodef_kernel<<<GB, 256>>>(Wn + l * NB * NB, bn + l * NB);
        gather_kernel<<<AB, 256>>>(l);
        if (big_ok) gemm_update_big<<<GB, 256, SMEM_BIG>>>(Wu1 + l * NB * NB, bu1 + l * NB,
                                                           Wu2 + l * NB * NB, bu2 + l * NB);
        else        gemm_update_kernel<<<GB, 256>>>(Wu1 + l * NB * NB, bu1 + l * NB,
                                                    Wu2 + l * NB * NB, bu2 + l * NB);
    }

    eatom_kernel<<<EATB, 256>>>(W1, b1, W2, b2);
    molred_kernel<<<nmol, 256>>>(out, nmol);
}

// round 15
// speedup vs baseline: 3.6901x; 1.0923x over previous
#include <cuda_runtime.h>
#include <cuda_fp16.h>
#include <math.h>

#define N_ATOMS   50000
#define N_EDGES   500000
#define NB        128
#define NG        50
#define N_CONV    3
#define MOLSZ     1000
#define NBINS     6144
#define DMAXT     6.0f
#define SCAN_CH   256
#define SCAN_NB   ((N_ATOMS + SCAN_CH - 1) / SCAN_CH)
#define SMEM_BIG  ((NB * NB + 64 * NB) * 4)   // 96 KB

// ---------------- device scratch (referenced ONLY inside device code!) ----------------
__device__ __align__(16) float  g_h     [N_ATOMS * NB];
__device__ __align__(16) __half g_nodefh[N_ATOMS * NB];
__device__ __align__(16) float  g_agg   [N_ATOMS * NB];
__device__ __align__(16) __half g_tdup  [N_CONV * NBINS * NB * 2];   // {t[b][c], t[b+1][c]}
__device__ __align__(16) float  g_efc3  [N_CONV * NB];
__device__ int   g_counts[N_ATOMS];
__device__ int   g_cursor[N_ATOMS];
__device__ int   g_rowptr[N_ATOMS + 1];
__device__ int   g_bsum[SCAN_NB];
__device__ int   g_boff[SCAN_NB];
__device__ int   g_emeta[N_EDGES];
__device__ __align__(8) int2 g_inc[2 * N_EDGES];
__device__ float g_eatom[N_ATOMS];

__device__ __forceinline__ float sspf(float x) {
    return fmaxf(x, 0.0f) + log1pf(expf(-fabsf(x))) - 0.6931471805599453f;
}

// packed 2xfp32 fma: d = a*b + d  (FFMA2 — only reachable via PTX f32x2)
__device__ __forceinline__ void ffma2(float2& d, const float2 a, const float2 b) {
    asm("fma.rn.f32x2 %0, %1, %2, %0;"
        : "+l"(*reinterpret_cast<unsigned long long*>(&d))
        : "l"(*reinterpret_cast<const unsigned long long*>(&a)),
          "l"(*reinterpret_cast<const unsigned long long*>(&b)));
}

// ---------------- CSR build ----------------
__global__ void zero_counts_kernel() {
    int i = blockIdx.x * blockDim.x + threadIdx.x;
    if (i < N_ATOMS) g_counts[i] = 0;
}

__global__ void edge_prep_kernel(const int* __restrict__ a, const float* __restrict__ xyz) {
    int e = blockIdx.x * blockDim.x + threadIdx.x;
    if (e >= N_EDGES) return;
    int i = a[2 * e], j = a[2 * e + 1];
    float dx = xyz[3 * i + 0] - xyz[3 * j + 0];
    float dy = xyz[3 * i + 1] - xyz[3 * j + 1];
    float dz = xyz[3 * i + 2] - xyz[3 * j + 2];
    float d = sqrtf(dx * dx + dy * dy + dz * dz);
    int meta;
    if (d <= DMAXT) {
        float t = d * ((float)(NBINS - 1) / DMAXT);
        int bin = (int)t;
        if (bin > NBINS - 2) bin = NBINS - 2;
        float fr = t - (float)bin;
        int f16 = (int)(fr * 65535.0f + 0.5f);
        if (f16 > 65535) f16 = 65535;
        meta = (bin << 16) | f16;
    } else {
        meta = -1;
    }
    g_emeta[e] = meta;
    atomicAdd(&g_counts[i], 1);
    atomicAdd(&g_counts[j], 1);
}

__global__ void scan1_kernel() {
    __shared__ int s[SCAN_CH];
    const int b = blockIdx.x, t = threadIdx.x;
    int i = b * SCAN_CH + t;
    int v = (i < N_ATOMS) ? g_counts[i] : 0;
    s[t] = v;
    __syncthreads();
    for (int off = 1; off < SCAN_CH; off <<= 1) {
        int add = (t >= off) ? s[t - off] : 0;
        __syncthreads();
        s[t] += add;
        __syncthreads();
    }
    if (i < N_ATOMS) g_rowptr[i] = s[t] - v;
    if (t == SCAN_CH - 1) g_bsum[b] = s[t];
}

__global__ void scan2_kernel() {
    __shared__ int s[256];
    int t = threadIdx.x;
    int v = (t < SCAN_NB) ? g_bsum[t] : 0;
    s[t] = v;
    __syncthreads();
    for (int off = 1; off < 256; off <<= 1) {
        int add = (t >= off) ? s[t - off] : 0;
        __syncthreads();
        s[t] += add;
        __syncthreads();
    }
    if (t < SCAN_NB) g_boff[t] = s[t] - v;
}

__global__ void scan3_kernel() {
    int i = blockIdx.x * blockDim.x + threadIdx.x;
    if (i < N_ATOMS) {
        int v = g_rowptr[i] + g_boff[i / SCAN_CH];
        g_rowptr[i] = v;
        g_cursor[i] = v;
    }
    if (i == 0) g_rowptr[N_ATOMS] = 2 * N_EDGES;
}

__global__ void fill_kernel(const int* __restrict__ a) {
    int e = blockIdx.x * blockDim.x + threadIdx.x;
    if (e >= N_EDGES) return;
    int i = a[2 * e], j = a[2 * e + 1];
    int meta = g_emeta[e];
    int p = atomicAdd(&g_cursor[i], 1);
    g_inc[p] = make_int2(j, meta);
    p = atomicAdd(&g_cursor[j], 1);
    g_inc[p] = make_int2(i, meta);
}

// ---------------- embedding ----------------
__global__ void h_init_kernel(const int* __restrict__ r, const float* __restrict__ embed) {
    int idx = blockIdx.x * blockDim.x + threadIdx.x;
    if (idx >= N_ATOMS * NB) return;
    int row = idx >> 7, c = idx & 127;
    g_h[idx] = embed[r[row] * NB + c];
}

// ---------------- far-edge ef (exact fp32) ----------------
__global__ void efc_kernel(const float* __restrict__ be1, const float* __restrict__ We2,
                           const float* __restrict__ be2) {
    __shared__ float sxc[NG];
    const int l = blockIdx.x, t = threadIdx.x;
    if (t < NG) sxc[t] = sspf(be1[l * NG + t]);
    __syncthreads();
    float v = be2[l * NB + t];
    for (int k = 0; k < NG; k++) v = fmaf(sxc[k], We2[l * NG * NB + k * NB + t], v);
    g_efc3[l * NB + t] = v;
}

// ---------------- ef(d) tables, dup layout written directly ----------------
__global__ void table_kernel(const float* __restrict__ We1, const float* __restrict__ be1,
                             const float* __restrict__ We2, const float* __restrict__ be2) {
    __shared__ float gg[NG];
    __shared__ float sx[NG];
    const int b = blockIdx.x, t = threadIdx.x;
    const float width = 5.0f / 49.0f;
    const float coeff = -0.5f / (width * width);
    float d = (float)b * (DMAXT / (float)(NBINS - 1));
    if (t < NG) {
        float df = d - (float)t * width;
        gg[t] = expf(coeff * df * df);
    }
    __syncthreads();
    for (int l = 0; l < N_CONV; l++) {
        if (t < NG) {
            float x = be1[l * NG + t];
            const float* W1l = We1 + l * NG * NG;
            #pragma unroll 10
            for (int m = 0; m < NG; m++) x = fmaf(gg[m], W1l[m * NG + t], x);
            sx[t] = sspf(x);
        }
        __syncthreads();
        float ef = be2[l * NB + t];
        const float* W2l = We2 + l * NG * NB;
        #pragma unroll 10
        for (int k = 0; k < NG; k++) ef = fmaf(sx[k], W2l[k * NB + t], ef);
        __half h = __float2half_rn(ef);
        const int rowbase = (l * NBINS + b) * NB;
        g_tdup[(rowbase + t) * 2 + 0] = h;                         // lo of own row
        if (b > 0)           g_tdup[(rowbase - NB + t) * 2 + 1] = h;  // hi of row b-1
        if (b == NBINS - 1)  g_tdup[(rowbase + t) * 2 + 1] = h;       // clamp tail
        __syncthreads();
    }
}

// ---------------- BIG GEMM (96KB, f32x2): nodef(fp16) = h @ Wn + bn ----------------
__global__ void __launch_bounds__(256) gemm_nodef_big(const float* __restrict__ W,
                                                      const float* __restrict__ bias) {
    extern __shared__ float sm[];
    float* Ws = sm;            // [128][128] 64 KB
    float* At = sm + NB * NB;  // [64][128]  32 KB
    const int tid  = threadIdx.x;
    const int row0 = blockIdx.x * 64;
    const int r0   = (tid >> 5) * 8;
    const int c0   = (tid & 31) * 4;

    {
        const float4* Wv = (const float4*)W;
        float4* Wsv = (float4*)Ws;
        for (int idx = tid; idx < NB * NB / 4; idx += 256) Wsv[idx] = Wv[idx];
        const int nrem = N_ATOMS - row0;
        for (int idx = tid; idx < 64 * (NB / 4); idx += 256) {
            int r = idx >> 5, k4 = idx & 31;
            float4 v = make_float4(0.f, 0.f, 0.f, 0.f);
            if (r < nrem) v = *(const float4*)&g_h[(row0 + r) * NB + k4 * 4];
            *(float4*)&At[r * NB + k4 * 4] = v;
        }
    }
    __syncthreads();

    float2 acc[8][2];
    #pragma unroll
    for (int rr = 0; rr < 8; rr++) { acc[rr][0] = make_float2(0.f, 0.f); acc[rr][1] = make_float2(0.f, 0.f); }

    #pragma unroll 2
    for (int k0 = 0; k0 < NB; k0 += 4) {
        float4 w0 = *(const float4*)&Ws[(k0 + 0) * NB + c0];
        float4 w1 = *(const float4*)&Ws[(k0 + 1) * NB + c0];
        float4 w2 = *(const float4*)&Ws[(k0 + 2) * NB + c0];
        float4 w3 = *(const float4*)&Ws[(k0 + 3) * NB + c0];
        float2 w0a = make_float2(w0.x, w0.y), w0b = make_float2(w0.z, w0.w);
        float2 w1a = make_float2(w1.x, w1.y), w1b = make_float2(w1.z, w1.w);
        float2 w2a = make_float2(w2.x, w2.y), w2b = make_float2(w2.z, w2.w);
        float2 w3a = make_float2(w3.x, w3.y), w3b = make_float2(w3.z, w3.w);
        #pragma unroll
        for (int rr = 0; rr < 8; rr++) {
            const float4 av = *(const float4*)&At[(r0 + rr) * NB + k0];
            float2 ax = make_float2(av.x, av.x);
            ffma2(acc[rr][0], ax, w0a); ffma2(acc[rr][1], ax, w0b);
            float2 ay = make_float2(av.y, av.y);
            ffma2(acc[rr][0], ay, w1a); ffma2(acc[rr][1], ay, w1b);
            float2 az = make_float2(av.z, av.z);
            ffma2(acc[rr][0], az, w2a); ffma2(acc[rr][1], az, w2b);
            float2 aw = make_float2(av.w, av.w);
            ffma2(acc[rr][0], aw, w3a); ffma2(acc[rr][1], aw, w3b);
        }
    }

    const float4 bv = *(const float4*)&bias[c0];
    #pragma unroll
    for (int rr = 0; rr < 8; rr++) {
        int r = row0 + r0 + rr;
        if (r >= N_ATOMS) break;
        __half2 lo = __floats2half2_rn(acc[rr][0].x + bv.x, acc[rr][0].y + bv.y);
        __half2 hi = __floats2half2_rn(acc[rr][1].x + bv.z, acc[rr][1].y + bv.w);
        uint2 pk; pk.x = *(unsigned*)&lo; pk.y = *(unsigned*)&hi;
        *(uint2*)&g_nodefh[r * NB + c0] = pk;
    }
}

// ---------------- BIG fused update (f32x2): h += ssp(agg @ Wu1 + bu1) @ Wu2 + bu2 ----------------
__global__ void __launch_bounds__(256) gemm_update_big(const float* __restrict__ Wu1,
                                                       const float* __restrict__ bu1,
                                                       const float* __restrict__ Wu2,
                                                       const float* __restrict__ bu2) {
    extern __shared__ float sm[];
    float* Ws = sm;
    float* At = sm + NB * NB;
    const int tid  = threadIdx.x;
    const int row0 = blockIdx.x * 64;
    const int r0   = (tid >> 5) * 8;
    const int c0   = (tid & 31) * 4;
    const int nrem = N_ATOMS - row0;

    {
        const float4* Wv = (const float4*)Wu1;
        float4* Wsv = (float4*)Ws;
        for (int idx = tid; idx < NB * NB / 4; idx += 256) Wsv[idx] = Wv[idx];
        for (int idx = tid; idx < 64 * (NB / 4); idx += 256) {
            int r = idx >> 5, k4 = idx & 31;
            float4 v = make_float4(0.f, 0.f, 0.f, 0.f);
            if (r < nrem) v = *(const float4*)&g_agg[(row0 + r) * NB + k4 * 4];
            *(float4*)&At[r * NB + k4 * 4] = v;
        }
    }
    __syncthreads();

    float2 acc[8][2];
    #pragma unroll
    for (int rr = 0; rr < 8; rr++) { acc[rr][0] = make_float2(0.f, 0.f); acc[rr][1] = make_float2(0.f, 0.f); }

    #pragma unroll 2
    for (int k0 = 0; k0 < NB; k0 += 4) {
        float4 w0 = *(const float4*)&Ws[(k0 + 0) * NB + c0];
        float4 w1 = *(const float4*)&Ws[(k0 + 1) * NB + c0];
        float4 w2 = *(const float4*)&Ws[(k0 + 2) * NB + c0];
        float4 w3 = *(const float4*)&Ws[(k0 + 3) * NB + c0];
        float2 w0a = make_float2(w0.x, w0.y), w0b = make_float2(w0.z, w0.w);
        float2 w1a = make_float2(w1.x, w1.y), w1b = make_float2(w1.z, w1.w);
        float2 w2a = make_float2(w2.x, w2.y), w2b = make_float2(w2.z, w2.w);
        float2 w3a = make_float2(w3.x, w3.y), w3b = make_float2(w3.z, w3.w);
        #pragma unroll
        for (int rr = 0; rr < 8; rr++) {
            const float4 av = *(const float4*)&At[(r0 + rr) * NB + k0];
            float2 ax = make_float2(av.x, av.x);
            ffma2(acc[rr][0], ax, w0a); ffma2(acc[rr][1], ax, w0b);
            float2 ay = make_float2(av.y, av.y);
            ffma2(acc[rr][0], ay, w1a); ffma2(acc[rr][1], ay, w1b);
            float2 az = make_float2(av.z, av.z);
            ffma2(acc[rr][0], az, w2a); ffma2(acc[rr][1], az, w2b);
            float2 aw = make_float2(av.w, av.w);
            ffma2(acc[rr][0], aw, w3a); ffma2(acc[rr][1], aw, w3b);
        }
    }

    // t1 = ssp(acc + bu1) back into At
    {
        const float4 bv = *(const float4*)&bu1[c0];
        __syncthreads();
        #pragma unroll
        for (int rr = 0; rr < 8; rr++) {
            float4 o = make_float4(sspf(acc[rr][0].x + bv.x), sspf(acc[rr][0].y + bv.y),
                                   sspf(acc[rr][1].x + bv.z), sspf(acc[rr][1].y + bv.w));
            *(float4*)&At[(r0 + rr) * NB + c0] = o;
        }
    }
    __syncthreads();
    {
        const float4* Wv = (const float4*)Wu2;
        float4* Wsv = (float4*)Ws;
        for (int idx = tid; idx < NB * NB / 4; idx += 256) Wsv[idx] = Wv[idx];
    }
    __syncthreads();

    #pragma unroll
    for (int rr = 0; rr < 8; rr++) { acc[rr][0] = make_float2(0.f, 0.f); acc[rr][1] = make_float2(0.f, 0.f); }

    #pragma unroll 2
    for (int k0 = 0; k0 < NB; k0 += 4) {
        float4 w0 = *(const float4*)&Ws[(k0 + 0) * NB + c0];
        float4 w1 = *(const float4*)&Ws[(k0 + 1) * NB + c0];
        float4 w2 = *(const float4*)&Ws[(k0 + 2) * NB + c0];
        float4 w3 = *(const float4*)&Ws[(k0 + 3) * NB + c0];
        float2 w0a = make_float2(w0.x, w0.y), w0b = make_float2(w0.z, w0.w);
        float2 w1a = make_float2(w1.x, w1.y), w1b = make_float2(w1.z, w1.w);
        float2 w2a = make_float2(w2.x, w2.y), w2b = make_float2(w2.z, w2.w);
        float2 w3a = make_float2(w3.x, w3.y), w3b = make_float2(w3.z, w3.w);
        #pragma unroll
        for (int rr = 0; rr < 8; rr++) {
            const float4 av = *(const float4*)&At[(r0 + rr) * NB + k0];
            float2 ax = make_float2(av.x, av.x);
            ffma2(acc[rr][0], ax, w0a); ffma2(acc[rr][1], ax, w0b);
            float2 ay = make_float2(av.y, av.y);
            ffma2(acc[rr][0], ay, w1a); ffma2(acc[rr][1], ay, w1b);
            float2 az = make_float2(av.z, av.z);
            ffma2(acc[rr][0], az, w2a); ffma2(acc[rr][1], az, w2b);
            float2 aw = make_float2(av.w, av.w);
            ffma2(acc[rr][0], aw, w3a); ffma2(acc[rr][1], aw, w3b);
        }
    }

    const float4 bv = *(const float4*)&bu2[c0];
    #pragma unroll
    for (int rr = 0; rr < 8; rr++) {
        int r = row0 + r0 + rr;
        if (r >= N_ATOMS) break;
        float4* p = (float4*)&g_h[r * NB + c0];
        float4 hv = *p;
        hv.x += acc[rr][0].x + bv.x;
        hv.y += acc[rr][0].y + bv.y;
        hv.z += acc[rr][1].x + bv.z;
        hv.w += acc[rr][1].y + bv.w;
        *p = hv;
    }
}

// ---------------- fallback 48KB GEMMs (FFMA, unchanged) ----------------
__global__ void __launch_bounds__(256) gemm_nodef_kernel(const float* __restrict__ W,
                                                         const float* __restrict__ bias) {
    __shared__ __align__(16) float At[64 * NB];
    __shared__ float Wp[NB * 32];
    const int tid  = threadIdx.x;
    const int row0 = blockIdx.x * 64;
    const int lane = tid & 31;
    const int r0   = (tid >> 5) * 8;
    {
        const int nrem = N_ATOMS - row0;
        for (int idx = tid; idx < 64 * (NB / 4); idx += 256) {
            int r = idx >> 5, k4 = idx & 31;
            float4 v = make_float4(0.f, 0.f, 0.f, 0.f);
            if (r < nrem) v = *(const float4*)&g_h[(row0 + r) * NB + k4 * 4];
            *(float4*)&At[r * NB + k4 * 4] = v;
        }
    }
    #pragma unroll
    for (int pass = 0; pass < 4; pass++) {
        const int cbase = pass * 32;
        __syncthreads();
        for (int idx = tid; idx < NB * 32; idx += 256) {
            int k = idx >> 5, c = idx & 31;
            Wp[k * 32 + c] = W[k * NB + cbase + c];
        }
        __syncthreads();
        float acc[8];
        #pragma unroll
        for (int rr = 0; rr < 8; rr++) acc[rr] = 0.0f;
        #pragma unroll 2
        for (int k0 = 0; k0 < NB; k0 += 4) {
            float w0 = Wp[(k0 + 0) * 32 + lane];
            float w1 = Wp[(k0 + 1) * 32 + lane];
            float w2 = Wp[(k0 + 2) * 32 + lane];
            float w3 = Wp[(k0 + 3) * 32 + lane];
            #pragma unroll
            for (int rr = 0; rr < 8; rr++) {
                const float4 av = *(const float4*)&At[(r0 + rr) * NB + k0];
                acc[rr] = fmaf(av.x, w0, acc[rr]);
                acc[rr] = fmaf(av.y, w1, acc[rr]);
                acc[rr] = fmaf(av.z, w2, acc[rr]);
                acc[rr] = fmaf(av.w, w3, acc[rr]);
            }
        }
        const float bv = bias[cbase + lane];
        #pragma unroll
        for (int rr = 0; rr < 8; rr++) {
            int r = row0 + r0 + rr;
            if (r >= N_ATOMS) break;
            g_nodefh[r * NB + cbase + lane] = __float2half_rn(acc[rr] + bv);
        }
    }
}

__global__ void __launch_bounds__(256) gemm_update_kernel(const float* __restrict__ Wu1,
                                                          const float* __restrict__ bu1,
                                                          const float* __restrict__ Wu2,
                                                          const float* __restrict__ bu2) {
    __shared__ __align__(16) float At[64 * NB];
    __shared__ float Wp[NB * 32];
    const int tid  = threadIdx.x;
    const int row0 = blockIdx.x * 64;
    const int lane = tid & 31;
    const int r0   = (tid >> 5) * 8;
    const int nrem = N_ATOMS - row0;

    for (int idx = tid; idx < 64 * (NB / 4); idx += 256) {
        int r = idx >> 5, k4 = idx & 31;
        float4 v = make_float4(0.f, 0.f, 0.f, 0.f);
        if (r < nrem) v = *(const float4*)&g_agg[(row0 + r) * NB + k4 * 4];
        *(float4*)&At[r * NB + k4 * 4] = v;
    }
    float t1r[4][8];
    #pragma unroll
    for (int pass = 0; pass < 4; pass++) {
        const int cbase = pass * 32;
        __syncthreads();
        for (int idx = tid; idx < NB * 32; idx += 256) {
            int k = idx >> 5, c = idx & 31;
            Wp[k * 32 + c] = Wu1[k * NB + cbase + c];
        }
        __syncthreads();
        float acc[8];
        #pragma unroll
        for (int rr = 0; rr < 8; rr++) acc[rr] = 0.0f;
        #pragma unroll 2
        for (int k0 = 0; k0 < NB; k0 += 4) {
            float w0 = Wp[(k0 + 0) * 32 + lane];
            float w1 = Wp[(k0 + 1) * 32 + lane];
            float w2 = Wp[(k0 + 2) * 32 + lane];
            float w3 = Wp[(k0 + 3) * 32 + lane];
            #pragma unroll
            for (int rr = 0; rr < 8; rr++) {
                const float4 av = *(const float4*)&At[(r0 + rr) * NB + k0];
                acc[rr] = fmaf(av.x, w0, acc[rr]);
                acc[rr] = fmaf(av.y, w1, acc[rr]);
                acc[rr] = fmaf(av.z, w2, acc[rr]);
                acc[rr] = fmaf(av.w, w3, acc[rr]);
            }
        }
        const float bv = bu1[cbase + lane];
        #pragma unroll
        for (int rr = 0; rr < 8; rr++) t1r[pass][rr] = sspf(acc[rr] + bv);
    }
    __syncthreads();
    #pragma unroll
    for (int pass = 0; pass < 4; pass++)
        #pragma unroll
        for (int rr = 0; rr < 8; rr++)
            At[(r0 + rr) * NB + pass * 32 + lane] = t1r[pass][rr];
    #pragma unroll
    for (int pass = 0; pass < 4; pass++) {
        const int cbase = pass * 32;
        __syncthreads();
        for (int idx = tid; idx < NB * 32; idx += 256) {
            int k = idx >> 5, c = idx & 31;
            Wp[k * 32 + c] = Wu2[k * NB + cbase + c];
        }
        __syncthreads();
        float acc[8];
        #pragma unroll
        for (int rr = 0; rr < 8; rr++) acc[rr] = 0.0f;
        #pragma unroll 2
        for (int k0 = 0; k0 < NB; k0 += 4) {
            float w0 = Wp[(k0 + 0) * 32 + lane];
            float w1 = Wp[(k0 + 1) * 32 + lane];
            float w2 = Wp[(k0 + 2) * 32 + lane];
            float w3 = Wp[(k0 + 3) * 32 + lane];
            #pragma unroll
            for (int rr = 0; rr < 8; rr++) {
                const float4 av = *(const float4*)&At[(r0 + rr) * NB + k0];
                acc[rr] = fmaf(av.x, w0, acc[rr]);
                acc[rr] = fmaf(av.y, w1, acc[rr]);
                acc[rr] = fmaf(av.z, w2, acc[rr]);
                acc[rr] = fmaf(av.w, w3, acc[rr]);
            }
        }
        const float bv = bu2[cbase + lane];
        #pragma unroll
        for (int rr = 0; rr < 8; rr++) {
            int r = row0 + r0 + rr;
            if (r >= N_ATOMS) break;
            g_h[r * NB + cbase + lane] += acc[rr] + bv;
        }
    }
}

// ---------------- aggregation: warp per node, dup-table lerp, 2-way unroll ----------------
__device__ __forceinline__ void gather_one(int2 cur, int lane, const __half* tdup,
                                           float4& av, float4& ac) {
    const int other = cur.x, meta = cur.y;
    const uint2 nfu = *(const uint2*)&g_nodefh[other * NB + 4 * lane];
    const float2 nf01 = __half22float2(*(const __half2*)&nfu.x);
    const float2 nf23 = __half22float2(*(const __half2*)&nfu.y);
    if (meta < 0) {
        ac.x += nf01.x; ac.y += nf01.y; ac.z += nf23.x; ac.w += nf23.y;
    } else {
        const int bin = meta >> 16;
        const float fr = (float)(meta & 0xffff) * (1.0f / 65535.0f);
        const uint4 tu = *(const uint4*)&tdup[(bin * NB + 4 * lane) * 2];
        const float2 p0 = __half22float2(*(const __half2*)&tu.x);
        const float2 p1 = __half22float2(*(const __half2*)&tu.y);
        const float2 p2 = __half22float2(*(const __half2*)&tu.z);
        const float2 p3 = __half22float2(*(const __half2*)&tu.w);
        av.x = fmaf(nf01.x, fmaf(fr, p0.y - p0.x, p0.x), av.x);
        av.y = fmaf(nf01.y, fmaf(fr, p1.y - p1.x, p1.x), av.y);
        av.z = fmaf(nf23.x, fmaf(fr, p2.y - p2.x, p2.x), av.z);
        av.w = fmaf(nf23.y, fmaf(fr, p3.y - p3.x, p3.x), av.w);
    }
}

__global__ void __launch_bounds__(256) gather_kernel(int l) {
    int gtid = blockIdx.x * blockDim.x + threadIdx.x;
    int node = gtid >> 5;
    if (node >= N_ATOMS) return;
    int lane = threadIdx.x & 31;
    const __half* tdup = g_tdup + l * (NBINS * NB * 2);
    const int s = g_rowptr[node];
    const int e = g_rowptr[node + 1];
    const float4 efc = *(const float4*)&g_efc3[l * NB + 4 * lane];
    float4 av0 = make_float4(0.f, 0.f, 0.f, 0.f);
    float4 av1 = make_float4(0.f, 0.f, 0.f, 0.f);
    float4 ac0 = make_float4(0.f, 0.f, 0.f, 0.f);
    float4 ac1 = make_float4(0.f, 0.f, 0.f, 0.f);

    int p = s;
    for (; p + 1 < e; p += 2) {
        int2 c0 = g_inc[p];
        int2 c1 = g_inc[p + 1];
        gather_one(c0, lane, tdup, av0, ac0);
        gather_one(c1, lane, tdup, av1, ac1);
    }
    if (p < e) gather_one(g_inc[p], lane, tdup, av0, ac0);

    av0.x += av1.x; av0.y += av1.y; av0.z += av1.z; av0.w += av1.w;
    ac0.x += ac1.x; ac0.y += ac1.y; ac0.z += ac1.z; ac0.w += ac1.w;
    av0.x = fmaf(ac0.x, efc.x, av0.x);
    av0.y = fmaf(ac0.y, efc.y, av0.y);
    av0.z = fmaf(ac0.z, efc.z, av0.z);
    av0.w = fmaf(ac0.w, efc.w, av0.w);
    *(float4*)&g_agg[node * NB + 4 * lane] = av0;
}

// ---------------- final head ----------------
#define EAT_APW 16
__global__ void __launch_bounds__(256) eatom_kernel(const float* __restrict__ W1,
                                                    const float* __restrict__ b1,
                                                    const float* __restrict__ W2,
                                                    const float* __restrict__ b2) {
    __shared__ float w1s[NB * 64];
    __shared__ float w2s[64];
    __shared__ float b1s[64];
    __shared__ __align__(16) float rowbuf[8][NB];
    const int tid = threadIdx.x;
    for (int idx = tid; idx < NB * 64; idx += 256) w1s[idx] = W1[idx];
    if (tid < 64) { w2s[tid] = W2[tid]; b1s[tid] = b1[tid]; }
    __syncthreads();

    const int wid = tid >> 5, lane = tid & 31;
    const float b2v = b2[0];
    for (int it = 0; it < EAT_APW; it++) {
        int atom = (blockIdx.x * 8 + wid) * EAT_APW + it;
        if (atom >= N_ATOMS) break;
        *(float4*)&rowbuf[wid][lane * 4] = *(const float4*)&g_h[atom * NB + lane * 4];
        __syncwarp();
        float acc0 = b1s[lane], acc1 = b1s[lane + 32];
        #pragma unroll 4
        for (int k = 0; k < NB; k++) {
            float hv = rowbuf[wid][k];
            acc0 = fmaf(hv, w1s[k * 64 + lane], acc0);
            acc1 = fmaf(hv, w1s[k * 64 + 32 + lane], acc1);
        }
        float e = sspf(acc0) * w2s[lane] + sspf(acc1) * w2s[lane + 32];
        #pragma unroll
        for (int off = 16; off > 0; off >>= 1) e += __shfl_xor_sync(0xffffffffu, e, off);
        if (lane == 0) g_eatom[atom] = e + b2v;
        __syncwarp();
    }
}

__global__ void molred_kernel(float* __restrict__ out, int nmol) {
    __shared__ float s[256];
    const int m = blockIdx.x, tid = threadIdx.x;
    if (m >= nmol) return;
    float v = 0.0f;
    for (int i = tid; i < MOLSZ; i += 256) v += g_eatom[m * MOLSZ + i];
    s[tid] = v;
    __syncthreads();
    for (int off = 128; off > 0; off >>= 1) {
        if (tid < off) s[tid] += s[tid + off];
        __syncthreads();
    }
    if (tid == 0) out[m] = s[0];
}

// ---------------- launch ----------------
extern "C" void kernel_launch(void* const* d_in, const int* in_sizes, int n_in,
                              void* d_out, int out_size) {
    const int*   r     = (const int*)  d_in[0];
    const float* xyz   = (const float*)d_in[1];
    const int*   a     = (const int*)  d_in[2];

    int base = 3;
    if (in_sizes[3] == 1 || (n_in > 4 && in_sizes[4] == 12800)) base = 4;

    const float* embed = (const float*)d_in[base + 0];
    const float* Wn    = (const float*)d_in[base + 1];
    const float* bn    = (const float*)d_in[base + 2];
    const float* We1   = (const float*)d_in[base + 3];
    const float* be1   = (const float*)d_in[base + 4];
    const float* We2   = (const float*)d_in[base + 5];
    const float* be2   = (const float*)d_in[base + 6];
    const float* Wu1   = (const float*)d_in[base + 7];
    const float* bu1   = (const float*)d_in[base + 8];
    const float* Wu2   = (const float*)d_in[base + 9];
    const float* bu2   = (const float*)d_in[base + 10];
    const float* W1    = (const float*)d_in[base + 11];
    const float* b1    = (const float*)d_in[base + 12];
    const float* W2    = (const float*)d_in[base + 13];
    const float* b2    = (const float*)d_in[base + 14];
    float* out = (float*)d_out;
    const int nmol = out_size;

    bool big_ok = true;
    if (cudaFuncSetAttribute(gemm_nodef_big,
            cudaFuncAttributeMaxDynamicSharedMemorySize, SMEM_BIG) != cudaSuccess) big_ok = false;
    if (cudaFuncSetAttribute(gemm_update_big,
            cudaFuncAttributeMaxDynamicSharedMemorySize, SMEM_BIG) != cudaSuccess) big_ok = false;

    const int EB  = (N_EDGES + 255) / 256;
    const int GB  = (N_ATOMS + 63) / 64;
    const int ZB  = (N_ATOMS * NB + 255) / 256;
    const int AB  = (N_ATOMS * 32 + 255) / 256;
    const int NBK = (N_ATOMS + 255) / 256;
    const int EATB = (N_ATOMS + 8 * EAT_APW - 1) / (8 * EAT_APW);

    zero_counts_kernel<<<NBK, 256>>>();
    edge_prep_kernel<<<EB, 256>>>(a, xyz);
    scan1_kernel<<<SCAN_NB, SCAN_CH>>>();
    scan2_kernel<<<1, 256>>>();
    scan3_kernel<<<NBK, 256>>>();
    fill_kernel<<<EB, 256>>>(a);
    h_init_kernel<<<ZB, 256>>>(r, embed);
    efc_kernel<<<N_CONV, NB>>>(be1, We2, be2);
    table_kernel<<<NBINS, NB>>>(We1, be1, We2, be2);

    for (int l = 0; l < N_CONV; l++) {
        if (big_ok) gemm_nodef_big<<<GB, 256, SMEM_BIG>>>(Wn + l * NB * NB, bn + l * NB);
        else        gemm_nodef_kernel<<<GB, 256>>>(Wn + l * NB * NB, bn + l * NB);
        gather_kernel<<<AB, 256>>>(l);
        if (big_ok) gemm_update_big<<<GB, 256, SMEM_BIG>>>(Wu1 + l * NB * NB, bu1 + l * NB,
                                                           Wu2 + l * NB * NB, bu2 + l * NB);
        else        gemm_update_kernel<<<GB, 256>>>(Wu1 + l * NB * NB, bu1 + l * NB,
                                                    Wu2 + l * NB * NB, bu2 + l * NB);
    }

    eatom_kernel<<<EATB, 256>>>(W1, b1, W2, b2);
    molred_kernel<<<nmol, 256>>>(out, nmol);
}

// round 16
// speedup vs baseline: 4.5285x; 1.2272x over previous
#include <cuda_runtime.h>
#include <cuda_fp16.h>
#include <mma.h>
#include <math.h>

using namespace nvcuda;

#define N_ATOMS   50000
#define N_EDGES   500000
#define NB        128
#define NG        50
#define N_CONV    3
#define MOLSZ     1000
#define NBINS     6144
#define DMAXT     6.0f
#define SCAN_CH   256
#define SCAN_NB   ((N_ATOMS + SCAN_CH - 1) / SCAN_CH)
#define LDW       136                         // padded fp16 leading dim (16B-aligned rows, conflict-free)
#define WMMA_SMEM ((NB * LDW + 64 * LDW) * 2) // 52224 B
#define SMEM_BIG  ((NB * NB + 64 * NB) * 4)   // 96 KB (FFMA2 fallback)
#define NCNB      (N_CONV * NB * NB)

// ---------------- device scratch (referenced ONLY inside device code!) ----------------
__device__ __align__(16) float  g_h     [N_ATOMS * NB];
__device__ __align__(16) __half g_nodefh[N_ATOMS * NB];
__device__ __align__(16) float  g_agg   [N_ATOMS * NB];
__device__ __align__(16) __half g_tdup  [N_CONV * NBINS * NB * 2];
__device__ __align__(16) float  g_efc3  [N_CONV * NB];
__device__ __align__(16) __half g_Wh    [3 * NCNB];   // fp16 weights: [Wn | Wu1 | Wu2], each [l][k][n]
__device__ int   g_counts[N_ATOMS];
__device__ int   g_cursor[N_ATOMS];
__device__ int   g_rowptr[N_ATOMS + 1];
__device__ int   g_bsum[SCAN_NB];
__device__ int   g_boff[SCAN_NB];
__device__ int   g_emeta[N_EDGES];
__device__ __align__(8) int2 g_inc[2 * N_EDGES];
__device__ float g_eatom[N_ATOMS];

__device__ __forceinline__ float sspf(float x) {
    return fmaxf(x, 0.0f) + log1pf(expf(-fabsf(x))) - 0.6931471805599453f;
}

__device__ __forceinline__ void ffma2(float2& d, const float2 a, const float2 b) {
    asm("fma.rn.f32x2 %0, %1, %2, %0;"
        : "+l"(*reinterpret_cast<unsigned long long*>(&d))
        : "l"(*reinterpret_cast<const unsigned long long*>(&a)),
          "l"(*reinterpret_cast<const unsigned long long*>(&b)));
}

// ---------------- CSR build ----------------
__global__ void zero_counts_kernel() {
    int i = blockIdx.x * blockDim.x + threadIdx.x;
    if (i < N_ATOMS) g_counts[i] = 0;
}

__global__ void edge_prep_kernel(const int* __restrict__ a, const float* __restrict__ xyz) {
    int e = blockIdx.x * blockDim.x + threadIdx.x;
    if (e >= N_EDGES) return;
    int i = a[2 * e], j = a[2 * e + 1];
    float dx = xyz[3 * i + 0] - xyz[3 * j + 0];
    float dy = xyz[3 * i + 1] - xyz[3 * j + 1];
    float dz = xyz[3 * i + 2] - xyz[3 * j + 2];
    float d = sqrtf(dx * dx + dy * dy + dz * dz);
    int meta;
    if (d <= DMAXT) {
        float t = d * ((float)(NBINS - 1) / DMAXT);
        int bin = (int)t;
        if (bin > NBINS - 2) bin = NBINS - 2;
        float fr = t - (float)bin;
        int f16 = (int)(fr * 65535.0f + 0.5f);
        if (f16 > 65535) f16 = 65535;
        meta = (bin << 16) | f16;
    } else {
        meta = -1;
    }
    g_emeta[e] = meta;
    atomicAdd(&g_counts[i], 1);
    atomicAdd(&g_counts[j], 1);
}

__global__ void scan1_kernel() {
    __shared__ int s[SCAN_CH];
    const int b = blockIdx.x, t = threadIdx.x;
    int i = b * SCAN_CH + t;
    int v = (i < N_ATOMS) ? g_counts[i] : 0;
    s[t] = v;
    __syncthreads();
    for (int off = 1; off < SCAN_CH; off <<= 1) {
        int add = (t >= off) ? s[t - off] : 0;
        __syncthreads();
        s[t] += add;
        __syncthreads();
    }
    if (i < N_ATOMS) g_rowptr[i] = s[t] - v;
    if (t == SCAN_CH - 1) g_bsum[b] = s[t];
}

__global__ void scan2_kernel() {
    __shared__ int s[256];
    int t = threadIdx.x;
    int v = (t < SCAN_NB) ? g_bsum[t] : 0;
    s[t] = v;
    __syncthreads();
    for (int off = 1; off < 256; off <<= 1) {
        int add = (t >= off) ? s[t - off] : 0;
        __syncthreads();
        s[t] += add;
        __syncthreads();
    }
    if (t < SCAN_NB) g_boff[t] = s[t] - v;
}

__global__ void scan3_kernel() {
    int i = blockIdx.x * blockDim.x + threadIdx.x;
    if (i < N_ATOMS) {
        int v = g_rowptr[i] + g_boff[i / SCAN_CH];
        g_rowptr[i] = v;
        g_cursor[i] = v;
    }
    if (i == 0) g_rowptr[N_ATOMS] = 2 * N_EDGES;
}

__global__ void fill_kernel(const int* __restrict__ a) {
    int e = blockIdx.x * blockDim.x + threadIdx.x;
    if (e >= N_EDGES) return;
    int i = a[2 * e], j = a[2 * e + 1];
    int meta = g_emeta[e];
    int p = atomicAdd(&g_cursor[i], 1);
    g_inc[p] = make_int2(j, meta);
    p = atomicAdd(&g_cursor[j], 1);
    g_inc[p] = make_int2(i, meta);
}

// ---------------- embedding + fp16 weight conversion ----------------
__global__ void h_init_kernel(const int* __restrict__ r, const float* __restrict__ embed) {
    int idx = blockIdx.x * blockDim.x + threadIdx.x;
    if (idx >= N_ATOMS * NB) return;
    int row = idx >> 7, c = idx & 127;
    g_h[idx] = embed[r[row] * NB + c];
}

__global__ void w16_kernel(const float* __restrict__ Wn, const float* __restrict__ Wu1,
                           const float* __restrict__ Wu2) {
    int idx = blockIdx.x * blockDim.x + threadIdx.x;
    if (idx >= NCNB) return;
    g_Wh[idx]            = __float2half_rn(Wn[idx]);
    g_Wh[NCNB + idx]     = __float2half_rn(Wu1[idx]);
    g_Wh[2 * NCNB + idx] = __float2half_rn(Wu2[idx]);
}

// ---------------- far-edge ef (exact fp32) ----------------
__global__ void efc_kernel(const float* __restrict__ be1, const float* __restrict__ We2,
                           const float* __restrict__ be2) {
    __shared__ float sxc[NG];
    const int l = blockIdx.x, t = threadIdx.x;
    if (t < NG) sxc[t] = sspf(be1[l * NG + t]);
    __syncthreads();
    float v = be2[l * NB + t];
    for (int k = 0; k < NG; k++) v = fmaf(sxc[k], We2[l * NG * NB + k * NB + t], v);
    g_efc3[l * NB + t] = v;
}

// ---------------- ef(d) tables, dup layout ----------------
__global__ void table_kernel(const float* __restrict__ We1, const float* __restrict__ be1,
                             const float* __restrict__ We2, const float* __restrict__ be2) {
    __shared__ float gg[NG];
    __shared__ float sx[NG];
    const int b = blockIdx.x, t = threadIdx.x;
    const float width = 5.0f / 49.0f;
    const float coeff = -0.5f / (width * width);
    float d = (float)b * (DMAXT / (float)(NBINS - 1));
    if (t < NG) {
        float df = d - (float)t * width;
        gg[t] = expf(coeff * df * df);
    }
    __syncthreads();
    for (int l = 0; l < N_CONV; l++) {
        if (t < NG) {
            float x = be1[l * NG + t];
            const float* W1l = We1 + l * NG * NG;
            #pragma unroll 10
            for (int m = 0; m < NG; m++) x = fmaf(gg[m], W1l[m * NG + t], x);
            sx[t] = sspf(x);
        }
        __syncthreads();
        float ef = be2[l * NB + t];
        const float* W2l = We2 + l * NG * NB;
        #pragma unroll 10
        for (int k = 0; k < NG; k++) ef = fmaf(sx[k], W2l[k * NB + t], ef);
        __half h = __float2half_rn(ef);
        const int rowbase = (l * NBINS + b) * NB;
        g_tdup[(rowbase + t) * 2 + 0] = h;
        if (b > 0)           g_tdup[(rowbase - NB + t) * 2 + 1] = h;
        if (b == NBINS - 1)  g_tdup[(rowbase + t) * 2 + 1] = h;
        __syncthreads();
    }
}

// ================= WMMA GEMMs (tensor cores, fp16 x fp16 -> fp32) =================
// Block: 64 rows x 128 cols. 8 warps in 4x2 grid: warp = 16 rows x 64 cols.
// Smem: Ws [128][LDW] fp16 (34 KB) + At [64][LDW] fp16 (17 KB), dynamic.

__global__ void __launch_bounds__(256) gemm_nodef_wmma(int l, const float* __restrict__ bias) {
    extern __shared__ __half sm16[];
    __half* Ws = sm16;                 // weights
    __half* At = sm16 + NB * LDW;      // A tile
    const __half* Wh = g_Wh + l * NB * NB;
    const int tid  = threadIdx.x;
    const int row0 = blockIdx.x * 64;
    const int wid  = tid >> 5, lane = tid & 31;
    const int m0 = (wid & 3) * 16;
    const int n0 = (wid >> 2) * 64;

    for (int idx = tid; idx < NB * NB; idx += 256) {
        int k = idx >> 7, n = idx & 127;
        Ws[k * LDW + n] = Wh[idx];
    }
    {
        const int nrem = N_ATOMS - row0;
        for (int idx = tid; idx < 64 * 64; idx += 256) {   // half2 granularity
            int r = idx >> 6, k2 = idx & 63;
            float2 v = make_float2(0.f, 0.f);
            if (r < nrem) v = *(const float2*)&g_h[(row0 + r) * NB + k2 * 2];
            *(__half2*)&At[r * LDW + k2 * 2] = __floats2half2_rn(v.x, v.y);
        }
    }
    __syncthreads();

    wmma::fragment<wmma::accumulator, 16, 16, 16, float> acc[4];
    #pragma unroll
    for (int f = 0; f < 4; f++) wmma::fill_fragment(acc[f], 0.0f);

    #pragma unroll
    for (int k0 = 0; k0 < NB; k0 += 16) {
        wmma::fragment<wmma::matrix_a, 16, 16, 16, __half, wmma::row_major> af;
        wmma::load_matrix_sync(af, At + m0 * LDW + k0, LDW);
        #pragma unroll
        for (int f = 0; f < 4; f++) {
            wmma::fragment<wmma::matrix_b, 16, 16, 16, __half, wmma::row_major> bf;
            wmma::load_matrix_sync(bf, Ws + k0 * LDW + n0 + f * 16, LDW);
            wmma::mma_sync(acc[f], af, bf, acc[f]);
        }
    }
    __syncthreads();   // all A reads done; reuse At as fp32 staging

    float* stg = (float*)At + wid * 272;
    #pragma unroll
    for (int f = 0; f < 4; f++) {
        wmma::store_matrix_sync(stg, acc[f], 16, wmma::mem_row_major);
        __syncwarp();
        const int n0f = n0 + f * 16;
        for (int idx = lane; idx < 256; idx += 32) {
            int r = idx >> 4, c = idx & 15;
            int row = row0 + m0 + r;
            if (row < N_ATOMS)
                g_nodefh[row * NB + n0f + c] = __float2half_rn(stg[idx] + bias[n0f + c]);
        }
        __syncwarp();
    }
}

__global__ void __launch_bounds__(256) gemm_update_wmma(int l, const float* __restrict__ bu1,
                                                        const float* __restrict__ bu2) {
    extern __shared__ __half sm16[];
    __half* Ws = sm16;
    __half* At = sm16 + NB * LDW;
    const __half* Wu1h = g_Wh + NCNB + l * NB * NB;
    const __half* Wu2h = g_Wh + 2 * NCNB + l * NB * NB;
    const int tid  = threadIdx.x;
    const int row0 = blockIdx.x * 64;
    const int wid  = tid >> 5, lane = tid & 31;
    const int m0 = (wid & 3) * 16;
    const int n0 = (wid >> 2) * 64;
    const int nrem = N_ATOMS - row0;

    for (int idx = tid; idx < NB * NB; idx += 256) {
        int k = idx >> 7, n = idx & 127;
        Ws[k * LDW + n] = Wu1h[idx];
    }
    for (int idx = tid; idx < 64 * 64; idx += 256) {
        int r = idx >> 6, k2 = idx & 63;
        float2 v = make_float2(0.f, 0.f);
        if (r < nrem) v = *(const float2*)&g_agg[(row0 + r) * NB + k2 * 2];
        *(__half2*)&At[r * LDW + k2 * 2] = __floats2half2_rn(v.x, v.y);
    }
    __syncthreads();

    wmma::fragment<wmma::accumulator, 16, 16, 16, float> acc[4];
    #pragma unroll
    for (int f = 0; f < 4; f++) wmma::fill_fragment(acc[f], 0.0f);
    #pragma unroll
    for (int k0 = 0; k0 < NB; k0 += 16) {
        wmma::fragment<wmma::matrix_a, 16, 16, 16, __half, wmma::row_major> af;
        wmma::load_matrix_sync(af, At + m0 * LDW + k0, LDW);
        #pragma unroll
        for (int f = 0; f < 4; f++) {
            wmma::fragment<wmma::matrix_b, 16, 16, 16, __half, wmma::row_major> bf;
            wmma::load_matrix_sync(bf, Ws + k0 * LDW + n0 + f * 16, LDW);
            wmma::mma_sync(acc[f], af, bf, acc[f]);
        }
    }
    __syncthreads();   // mainloop1 done: Ws free for staging, At free for t1

    // t1 = ssp(acc + bu1) -> At (fp16), staged through Ws region
    {
        float* stg = (float*)Ws + wid * 272;
        #pragma unroll
        for (int f = 0; f < 4; f++) {
            wmma::store_matrix_sync(stg, acc[f], 16, wmma::mem_row_major);
            __syncwarp();
            const int n0f = n0 + f * 16;
            for (int idx = lane; idx < 256; idx += 32) {
                int r = idx >> 4, c = idx & 15;
                At[(m0 + r) * LDW + n0f + c] = __float2half_rn(sspf(stg[idx] + bu1[n0f + c]));
            }
            __syncwarp();
        }
    }
    __syncthreads();
    for (int idx = tid; idx < NB * NB; idx += 256) {
        int k = idx >> 7, n = idx & 127;
        Ws[k * LDW + n] = Wu2h[idx];
    }
    __syncthreads();

    #pragma unroll
    for (int f = 0; f < 4; f++) wmma::fill_fragment(acc[f], 0.0f);
    #pragma unroll
    for (int k0 = 0; k0 < NB; k0 += 16) {
        wmma::fragment<wmma::matrix_a, 16, 16, 16, __half, wmma::row_major> af;
        wmma::load_matrix_sync(af, At + m0 * LDW + k0, LDW);
        #pragma unroll
        for (int f = 0; f < 4; f++) {
            wmma::fragment<wmma::matrix_b, 16, 16, 16, __half, wmma::row_major> bf;
            wmma::load_matrix_sync(bf, Ws + k0 * LDW + n0 + f * 16, LDW);
            wmma::mma_sync(acc[f], af, bf, acc[f]);
        }
    }
    __syncthreads();   // t1 reads done: reuse At for staging

    {
        float* stg = (float*)At + wid * 272;
        #pragma unroll
        for (int f = 0; f < 4; f++) {
            wmma::store_matrix_sync(stg, acc[f], 16, wmma::mem_row_major);
            __syncwarp();
            const int n0f = n0 + f * 16;
            for (int idx = lane; idx < 256; idx += 32) {
                int r = idx >> 4, c = idx & 15;
                int row = row0 + m0 + r;
                if (row < N_ATOMS)
                    g_h[row * NB + n0f + c] += stg[idx] + bu2[n0f + c];
            }
            __syncwarp();
        }
    }
}

// ================= FFMA2 96KB fallbacks (round-15 versions) =================
__global__ void __launch_bounds__(256) gemm_nodef_big(const float* __restrict__ W,
                                                      const float* __restrict__ bias) {
    extern __shared__ float sm[];
    float* Ws = sm;
    float* At = sm + NB * NB;
    const int tid  = threadIdx.x;
    const int row0 = blockIdx.x * 64;
    const int r0   = (tid >> 5) * 8;
    const int c0   = (tid & 31) * 4;
    {
        const float4* Wv = (const float4*)W;
        float4* Wsv = (float4*)Ws;
        for (int idx = tid; idx < NB * NB / 4; idx += 256) Wsv[idx] = Wv[idx];
        const int nrem = N_ATOMS - row0;
        for (int idx = tid; idx < 64 * (NB / 4); idx += 256) {
            int r = idx >> 5, k4 = idx & 31;
            float4 v = make_float4(0.f, 0.f, 0.f, 0.f);
            if (r < nrem) v = *(const float4*)&g_h[(row0 + r) * NB + k4 * 4];
            *(float4*)&At[r * NB + k4 * 4] = v;
        }
    }
    __syncthreads();
    float2 acc[8][2];
    #pragma unroll
    for (int rr = 0; rr < 8; rr++) { acc[rr][0] = make_float2(0.f, 0.f); acc[rr][1] = make_float2(0.f, 0.f); }
    #pragma unroll 2
    for (int k0 = 0; k0 < NB; k0 += 4) {
        float4 w0 = *(const float4*)&Ws[(k0 + 0) * NB + c0];
        float4 w1 = *(const float4*)&Ws[(k0 + 1) * NB + c0];
        float4 w2 = *(const float4*)&Ws[(k0 + 2) * NB + c0];
        float4 w3 = *(const float4*)&Ws[(k0 + 3) * NB + c0];
        float2 w0a = make_float2(w0.x, w0.y), w0b = make_float2(w0.z, w0.w);
        float2 w1a = make_float2(w1.x, w1.y), w1b = make_float2(w1.z, w1.w);
        float2 w2a = make_float2(w2.x, w2.y), w2b = make_float2(w2.z, w2.w);
        float2 w3a = make_float2(w3.x, w3.y), w3b = make_float2(w3.z, w3.w);
        #pragma unroll
        for (int rr = 0; rr < 8; rr++) {
            const float4 av = *(const float4*)&At[(r0 + rr) * NB + k0];
            float2 ax = make_float2(av.x, av.x);
            ffma2(acc[rr][0], ax, w0a); ffma2(acc[rr][1], ax, w0b);
            float2 ay = make_float2(av.y, av.y);
            ffma2(acc[rr][0], ay, w1a); ffma2(acc[rr][1], ay, w1b);
            float2 az = make_float2(av.z, av.z);
            ffma2(acc[rr][0], az, w2a); ffma2(acc[rr][1], az, w2b);
            float2 aw = make_float2(av.w, av.w);
            ffma2(acc[rr][0], aw, w3a); ffma2(acc[rr][1], aw, w3b);
        }
    }
    const float4 bv = *(const float4*)&bias[c0];
    #pragma unroll
    for (int rr = 0; rr < 8; rr++) {
        int r = row0 + r0 + rr;
        if (r >= N_ATOMS) break;
        __half2 lo = __floats2half2_rn(acc[rr][0].x + bv.x, acc[rr][0].y + bv.y);
        __half2 hi = __floats2half2_rn(acc[rr][1].x + bv.z, acc[rr][1].y + bv.w);
        uint2 pk; pk.x = *(unsigned*)&lo; pk.y = *(unsigned*)&hi;
        *(uint2*)&g_nodefh[r * NB + c0] = pk;
    }
}

__global__ void __launch_bounds__(256) gemm_update_big(const float* __restrict__ Wu1,
                                                       const float* __restrict__ bu1,
                                                       const float* __restrict__ Wu2,
                                                       const float* __restrict__ bu2) {
    extern __shared__ float sm[];
    float* Ws = sm;
    float* At = sm + NB * NB;
    const int tid  = threadIdx.x;
    const int row0 = blockIdx.x * 64;
    const int r0   = (tid >> 5) * 8;
    const int c0   = (tid & 31) * 4;
    const int nrem = N_ATOMS - row0;
    {
        const float4* Wv = (const float4*)Wu1;
        float4* Wsv = (float4*)Ws;
        for (int idx = tid; idx < NB * NB / 4; idx += 256) Wsv[idx] = Wv[idx];
        for (int idx = tid; idx < 64 * (NB / 4); idx += 256) {
            int r = idx >> 5, k4 = idx & 31;
            float4 v = make_float4(0.f, 0.f, 0.f, 0.f);
            if (r < nrem) v = *(const float4*)&g_agg[(row0 + r) * NB + k4 * 4];
            *(float4*)&At[r * NB + k4 * 4] = v;
        }
    }
    __syncthreads();
    float2 acc[8][2];
    #pragma unroll
    for (int rr = 0; rr < 8; rr++) { acc[rr][0] = make_float2(0.f, 0.f); acc[rr][1] = make_float2(0.f, 0.f); }
    #pragma unroll 2
    for (int k0 = 0; k0 < NB; k0 += 4) {
        float4 w0 = *(const float4*)&Ws[(k0 + 0) * NB + c0];
        float4 w1 = *(const float4*)&Ws[(k0 + 1) * NB + c0];
        float4 w2 = *(const float4*)&Ws[(k0 + 2) * NB + c0];
        float4 w3 = *(const float4*)&Ws[(k0 + 3) * NB + c0];
        float2 w0a = make_float2(w0.x, w0.y), w0b = make_float2(w0.z, w0.w);
        float2 w1a = make_float2(w1.x, w1.y), w1b = make_float2(w1.z, w1.w);
        float2 w2a = make_float2(w2.x, w2.y), w2b = make_float2(w2.z, w2.w);
        float2 w3a = make_float2(w3.x, w3.y), w3b = make_float2(w3.z, w3.w);
        #pragma unroll
        for (int rr = 0; rr < 8; rr++) {
            const float4 av = *(const float4*)&At[(r0 + rr) * NB + k0];
            float2 ax = make_float2(av.x, av.x);
            ffma2(acc[rr][0], ax, w0a); ffma2(acc[rr][1], ax, w0b);
            float2 ay = make_float2(av.y, av.y);
            ffma2(acc[rr][0], ay, w1a); ffma2(acc[rr][1], ay, w1b);
            float2 az = make_float2(av.z, av.z);
            ffma2(acc[rr][0], az, w2a); ffma2(acc[rr][1], az, w2b);
            float2 aw = make_float2(av.w, av.w);
            ffma2(acc[rr][0], aw, w3a); ffma2(acc[rr][1], aw, w3b);
        }
    }
    {
        const float4 bv = *(const float4*)&bu1[c0];
        __syncthreads();
        #pragma unroll
        for (int rr = 0; rr < 8; rr++) {
            float4 o = make_float4(sspf(acc[rr][0].x + bv.x), sspf(acc[rr][0].y + bv.y),
                                   sspf(acc[rr][1].x + bv.z), sspf(acc[rr][1].y + bv.w));
            *(float4*)&At[(r0 + rr) * NB + c0] = o;
        }
    }
    __syncthreads();
    {
        const float4* Wv = (const float4*)Wu2;
        float4* Wsv = (float4*)Ws;
        for (int idx = tid; idx < NB * NB / 4; idx += 256) Wsv[idx] = Wv[idx];
    }
    __syncthreads();
    #pragma unroll
    for (int rr = 0; rr < 8; rr++) { acc[rr][0] = make_float2(0.f, 0.f); acc[rr][1] = make_float2(0.f, 0.f); }
    #pragma unroll 2
    for (int k0 = 0; k0 < NB; k0 += 4) {
        float4 w0 = *(const float4*)&Ws[(k0 + 0) * NB + c0];
        float4 w1 = *(const float4*)&Ws[(k0 + 1) * NB + c0];
        float4 w2 = *(const float4*)&Ws[(k0 + 2) * NB + c0];
        float4 w3 = *(const float4*)&Ws[(k0 + 3) * NB + c0];
        float2 w0a = make_float2(w0.x, w0.y), w0b = make_float2(w0.z, w0.w);
        float2 w1a = make_float2(w1.x, w1.y), w1b = make_float2(w1.z, w1.w);
        float2 w2a = make_float2(w2.x, w2.y), w2b = make_float2(w2.z, w2.w);
        float2 w3a = make_float2(w3.x, w3.y), w3b = make_float2(w3.z, w3.w);
        #pragma unroll
        for (int rr = 0; rr < 8; rr++) {
            const float4 av = *(const float4*)&At[(r0 + rr) * NB + k0];
            float2 ax = make_float2(av.x, av.x);
            ffma2(acc[rr][0], ax, w0a); ffma2(acc[rr][1], ax, w0b);
            float2 ay = make_float2(av.y, av.y);
            ffma2(acc[rr][0], ay, w1a); ffma2(acc[rr][1], ay, w1b);
            float2 az = make_float2(av.z, av.z);
            ffma2(acc[rr][0], az, w2a); ffma2(acc[rr][1], az, w2b);
            float2 aw = make_float2(av.w, av.w);
            ffma2(acc[rr][0], aw, w3a); ffma2(acc[rr][1], aw, w3b);
        }
    }
    const float4 bv = *(const float4*)&bu2[c0];
    #pragma unroll
    for (int rr = 0; rr < 8; rr++) {
        int r = row0 + r0 + rr;
        if (r >= N_ATOMS) break;
        float4* p = (float4*)&g_h[r * NB + c0];
        float4 hv = *p;
        hv.x += acc[rr][0].x + bv.x;
        hv.y += acc[rr][0].y + bv.y;
        hv.z += acc[rr][1].x + bv.z;
        hv.w += acc[rr][1].y + bv.w;
        *p = hv;
    }
}

// ---------------- aggregation: warp per node, dup-table lerp, 2-way unroll ----------------
__device__ __forceinline__ void gather_one(int2 cur, int lane, const __half* tdup,
                                           float4& av, float4& ac) {
    const int other = cur.x, meta = cur.y;
    const uint2 nfu = *(const uint2*)&g_nodefh[other * NB + 4 * lane];
    const float2 nf01 = __half22float2(*(const __half2*)&nfu.x);
    const float2 nf23 = __half22float2(*(const __half2*)&nfu.y);
    if (meta < 0) {
        ac.x += nf01.x; ac.y += nf01.y; ac.z += nf23.x; ac.w += nf23.y;
    } else {
        const int bin = meta >> 16;
        const float fr = (float)(meta & 0xffff) * (1.0f / 65535.0f);
        const uint4 tu = *(const uint4*)&tdup[(bin * NB + 4 * lane) * 2];
        const float2 p0 = __half22float2(*(const __half2*)&tu.x);
        const float2 p1 = __half22float2(*(const __half2*)&tu.y);
        const float2 p2 = __half22float2(*(const __half2*)&tu.z);
        const float2 p3 = __half22float2(*(const __half2*)&tu.w);
        av.x = fmaf(nf01.x, fmaf(fr, p0.y - p0.x, p0.x), av.x);
        av.y = fmaf(nf01.y, fmaf(fr, p1.y - p1.x, p1.x), av.y);
        av.z = fmaf(nf23.x, fmaf(fr, p2.y - p2.x, p2.x), av.z);
        av.w = fmaf(nf23.y, fmaf(fr, p3.y - p3.x, p3.x), av.w);
    }
}

__global__ void __launch_bounds__(256) gather_kernel(int l) {
    int gtid = blockIdx.x * blockDim.x + threadIdx.x;
    int node = gtid >> 5;
    if (node >= N_ATOMS) return;
    int lane = threadIdx.x & 31;
    const __half* tdup = g_tdup + l * (NBINS * NB * 2);
    const int s = g_rowptr[node];
    const int e = g_rowptr[node + 1];
    const float4 efc = *(const float4*)&g_efc3[l * NB + 4 * lane];
    float4 av0 = make_float4(0.f, 0.f, 0.f, 0.f);
    float4 av1 = make_float4(0.f, 0.f, 0.f, 0.f);
    float4 ac0 = make_float4(0.f, 0.f, 0.f, 0.f);
    float4 ac1 = make_float4(0.f, 0.f, 0.f, 0.f);

    int p = s;
    for (; p + 1 < e; p += 2) {
        int2 c0 = g_inc[p];
        int2 c1 = g_inc[p + 1];
        gather_one(c0, lane, tdup, av0, ac0);
        gather_one(c1, lane, tdup, av1, ac1);
    }
    if (p < e) gather_one(g_inc[p], lane, tdup, av0, ac0);

    av0.x += av1.x; av0.y += av1.y; av0.z += av1.z; av0.w += av1.w;
    ac0.x += ac1.x; ac0.y += ac1.y; ac0.z += ac1.z; ac0.w += ac1.w;
    av0.x = fmaf(ac0.x, efc.x, av0.x);
    av0.y = fmaf(ac0.y, efc.y, av0.y);
    av0.z = fmaf(ac0.z, efc.z, av0.z);
    av0.w = fmaf(ac0.w, efc.w, av0.w);
    *(float4*)&g_agg[node * NB + 4 * lane] = av0;
}

// ---------------- final head ----------------
#define EAT_APW 16
__global__ void __launch_bounds__(256) eatom_kernel(const float* __restrict__ W1,
                                                    const float* __restrict__ b1,
                                                    const float* __restrict__ W2,
                                                    const float* __restrict__ b2) {
    __shared__ float w1s[NB * 64];
    __shared__ float w2s[64];
    __shared__ float b1s[64];
    __shared__ __align__(16) float rowbuf[8][NB];
    const int tid = threadIdx.x;
    for (int idx = tid; idx < NB * 64; idx += 256) w1s[idx] = W1[idx];
    if (tid < 64) { w2s[tid] = W2[tid]; b1s[tid] = b1[tid]; }
    __syncthreads();

    const int wid = tid >> 5, lane = tid & 31;
    const float b2v = b2[0];
    for (int it = 0; it < EAT_APW; it++) {
        int atom = (blockIdx.x * 8 + wid) * EAT_APW + it;
        if (atom >= N_ATOMS) break;
        *(float4*)&rowbuf[wid][lane * 4] = *(const float4*)&g_h[atom * NB + lane * 4];
        __syncwarp();
        float acc0 = b1s[lane], acc1 = b1s[lane + 32];
        #pragma unroll 4
        for (int k = 0; k < NB; k++) {
            float hv = rowbuf[wid][k];
            acc0 = fmaf(hv, w1s[k * 64 + lane], acc0);
            acc1 = fmaf(hv, w1s[k * 64 + 32 + lane], acc1);
        }
        float e = sspf(acc0) * w2s[lane] + sspf(acc1) * w2s[lane + 32];
        #pragma unroll
        for (int off = 16; off > 0; off >>= 1) e += __shfl_xor_sync(0xffffffffu, e, off);
        if (lane == 0) g_eatom[atom] = e + b2v;
        __syncwarp();
    }
}

__global__ void molred_kernel(float* __restrict__ out, int nmol) {
    __shared__ float s[256];
    const int m = blockIdx.x, tid = threadIdx.x;
    if (m >= nmol) return;
    float v = 0.0f;
    for (int i = tid; i < MOLSZ; i += 256) v += g_eatom[m * MOLSZ + i];
    s[tid] = v;
    __syncthreads();
    for (int off = 128; off > 0; off >>= 1) {
        if (tid < off) s[tid] += s[tid + off];
        __syncthreads();
    }
    if (tid == 0) out[m] = s[0];
}

// ---------------- launch ----------------
extern "C" void kernel_launch(void* const* d_in, const int* in_sizes, int n_in,
                              void* d_out, int out_size) {
    const int*   r     = (const int*)  d_in[0];
    const float* xyz   = (const float*)d_in[1];
    const int*   a     = (const int*)  d_in[2];

    int base = 3;
    if (in_sizes[3] == 1 || (n_in > 4 && in_sizes[4] == 12800)) base = 4;

    const float* embed = (const float*)d_in[base + 0];
    const float* Wn    = (const float*)d_in[base + 1];
    const float* bn    = (const float*)d_in[base + 2];
    const float* We1   = (const float*)d_in[base + 3];
    const float* be1   = (const float*)d_in[base + 4];
    const float* We2   = (const float*)d_in[base + 5];
    const float* be2   = (const float*)d_in[base + 6];
    const float* Wu1   = (const float*)d_in[base + 7];
    const float* bu1   = (const float*)d_in[base + 8];
    const float* Wu2   = (const float*)d_in[base + 9];
    const float* bu2   = (const float*)d_in[base + 10];
    const float* W1    = (const float*)d_in[base + 11];
    const float* b1    = (const float*)d_in[base + 12];
    const float* W2    = (const float*)d_in[base + 13];
    const float* b2    = (const float*)d_in[base + 14];
    float* out = (float*)d_out;
    const int nmol = out_size;

    bool wmma_ok = true;
    if (cudaFuncSetAttribute(gemm_nodef_wmma,
            cudaFuncAttributeMaxDynamicSharedMemorySize, WMMA_SMEM) != cudaSuccess) wmma_ok = false;
    if (cudaFuncSetAttribute(gemm_update_wmma,
            cudaFuncAttributeMaxDynamicSharedMemorySize, WMMA_SMEM) != cudaSuccess) wmma_ok = false;
    bool big_ok = true;
    if (cudaFuncSetAttribute(gemm_nodef_big,
            cudaFuncAttributeMaxDynamicSharedMemorySize, SMEM_BIG) != cudaSuccess) big_ok = false;
    if (cudaFuncSetAttribute(gemm_update_big,
            cudaFuncAttributeMaxDynamicSharedMemorySize, SMEM_BIG) != cudaSuccess) big_ok = false;

    const int EB  = (N_EDGES + 255) / 256;
    const int GB  = (N_ATOMS + 63) / 64;
    const int ZB  = (N_ATOMS * NB + 255) / 256;
    const int AB  = (N_ATOMS * 32 + 255) / 256;
    const int NBK = (N_ATOMS + 255) / 256;
    const int WB  = (NCNB + 255) / 256;
    const int EATB = (N_ATOMS + 8 * EAT_APW - 1) / (8 * EAT_APW);

    zero_counts_kernel<<<NBK, 256>>>();
    edge_prep_kernel<<<EB, 256>>>(a, xyz);
    scan1_kernel<<<SCAN_NB, SCAN_CH>>>();
    scan2_kernel<<<1, 256>>>();
    scan3_kernel<<<NBK, 256>>>();
    fill_kernel<<<EB, 256>>>(a);
    h_init_kernel<<<ZB, 256>>>(r, embed);
    w16_kernel<<<WB, 256>>>(Wn, Wu1, Wu2);
    efc_kernel<<<N_CONV, NB>>>(be1, We2, be2);
    table_kernel<<<NBINS, NB>>>(We1, be1, We2, be2);

    for (int l = 0; l < N_CONV; l++) {
        if (wmma_ok)     gemm_nodef_wmma<<<GB, 256, WMMA_SMEM>>>(l, bn + l * NB);
        else if (big_ok) gemm_nodef_big<<<GB, 256, SMEM_BIG>>>(Wn + l * NB * NB, bn + l * NB);
        gather_kernel<<<AB, 256>>>(l);
        if (wmma_ok)     gemm_update_wmma<<<GB, 256, WMMA_SMEM>>>(l, bu1 + l * NB, bu2 + l * NB);
        else if (big_ok) gemm_update_big<<<GB, 256, SMEM_BIG>>>(Wu1 + l * NB * NB, bu1 + l * NB,
                                                                Wu2 + l * NB * NB, bu2 + l * NB);
    }

    eatom_kernel<<<EATB, 256>>>(W1, b1, W2, b2);
    molred_kernel<<<nmol, 256>>>(out, nmol);
}

// round 17
// speedup vs baseline: 4.7940x; 1.0586x over previous
#include <cuda_runtime.h>
#include <cuda_fp16.h>
#include <mma.h>
#include <math.h>

using namespace nvcuda;

#define N_ATOMS   50000
#define N_EDGES   500000
#define NB        128
#define NG        50
#define N_CONV    3
#define MOLSZ     1000
#define NBINS     3072
#define DMAXT     6.0f
#define SCAN_CH   256
#define SCAN_NB   ((N_ATOMS + SCAN_CH - 1) / SCAN_CH)
#define LDW       136
#define WMMA_SMEM ((NB * LDW + 64 * LDW) * 2)
#define NCNB      (N_CONV * NB * NB)

// ---------------- device scratch (referenced ONLY inside device code!) ----------------
__device__ __align__(16) float  g_h     [N_ATOMS * NB];
__device__ __align__(16) __half g_nodefh[N_ATOMS * NB];
__device__ __align__(16) float  g_agg   [N_ATOMS * NB];
__device__ __align__(16) __half g_tdup  [N_CONV * NBINS * NB * 2];
__device__ __align__(16) float  g_efc3  [N_CONV * NB];
__device__ __align__(16) __half g_Wh    [3 * NCNB];   // [Wn | Wu1 | Wu2]
__device__ int   g_counts[N_ATOMS];
__device__ int   g_cursor[N_ATOMS];
__device__ int   g_rowptr[N_ATOMS + 1];
__device__ int   g_bsum[SCAN_NB];
__device__ int   g_boff[SCAN_NB];
__device__ int   g_emeta[N_EDGES];
__device__ __align__(8) int2 g_inc[2 * N_EDGES];
__device__ float g_eatom[N_ATOMS];

__device__ __forceinline__ float sspf(float x) {
    return fmaxf(x, 0.0f) + log1pf(expf(-fabsf(x))) - 0.6931471805599453f;
}

// ---------------- CSR build ----------------
__global__ void zero_counts_kernel() {
    int i = blockIdx.x * blockDim.x + threadIdx.x;
    if (i < N_ATOMS) g_counts[i] = 0;
}

__global__ void edge_prep_kernel(const int* __restrict__ a, const float* __restrict__ xyz) {
    int e = blockIdx.x * blockDim.x + threadIdx.x;
    if (e >= N_EDGES) return;
    int i = a[2 * e], j = a[2 * e + 1];
    float dx = xyz[3 * i + 0] - xyz[3 * j + 0];
    float dy = xyz[3 * i + 1] - xyz[3 * j + 1];
    float dz = xyz[3 * i + 2] - xyz[3 * j + 2];
    float d = sqrtf(dx * dx + dy * dy + dz * dz);
    int meta;
    if (d <= DMAXT) {
        float t = d * ((float)(NBINS - 1) / DMAXT);
        int bin = (int)t;
        if (bin > NBINS - 2) bin = NBINS - 2;
        float fr = t - (float)bin;
        int f16 = (int)(fr * 65535.0f + 0.5f);
        if (f16 > 65535) f16 = 65535;
        meta = (bin << 16) | f16;
    } else {
        meta = -1;
    }
    g_emeta[e] = meta;
    atomicAdd(&g_counts[i], 1);
    atomicAdd(&g_counts[j], 1);
}

__global__ void scan1_kernel() {
    __shared__ int s[SCAN_CH];
    const int b = blockIdx.x, t = threadIdx.x;
    int i = b * SCAN_CH + t;
    int v = (i < N_ATOMS) ? g_counts[i] : 0;
    s[t] = v;
    __syncthreads();
    for (int off = 1; off < SCAN_CH; off <<= 1) {
        int add = (t >= off) ? s[t - off] : 0;
        __syncthreads();
        s[t] += add;
        __syncthreads();
    }
    if (i < N_ATOMS) g_rowptr[i] = s[t] - v;
    if (t == SCAN_CH - 1) g_bsum[b] = s[t];
}

__global__ void scan2_kernel() {
    __shared__ int s[256];
    int t = threadIdx.x;
    int v = (t < SCAN_NB) ? g_bsum[t] : 0;
    s[t] = v;
    __syncthreads();
    for (int off = 1; off < 256; off <<= 1) {
        int add = (t >= off) ? s[t - off] : 0;
        __syncthreads();
        s[t] += add;
        __syncthreads();
    }
    if (t < SCAN_NB) g_boff[t] = s[t] - v;
}

__global__ void scan3_kernel() {
    int i = blockIdx.x * blockDim.x + threadIdx.x;
    if (i < N_ATOMS) {
        int v = g_rowptr[i] + g_boff[i / SCAN_CH];
        g_rowptr[i] = v;
        g_cursor[i] = v;
    }
    if (i == 0) g_rowptr[N_ATOMS] = 2 * N_EDGES;
}

__global__ void fill_kernel(const int* __restrict__ a) {
    int e = blockIdx.x * blockDim.x + threadIdx.x;
    if (e >= N_EDGES) return;
    int i = a[2 * e], j = a[2 * e + 1];
    int meta = g_emeta[e];
    int p = atomicAdd(&g_cursor[i], 1);
    g_inc[p] = make_int2(j, meta);
    p = atomicAdd(&g_cursor[j], 1);
    g_inc[p] = make_int2(i, meta);
}

// ---------------- embedding + fp16 weights ----------------
__global__ void h_init_kernel(const int* __restrict__ r, const float* __restrict__ embed) {
    int idx = blockIdx.x * blockDim.x + threadIdx.x;
    if (idx >= N_ATOMS * NB) return;
    int row = idx >> 7, c = idx & 127;
    g_h[idx] = embed[r[row] * NB + c];
}

__global__ void w16_kernel(const float* __restrict__ Wn, const float* __restrict__ Wu1,
                           const float* __restrict__ Wu2) {
    int idx = blockIdx.x * blockDim.x + threadIdx.x;
    if (idx >= NCNB) return;
    g_Wh[idx]            = __float2half_rn(Wn[idx]);
    g_Wh[NCNB + idx]     = __float2half_rn(Wu1[idx]);
    g_Wh[2 * NCNB + idx] = __float2half_rn(Wu2[idx]);
}

// ---------------- far-edge ef (exact fp32) ----------------
__global__ void efc_kernel(const float* __restrict__ be1, const float* __restrict__ We2,
                           const float* __restrict__ be2) {
    __shared__ float sxc[NG];
    const int l = blockIdx.x, t = threadIdx.x;
    if (t < NG) sxc[t] = sspf(be1[l * NG + t]);
    __syncthreads();
    float v = be2[l * NB + t];
    for (int k = 0; k < NG; k++) v = fmaf(sxc[k], We2[l * NG * NB + k * NB + t], v);
    g_efc3[l * NB + t] = v;
}

// ---------------- ef(d) tables, dup layout ----------------
__global__ void table_kernel(const float* __restrict__ We1, const float* __restrict__ be1,
                             const float* __restrict__ We2, const float* __restrict__ be2) {
    __shared__ float gg[NG];
    __shared__ float sx[NG];
    const int b = blockIdx.x, t = threadIdx.x;
    const float width = 5.0f / 49.0f;
    const float coeff = -0.5f / (width * width);
    float d = (float)b * (DMAXT / (float)(NBINS - 1));
    if (t < NG) {
        float df = d - (float)t * width;
        gg[t] = expf(coeff * df * df);
    }
    __syncthreads();
    for (int l = 0; l < N_CONV; l++) {
        if (t < NG) {
            float x = be1[l * NG + t];
            const float* W1l = We1 + l * NG * NG;
            #pragma unroll 10
            for (int m = 0; m < NG; m++) x = fmaf(gg[m], W1l[m * NG + t], x);
            sx[t] = sspf(x);
        }
        __syncthreads();
        float ef = be2[l * NB + t];
        const float* W2l = We2 + l * NG * NB;
        #pragma unroll 10
        for (int k = 0; k < NG; k++) ef = fmaf(sx[k], W2l[k * NB + t], ef);
        __half h = __float2half_rn(ef);
        const int rowbase = (l * NBINS + b) * NB;
        g_tdup[(rowbase + t) * 2 + 0] = h;
        if (b > 0)           g_tdup[(rowbase - NB + t) * 2 + 1] = h;
        if (b == NBINS - 1)  g_tdup[(rowbase + t) * 2 + 1] = h;
        __syncthreads();
    }
}

// ================= WMMA GEMMs =================
__global__ void __launch_bounds__(256) gemm_nodef_wmma(int l, const float* __restrict__ bias) {
    extern __shared__ __half sm16[];
    __half* Ws = sm16;
    __half* At = sm16 + NB * LDW;
    const __half* Wh = g_Wh + l * NB * NB;
    const int tid  = threadIdx.x;
    const int row0 = blockIdx.x * 64;
    const int wid  = tid >> 5, lane = tid & 31;
    const int m0 = (wid & 3) * 16;
    const int n0 = (wid >> 2) * 64;

    for (int idx = tid; idx < NB * NB; idx += 256) {
        int k = idx >> 7, n = idx & 127;
        Ws[k * LDW + n] = Wh[idx];
    }
    {
        const int nrem = N_ATOMS - row0;
        for (int idx = tid; idx < 64 * 64; idx += 256) {
            int r = idx >> 6, k2 = idx & 63;
            float2 v = make_float2(0.f, 0.f);
            if (r < nrem) v = *(const float2*)&g_h[(row0 + r) * NB + k2 * 2];
            *(__half2*)&At[r * LDW + k2 * 2] = __floats2half2_rn(v.x, v.y);
        }
    }
    __syncthreads();

    wmma::fragment<wmma::accumulator, 16, 16, 16, float> acc[4];
    #pragma unroll
    for (int f = 0; f < 4; f++) wmma::fill_fragment(acc[f], 0.0f);
    #pragma unroll
    for (int k0 = 0; k0 < NB; k0 += 16) {
        wmma::fragment<wmma::matrix_a, 16, 16, 16, __half, wmma::row_major> af;
        wmma::load_matrix_sync(af, At + m0 * LDW + k0, LDW);
        #pragma unroll
        for (int f = 0; f < 4; f++) {
            wmma::fragment<wmma::matrix_b, 16, 16, 16, __half, wmma::row_major> bf;
            wmma::load_matrix_sync(bf, Ws + k0 * LDW + n0 + f * 16, LDW);
            wmma::mma_sync(acc[f], af, bf, acc[f]);
        }
    }
    __syncthreads();

    float* stg = (float*)At + wid * 272;
    #pragma unroll
    for (int f = 0; f < 4; f++) {
        wmma::store_matrix_sync(stg, acc[f], 16, wmma::mem_row_major);
        __syncwarp();
        const int n0f = n0 + f * 16;
        for (int idx = lane; idx < 256; idx += 32) {
            int r = idx >> 4, c = idx & 15;
            int row = row0 + m0 + r;
            if (row < N_ATOMS)
                g_nodefh[row * NB + n0f + c] = __float2half_rn(stg[idx] + bias[n0f + c]);
        }
        __syncwarp();
    }
}

// fused: h += ssp(agg@Wu1+bu1)@Wu2+bu2 ; then (if has_next) nodef = h_new @ Wn(l+1) + bn(l+1)
__global__ void __launch_bounds__(256) gemm_update_fused_wmma(int l, const float* __restrict__ bu1,
                                                              const float* __restrict__ bu2,
                                                              const float* __restrict__ bnn,
                                                              int has_next) {
    extern __shared__ __half sm16[];
    __half* Ws = sm16;
    __half* At = sm16 + NB * LDW;
    const __half* Wu1h = g_Wh + NCNB + l * NB * NB;
    const __half* Wu2h = g_Wh + 2 * NCNB + l * NB * NB;
    const int tid  = threadIdx.x;
    const int row0 = blockIdx.x * 64;
    const int wid  = tid >> 5, lane = tid & 31;
    const int m0 = (wid & 3) * 16;
    const int n0 = (wid >> 2) * 64;
    const int nrem = N_ATOMS - row0;

    for (int idx = tid; idx < NB * NB; idx += 256) {
        int k = idx >> 7, n = idx & 127;
        Ws[k * LDW + n] = Wu1h[idx];
    }
    for (int idx = tid; idx < 64 * 64; idx += 256) {
        int r = idx >> 6, k2 = idx & 63;
        float2 v = make_float2(0.f, 0.f);
        if (r < nrem) v = *(const float2*)&g_agg[(row0 + r) * NB + k2 * 2];
        *(__half2*)&At[r * LDW + k2 * 2] = __floats2half2_rn(v.x, v.y);
    }
    __syncthreads();

    wmma::fragment<wmma::accumulator, 16, 16, 16, float> acc[4];
    #pragma unroll
    for (int f = 0; f < 4; f++) wmma::fill_fragment(acc[f], 0.0f);
    #pragma unroll
    for (int k0 = 0; k0 < NB; k0 += 16) {
        wmma::fragment<wmma::matrix_a, 16, 16, 16, __half, wmma::row_major> af;
        wmma::load_matrix_sync(af, At + m0 * LDW + k0, LDW);
        #pragma unroll
        for (int f = 0; f < 4; f++) {
            wmma::fragment<wmma::matrix_b, 16, 16, 16, __half, wmma::row_major> bf;
            wmma::load_matrix_sync(bf, Ws + k0 * LDW + n0 + f * 16, LDW);
            wmma::mma_sync(acc[f], af, bf, acc[f]);
        }
    }
    __syncthreads();

    // t1 = ssp(acc + bu1) -> At (fp16), staged through Ws scratch
    {
        float* stg = (float*)Ws + wid * 272;
        #pragma unroll
        for (int f = 0; f < 4; f++) {
            wmma::store_matrix_sync(stg, acc[f], 16, wmma::mem_row_major);
            __syncwarp();
            const int n0f = n0 + f * 16;
            for (int idx = lane; idx < 256; idx += 32) {
                int r = idx >> 4, c = idx & 15;
                At[(m0 + r) * LDW + n0f + c] = __float2half_rn(sspf(stg[idx] + bu1[n0f + c]));
            }
            __syncwarp();
        }
    }
    __syncthreads();
    for (int idx = tid; idx < NB * NB; idx += 256) {
        int k = idx >> 7, n = idx & 127;
        Ws[k * LDW + n] = Wu2h[idx];
    }
    __syncthreads();

    #pragma unroll
    for (int f = 0; f < 4; f++) wmma::fill_fragment(acc[f], 0.0f);
    #pragma unroll
    for (int k0 = 0; k0 < NB; k0 += 16) {
        wmma::fragment<wmma::matrix_a, 16, 16, 16, __half, wmma::row_major> af;
        wmma::load_matrix_sync(af, At + m0 * LDW + k0, LDW);
        #pragma unroll
        for (int f = 0; f < 4; f++) {
            wmma::fragment<wmma::matrix_b, 16, 16, 16, __half, wmma::row_major> bf;
            wmma::load_matrix_sync(bf, Ws + k0 * LDW + n0 + f * 16, LDW);
            wmma::mma_sync(acc[f], af, bf, acc[f]);
        }
    }
    __syncthreads();   // t1 reads done; At and Ws reusable

    // h_new = h + acc + bu2 -> global h; also fp16 h_new -> At tile (for next nodef)
    {
        float* stg = (float*)Ws + wid * 272;
        #pragma unroll
        for (int f = 0; f < 4; f++) {
            wmma::store_matrix_sync(stg, acc[f], 16, wmma::mem_row_major);
            __syncwarp();
            const int n0f = n0 + f * 16;
            for (int idx = lane; idx < 256; idx += 32) {
                int r = idx >> 4, c = idx & 15;
                int row = row0 + m0 + r;
                if (row < N_ATOMS) {
                    float hnew = g_h[row * NB + n0f + c] + stg[idx] + bu2[n0f + c];
                    g_h[row * NB + n0f + c] = hnew;
                    if (has_next) At[(m0 + r) * LDW + n0f + c] = __float2half_rn(hnew);
                } else if (has_next) {
                    At[(m0 + r) * LDW + n0f + c] = __half(0);
                }
            }
            __syncwarp();
        }
    }
    if (!has_next) return;

    __syncthreads();
    {
        const __half* Wnn = g_Wh + (l + 1) * NB * NB;
        for (int idx = tid; idx < NB * NB; idx += 256) {
            int k = idx >> 7, n = idx & 127;
            Ws[k * LDW + n] = Wnn[idx];
        }
    }
    __syncthreads();

    #pragma unroll
    for (int f = 0; f < 4; f++) wmma::fill_fragment(acc[f], 0.0f);
    #pragma unroll
    for (int k0 = 0; k0 < NB; k0 += 16) {
        wmma::fragment<wmma::matrix_a, 16, 16, 16, __half, wmma::row_major> af;
        wmma::load_matrix_sync(af, At + m0 * LDW + k0, LDW);
        #pragma unroll
        for (int f = 0; f < 4; f++) {
            wmma::fragment<wmma::matrix_b, 16, 16, 16, __half, wmma::row_major> bf;
            wmma::load_matrix_sync(bf, Ws + k0 * LDW + n0 + f * 16, LDW);
            wmma::mma_sync(acc[f], af, bf, acc[f]);
        }
    }
    __syncthreads();

    {
        float* stg = (float*)At + wid * 272;
        #pragma unroll
        for (int f = 0; f < 4; f++) {
            wmma::store_matrix_sync(stg, acc[f], 16, wmma::mem_row_major);
            __syncwarp();
            const int n0f = n0 + f * 16;
            for (int idx = lane; idx < 256; idx += 32) {
                int r = idx >> 4, c = idx & 15;
                int row = row0 + m0 + r;
                if (row < N_ATOMS)
                    g_nodefh[row * NB + n0f + c] = __float2half_rn(stg[idx] + bnn[n0f + c]);
            }
            __syncwarp();
        }
    }
}

// ---------------- aggregation: warp per node, dup-table lerp, 2-way unroll ----------------
__device__ __forceinline__ void gather_one(int2 cur, int lane, const __half* tdup,
                                           float4& av, float4& ac) {
    const int other = cur.x, meta = cur.y;
    const uint2 nfu = *(const uint2*)&g_nodefh[other * NB + 4 * lane];
    const float2 nf01 = __half22float2(*(const __half2*)&nfu.x);
    const float2 nf23 = __half22float2(*(const __half2*)&nfu.y);
    if (meta < 0) {
        ac.x += nf01.x; ac.y += nf01.y; ac.z += nf23.x; ac.w += nf23.y;
    } else {
        const int bin = meta >> 16;
        const float fr = (float)(meta & 0xffff) * (1.0f / 65535.0f);
        const uint4 tu = *(const uint4*)&tdup[(bin * NB + 4 * lane) * 2];
        const float2 p0 = __half22float2(*(const __half2*)&tu.x);
        const float2 p1 = __half22float2(*(const __half2*)&tu.y);
        const float2 p2 = __half22float2(*(const __half2*)&tu.z);
        const float2 p3 = __half22float2(*(const __half2*)&tu.w);
        av.x = fmaf(nf01.x, fmaf(fr, p0.y - p0.x, p0.x), av.x);
        av.y = fmaf(nf01.y, fmaf(fr, p1.y - p1.x, p1.x), av.y);
        av.z = fmaf(nf23.x, fmaf(fr, p2.y - p2.x, p2.x), av.z);
        av.w = fmaf(nf23.y, fmaf(fr, p3.y - p3.x, p3.x), av.w);
    }
}

__global__ void __launch_bounds__(256) gather_kernel(int l) {
    int gtid = blockIdx.x * blockDim.x + threadIdx.x;
    int node = gtid >> 5;
    if (node >= N_ATOMS) return;
    int lane = threadIdx.x & 31;
    const __half* tdup = g_tdup + l * (NBINS * NB * 2);
    const int s = g_rowptr[node];
    const int e = g_rowptr[node + 1];
    const float4 efc = *(const float4*)&g_efc3[l * NB + 4 * lane];
    float4 av0 = make_float4(0.f, 0.f, 0.f, 0.f);
    float4 av1 = make_float4(0.f, 0.f, 0.f, 0.f);
    float4 ac0 = make_float4(0.f, 0.f, 0.f, 0.f);
    float4 ac1 = make_float4(0.f, 0.f, 0.f, 0.f);

    int p = s;
    for (; p + 1 < e; p += 2) {
        int2 c0 = g_inc[p];
        int2 c1 = g_inc[p + 1];
        gather_one(c0, lane, tdup, av0, ac0);
        gather_one(c1, lane, tdup, av1, ac1);
    }
    if (p < e) gather_one(g_inc[p], lane, tdup, av0, ac0);

    av0.x += av1.x; av0.y += av1.y; av0.z += av1.z; av0.w += av1.w;
    ac0.x += ac1.x; ac0.y += ac1.y; ac0.z += ac1.z; ac0.w += ac1.w;
    av0.x = fmaf(ac0.x, efc.x, av0.x);
    av0.y = fmaf(ac0.y, efc.y, av0.y);
    av0.z = fmaf(ac0.z, efc.z, av0.z);
    av0.w = fmaf(ac0.w, efc.w, av0.w);
    *(float4*)&g_agg[node * NB + 4 * lane] = av0;
}

// ---------------- final head ----------------
#define EAT_APW 16
__global__ void __launch_bounds__(256) eatom_kernel(const float* __restrict__ W1,
                                                    const float* __restrict__ b1,
                                                    const float* __restrict__ W2,
                                                    const float* __restrict__ b2) {
    __shared__ float w1s[NB * 64];
    __shared__ float w2s[64];
    __shared__ float b1s[64];
    __shared__ __align__(16) float rowbuf[8][NB];
    const int tid = threadIdx.x;
    for (int idx = tid; idx < NB * 64; idx += 256) w1s[idx] = W1[idx];
    if (tid < 64) { w2s[tid] = W2[tid]; b1s[tid] = b1[tid]; }
    __syncthreads();

    const int wid = tid >> 5, lane = tid & 31;
    const float b2v = b2[0];
    for (int it = 0; it < EAT_APW; it++) {
        int atom = (blockIdx.x * 8 + wid) * EAT_APW + it;
        if (atom >= N_ATOMS) break;
        *(float4*)&rowbuf[wid][lane * 4] = *(const float4*)&g_h[atom * NB + lane * 4];
        __syncwarp();
        float acc0 = b1s[lane], acc1 = b1s[lane + 32];
        #pragma unroll 4
        for (int k = 0; k < NB; k++) {
            float hv = rowbuf[wid][k];
            acc0 = fmaf(hv, w1s[k * 64 + lane], acc0);
            acc1 = fmaf(hv, w1s[k * 64 + 32 + lane], acc1);
        }
        float e = sspf(acc0) * w2s[lane] + sspf(acc1) * w2s[lane + 32];
        #pragma unroll
        for (int off = 16; off > 0; off >>= 1) e += __shfl_xor_sync(0xffffffffu, e, off);
        if (lane == 0) g_eatom[atom] = e + b2v;
        __syncwarp();
    }
}

__global__ void molred_kernel(float* __restrict__ out, int nmol) {
    __shared__ float s[256];
    const int m = blockIdx.x, tid = threadIdx.x;
    if (m >= nmol) return;
    float v = 0.0f;
    for (int i = tid; i < MOLSZ; i += 256) v += g_eatom[m * MOLSZ + i];
    s[tid] = v;
    __syncthreads();
    for (int off = 128; off > 0; off >>= 1) {
        if (tid < off) s[tid] += s[tid + off];
        __syncthreads();
    }
    if (tid == 0) out[m] = s[0];
}

// ---------------- launch ----------------
extern "C" void kernel_launch(void* const* d_in, const int* in_sizes, int n_in,
                              void* d_out, int out_size) {
    const int*   r     = (const int*)  d_in[0];
    const float* xyz   = (const float*)d_in[1];
    const int*   a     = (const int*)  d_in[2];

    int base = 3;
    if (in_sizes[3] == 1 || (n_in > 4 && in_sizes[4] == 12800)) base = 4;

    const float* embed = (const float*)d_in[base + 0];
    const float* Wn    = (const float*)d_in[base + 1];
    const float* bn    = (const float*)d_in[base + 2];
    const float* We1   = (const float*)d_in[base + 3];
    const float* be1   = (const float*)d_in[base + 4];
    const float* We2   = (const float*)d_in[base + 5];
    const float* be2   = (const float*)d_in[base + 6];
    const float* Wu1   = (const float*)d_in[base + 7];
    const float* bu1   = (const float*)d_in[base + 8];
    const float* Wu2   = (const float*)d_in[base + 9];
    const float* bu2   = (const float*)d_in[base + 10];
    const float* W1    = (const float*)d_in[base + 11];
    const float* b1    = (const float*)d_in[base + 12];
    const float* W2    = (const float*)d_in[base + 13];
    const float* b2    = (const float*)d_in[base + 14];
    float* out = (float*)d_out;
    const int nmol = out_size;

    cudaFuncSetAttribute(gemm_nodef_wmma,
        cudaFuncAttributeMaxDynamicSharedMemorySize, WMMA_SMEM);
    cudaFuncSetAttribute(gemm_update_fused_wmma,
        cudaFuncAttributeMaxDynamicSharedMemorySize, WMMA_SMEM);

    // optional side stream for overlapping table build with CSR build (created once)
    static cudaStream_t s2 = 0;
    static cudaEvent_t evFork = 0, evJoin = 0;
    static bool tried = false;
    static bool streams_ok = false;
    if (!tried) {
        tried = true;
        streams_ok =
            cudaStreamCreateWithFlags(&s2, cudaStreamNonBlocking) == cudaSuccess &&
            cudaEventCreateWithFlags(&evFork, cudaEventDisableTiming) == cudaSuccess &&
            cudaEventCreateWithFlags(&evJoin, cudaEventDisableTiming) == cudaSuccess;
    }

    const int EB  = (N_EDGES + 255) / 256;
    const int GB  = (N_ATOMS + 63) / 64;
    const int ZB  = (N_ATOMS * NB + 255) / 256;
    const int AB  = (N_ATOMS * 32 + 255) / 256;
    const int NBK = (N_ATOMS + 255) / 256;
    const int WB  = (NCNB + 255) / 256;
    const int EATB = (N_ATOMS + 8 * EAT_APW - 1) / (8 * EAT_APW);

    if (streams_ok) {
        cudaEventRecord(evFork, 0);
        cudaStreamWaitEvent(s2, evFork, 0);
        w16_kernel<<<WB, 256, 0, s2>>>(Wn, Wu1, Wu2);
        efc_kernel<<<N_CONV, NB, 0, s2>>>(be1, We2, be2);
        table_kernel<<<NBINS, NB, 0, s2>>>(We1, be1, We2, be2);
        cudaEventRecord(evJoin, s2);
    } else {
        w16_kernel<<<WB, 256>>>(Wn, Wu1, Wu2);
        efc_kernel<<<N_CONV, NB>>>(be1, We2, be2);
        table_kernel<<<NBINS, NB>>>(We1, be1, We2, be2);
    }

    zero_counts_kernel<<<NBK, 256>>>();
    edge_prep_kernel<<<EB, 256>>>(a, xyz);
    scan1_kernel<<<SCAN_NB, SCAN_CH>>>();
    scan2_kernel<<<1, 256>>>();
    scan3_kernel<<<NBK, 256>>>();
    fill_kernel<<<EB, 256>>>(a);
    h_init_kernel<<<ZB, 256>>>(r, embed);

    if (streams_ok) cudaStreamWaitEvent(0, evJoin, 0);

    gemm_nodef_wmma<<<GB, 256, WMMA_SMEM>>>(0, bn);
    for (int l = 0; l < N_CONV; l++) {
        gather_kernel<<<AB, 256>>>(l);
        const float* bnn = (l + 1 < N_CONV) ? (bn + (l + 1) * NB) : bn;
        gemm_update_fused_wmma<<<GB, 256, WMMA_SMEM>>>(l, bu1 + l * NB, bu2 + l * NB,
                                                       bnn, (l + 1 < N_CONV) ? 1 : 0);
    }

    eatom_kernel<<<EATB, 256>>>(W1, b1, W2, b2);
    molred_kernel<<<nmol, 256>>>(out, nmol);
}